// round 5
// baseline (speedup 1.0000x reference)
#include <cuda_runtime.h>
#include <math.h>

#define N    64
#define LD   65            // padded leading dim in shared (bank-conflict free columns)
#define NT   256           // threads per block
#define TILE (N*LD)        // floats per shared buffer
#define MAXB 8192

#define TAU_BATCH  1e-9f
#define TAU_SINGLE 1e-10f

// ----------------------------------------------------------------------------
// Global scratch (static __device__ arrays: no allocation in kernel_launch)
// ----------------------------------------------------------------------------
__device__ float g_M  [N*N];
__device__ float g_Ms [N*N];
__device__ float g_Mis[N*N];
__device__ float g_L  [N*N];
__device__ float g_C  [N*N];
__device__ float g_VM [N*N];                 // warm-start eigvecs of M
__device__ float g_VL [N*N];                 // warm-start eigvecs of L
__device__ float g_scratch[(size_t)MAXB*N*N];  // per-matrix logm
__device__ float g_Vw     [(size_t)MAXB*N*N];  // per-matrix eigvec warm start
__device__ float g_partial[(MAXB/32)*N*N];     // reduction partials

// ----------------------------------------------------------------------------
// Block-cooperative helpers (blockDim.x == NT). Every helper ends with
// __syncthreads() and assumes its inputs are ready on entry.
// ----------------------------------------------------------------------------
__device__ __forceinline__ void g2s(float* S, const float* __restrict__ G) {
    for (int idx = threadIdx.x; idx < N*N; idx += NT)
        S[(idx >> 6) * LD + (idx & 63)] = G[idx];
    __syncthreads();
}
__device__ __forceinline__ void s2g(float* __restrict__ G, const float* S) {
    for (int idx = threadIdx.x; idx < N*N; idx += NT)
        G[idx] = S[(idx >> 6) * LD + (idx & 63)];
    __syncthreads();
}
__device__ __forceinline__ void set_identity(float* S) {
    for (int idx = threadIdx.x; idx < N*N; idx += NT) {
        int i = idx >> 6, j = idx & 63;
        S[i * LD + j] = (i == j) ? 1.0f : 0.0f;
    }
    __syncthreads();
}
__device__ __forceinline__ void symmetrize(float* A) {
    for (int idx = threadIdx.x; idx < N*N; idx += NT) {
        int i = idx >> 6, j = idx & 63;
        if (i < j) {
            float t = 0.5f * (A[i*LD + j] + A[j*LD + i]);
            A[i*LD + j] = t;
            A[j*LD + i] = t;
        }
    }
    __syncthreads();
}

// D = A * B   (all shared, 64x64, LD-padded). D must not alias A or B.
__device__ __forceinline__ void gemm_nn(float* D, const float* A, const float* B) {
    const int tx = (threadIdx.x & 15) << 2;
    const int ty = (threadIdx.x >> 4) << 2;
    float acc[4][4] = {};
#pragma unroll 8
    for (int k = 0; k < N; ++k) {
        float a0 = A[(ty+0)*LD + k], a1 = A[(ty+1)*LD + k];
        float a2 = A[(ty+2)*LD + k], a3 = A[(ty+3)*LD + k];
        float b0 = B[k*LD + tx+0], b1 = B[k*LD + tx+1];
        float b2 = B[k*LD + tx+2], b3 = B[k*LD + tx+3];
        acc[0][0] += a0*b0; acc[0][1] += a0*b1; acc[0][2] += a0*b2; acc[0][3] += a0*b3;
        acc[1][0] += a1*b0; acc[1][1] += a1*b1; acc[1][2] += a1*b2; acc[1][3] += a1*b3;
        acc[2][0] += a2*b0; acc[2][1] += a2*b1; acc[2][2] += a2*b2; acc[2][3] += a2*b3;
        acc[3][0] += a3*b0; acc[3][1] += a3*b1; acc[3][2] += a3*b2; acc[3][3] += a3*b3;
    }
#pragma unroll
    for (int r = 0; r < 4; ++r)
#pragma unroll
        for (int c = 0; c < 4; ++c)
            D[(ty+r)*LD + tx + c] = acc[r][c];
    __syncthreads();
}

// D = A^T * B
__device__ __forceinline__ void gemm_tn(float* D, const float* A, const float* B) {
    const int tx = (threadIdx.x & 15) << 2;
    const int ty = (threadIdx.x >> 4) << 2;
    float acc[4][4] = {};
#pragma unroll 8
    for (int k = 0; k < N; ++k) {
        float a0 = A[k*LD + ty+0], a1 = A[k*LD + ty+1];
        float a2 = A[k*LD + ty+2], a3 = A[k*LD + ty+3];
        float b0 = B[k*LD + tx+0], b1 = B[k*LD + tx+1];
        float b2 = B[k*LD + tx+2], b3 = B[k*LD + tx+3];
        acc[0][0] += a0*b0; acc[0][1] += a0*b1; acc[0][2] += a0*b2; acc[0][3] += a0*b3;
        acc[1][0] += a1*b0; acc[1][1] += a1*b1; acc[1][2] += a1*b2; acc[1][3] += a1*b3;
        acc[2][0] += a2*b0; acc[2][1] += a2*b1; acc[2][2] += a2*b2; acc[2][3] += a2*b3;
        acc[3][0] += a3*b0; acc[3][1] += a3*b1; acc[3][2] += a3*b2; acc[3][3] += a3*b3;
    }
#pragma unroll
    for (int r = 0; r < 4; ++r)
#pragma unroll
        for (int c = 0; c < 4; ++c)
            D[(ty+r)*LD + tx + c] = acc[r][c];
    __syncthreads();
}

// D = A * B^T
__device__ __forceinline__ void gemm_nt(float* D, const float* A, const float* B) {
    const int tx = (threadIdx.x & 15) << 2;
    const int ty = (threadIdx.x >> 4) << 2;
    float acc[4][4] = {};
#pragma unroll 8
    for (int k = 0; k < N; ++k) {
        float a0 = A[(ty+0)*LD + k], a1 = A[(ty+1)*LD + k];
        float a2 = A[(ty+2)*LD + k], a3 = A[(ty+3)*LD + k];
        float b0 = B[(tx+0)*LD + k], b1 = B[(tx+1)*LD + k];
        float b2 = B[(tx+2)*LD + k], b3 = B[(tx+3)*LD + k];
        acc[0][0] += a0*b0; acc[0][1] += a0*b1; acc[0][2] += a0*b2; acc[0][3] += a0*b3;
        acc[1][0] += a1*b0; acc[1][1] += a1*b1; acc[1][2] += a1*b2; acc[1][3] += a1*b3;
        acc[2][0] += a2*b0; acc[2][1] += a2*b1; acc[2][2] += a2*b2; acc[2][3] += a2*b3;
        acc[3][0] += a3*b0; acc[3][1] += a3*b1; acc[3][2] += a3*b2; acc[3][3] += a3*b3;
    }
#pragma unroll
    for (int r = 0; r < 4; ++r)
#pragma unroll
        for (int c = 0; c < 4; ++c)
            D[(ty+r)*LD + tx + c] = acc[r][c];
    __syncthreads();
}

// D = V * diag(f(diag(A))).  mode: 0=log, 1=exp, 2=sqrt, 3=1/sqrt
__device__ __forceinline__ void colscale(float* D, const float* V, const float* A, int mode) {
    __shared__ float f[64];
    if (threadIdx.x < 64) {
        float d = A[threadIdx.x * LD + threadIdx.x];
        float v;
        if      (mode == 0) v = logf(fmaxf(d, 1e-30f));
        else if (mode == 1) v = expf(d);
        else if (mode == 2) v = sqrtf(fmaxf(d, 0.0f));
        else                v = 1.0f / sqrtf(fmaxf(d, 1e-30f));
        f[threadIdx.x] = v;
    }
    __syncthreads();
    for (int idx = threadIdx.x; idx < N*N; idx += NT) {
        int i = idx >> 6, k = idx & 63;
        D[i*LD + k] = V[i*LD + k] * f[k];
    }
    __syncthreads();
}

// ----------------------------------------------------------------------------
// Parallel cyclic threshold-Jacobi eigensolver. A (symmetric, LD-padded
// shared) is diagonalized in place; V accumulates rotations (A_in = V D V^T
// on exit, D = diag(A_out)). Per-pair skip is WARP-UNIFORM (pb = tid>>6 is
// constant within a warp), so skipped pairs cost zero shared traffic and
// no divergence. Skip threshold max(tau*tot, off2)/8192 guarantees the
// skipped off-diag mass per sweep is <= 0.49*off2 (convergence preserved).
// ----------------------------------------------------------------------------
__device__ void jacobi(float* A, float* V, float tau) {
    __shared__ float s_c[32], s_s[32];
    __shared__ int   s_p[32], s_q[32];
    __shared__ float s_red[8];
    __shared__ float s_tot, s_thr2;
    __shared__ int   s_go;
    const int tid   = threadIdx.x;
    const int lane6 = tid & 63;   // row/col owned in update phases
    const int pb    = tid >> 6;   // pair-group base (0..3), warp-uniform

    // --- total F-norm^2, once (invariant under the rotations) ---
    {
        float tot = 0.0f;
        for (int idx = tid; idx < N*N; idx += NT) {
            float v = A[(idx >> 6)*LD + (idx & 63)];
            tot += v * v;
        }
#pragma unroll
        for (int o = 16; o > 0; o >>= 1)
            tot += __shfl_down_sync(0xffffffffu, tot, o);
        if ((tid & 31) == 0) s_red[tid >> 5] = tot;
        __syncthreads();
        if (tid == 0) {
            float t = 0.0f;
            for (int w = 0; w < 8; ++w) t += s_red[w];
            s_tot = t;
        }
        __syncthreads();
    }

    for (int sweep = 0; sweep < 16; ++sweep) {
        // --- off-diagonal mass (fixed-order deterministic reduction) ---
        float off = 0.0f;
        for (int idx = tid; idx < N*N; idx += NT) {
            int i = idx >> 6, j = idx & 63;
            if (i != j) { float v = A[i*LD + j]; off += v * v; }
        }
#pragma unroll
        for (int o = 16; o > 0; o >>= 1)
            off += __shfl_down_sync(0xffffffffu, off, o);
        if ((tid & 31) == 0) s_red[tid >> 5] = off;
        __syncthreads();
        if (tid == 0) {
            float o = 0.0f;
            for (int w = 0; w < 8; ++w) o += s_red[w];
            float gate = tau * s_tot;
            s_go   = (o > gate) ? 1 : 0;
            s_thr2 = fmaxf(gate, o) * (1.0f / 8192.0f);
        }
        __syncthreads();
        if (!s_go) break;

        // --- one sweep: 63 rounds of 32 disjoint rotations ---
        for (int r = 0; r < 63; ++r) {
            if (tid < 32) {
                int i = tid, p, q;
                if (i == 0) { p = 63; q = r; }
                else        { p = (r + i) % 63; q = (r + 63 - i) % 63; }
                if (p > q) { int t2 = p; p = q; q = t2; }
                float apq = A[p*LD + q];
                float c = 1.0f, s = 0.0f;
                if (apq * apq > s_thr2) {   // threshold rotation
                    float app = A[p*LD + p], aqq = A[q*LD + q];
                    float tau2 = (aqq - app) / (2.0f * apq);
                    float t    = copysignf(1.0f, tau2) / (fabsf(tau2) + sqrtf(1.0f + tau2 * tau2));
                    c = 1.0f / sqrtf(1.0f + t * t);
                    s = t * c;
                }
                s_p[i] = p; s_q[i] = q; s_c[i] = c; s_s[i] = s;
            }
            __syncthreads();
            // column phase: A <- A * J  (skip is warp-uniform on s==0)
#pragma unroll
            for (int w = 0; w < 8; ++w) {
                int pi = pb + 4 * w;
                float s = s_s[pi];
                if (s != 0.0f) {
                    float c = s_c[pi];
                    int p = s_p[pi], q = s_q[pi];
                    float x = A[lane6*LD + p], y = A[lane6*LD + q];
                    A[lane6*LD + p] = c * x - s * y;
                    A[lane6*LD + q] = s * x + c * y;
                }
            }
            __syncthreads();
            // row phase (A <- J^T A) + V phase (V <- V J), merged
#pragma unroll
            for (int w = 0; w < 8; ++w) {
                int pi = pb + 4 * w;
                float s = s_s[pi];
                if (s != 0.0f) {
                    float c = s_c[pi];
                    int p = s_p[pi], q = s_q[pi];
                    float x = A[p*LD + lane6], y = A[q*LD + lane6];
                    A[p*LD + lane6] = c * x - s * y;
                    A[q*LD + lane6] = s * x + c * y;
                    float vx = V[lane6*LD + p], vy = V[lane6*LD + q];
                    V[lane6*LD + p] = c * vx - s * vy;
                    V[lane6*LD + q] = s * vx + c * vy;
                }
            }
            __syncthreads();
        }
    }
    __syncthreads();
}

// ----------------------------------------------------------------------------
// Kernels
// ----------------------------------------------------------------------------

// Stage-1 reduction: each block sums 32 consecutive matrices of src.
__global__ void __launch_bounds__(NT) reduce32_kernel(const float* __restrict__ src,
                                                      float* __restrict__ dst, int Bsz) {
    int j = blockIdx.x;
    int b0 = j * 32;
    int cnt = min(32, Bsz - b0);
    for (int i = threadIdx.x; i < N*N; i += NT) {
        float a = 0.0f;
        for (int k = 0; k < cnt; ++k)
            a += src[(size_t)(b0 + k) * (N*N) + i];
        dst[(size_t)j * (N*N) + i] = a;
    }
}

// Stage-2: dst[i] = scale * sum_j part[j][i].  Launch <<<16, 256>>>.
__global__ void __launch_bounds__(NT) reduceFinal_kernel(const float* __restrict__ part,
                                                         float* __restrict__ dst,
                                                         int nb, float scale) {
    int i = blockIdx.x * NT + threadIdx.x;
    float a = 0.0f;
    for (int j = 0; j < nb; ++j)
        a += part[(size_t)j * (N*N) + i];
    dst[i] = a * scale;
}

// eigh(M) -> Ms = sqrtm(M), Mis = invsqrtm(M). Warm-starts from g_VM.
__global__ void __launch_bounds__(NT) prep_M_kernel(int warm) {
    extern __shared__ float sm[];
    float *b0 = sm, *b1 = sm + TILE, *b2 = sm + 2*TILE, *b3 = sm + 3*TILE;
    g2s(b0, g_M);
    float *pA, *fr;
    if (warm) {
        g2s(b1, g_VM);
        gemm_nn(b2, b0, b1);   // M V
        gemm_tn(b3, b1, b2);   // V^T M V
        symmetrize(b3);
        pA = b3; fr = b0;
    } else {
        set_identity(b1);
        symmetrize(b0);
        pA = b0; fr = b3;
    }
    jacobi(pA, b1, TAU_SINGLE);
    s2g(g_VM, b1);
    colscale(b2, b1, pA, 2);   // V sqrt(d)
    gemm_nt(fr, b2, b1);
    s2g(g_Ms, fr);
    colscale(b2, b1, pA, 3);   // V / sqrt(d)
    gemm_nt(fr, b2, b1);
    s2g(g_Mis, fr);
}

// Per-matrix: Y = Mis X Mis; eigh(Y) (warm-started); logm -> g_scratch; V -> g_Vw.
__global__ void __launch_bounds__(NT) batch_log_kernel(const float* __restrict__ data, int warm) {
    extern __shared__ float sm[];
    float *b0 = sm, *b1 = sm + TILE, *b2 = sm + 2*TILE, *b3 = sm + 3*TILE;
    const size_t b = blockIdx.x;
    const float* X = data + b * (N*N);

    g2s(b1, g_Mis);
    g2s(b0, X);
    gemm_nn(b2, b1, b0);       // Mis X
    gemm_nn(b0, b2, b1);       // Y = Mis X Mis

    float *pA, *fr;
    if (warm) {
        g2s(b1, g_Vw + b * (N*N));   // previous eigvecs
        gemm_nn(b2, b0, b1);         // Y V
        gemm_tn(b3, b1, b2);         // V^T Y V  (near-diagonal)
        symmetrize(b3);
        pA = b3; fr = b0;
    } else {
        set_identity(b1);
        symmetrize(b0);
        pA = b0; fr = b3;
    }
    jacobi(pA, b1, TAU_BATCH);
    s2g(g_Vw + b * (N*N), b1);

    colscale(b2, b1, pA, 0);         // V log(d)
    gemm_nt(fr, b2, b1);             // logm(Y) = V log(d) V^T
    s2g(g_scratch + b * (N*N), fr);
}

// M <- sym(Ms expm(L) Ms).  Warm-starts L's eig from g_VL.
__global__ void __launch_bounds__(NT) update_M_kernel(int warm) {
    extern __shared__ float sm[];
    float *b0 = sm, *b1 = sm + TILE, *b2 = sm + 2*TILE, *b3 = sm + 3*TILE;
    g2s(b0, g_L);
    float *pA, *fr;
    if (warm) {
        g2s(b1, g_VL);
        gemm_nn(b2, b0, b1);
        gemm_tn(b3, b1, b2);
        symmetrize(b3);
        pA = b3; fr = b0;
    } else {
        set_identity(b1);
        symmetrize(b0);
        pA = b0; fr = b3;
    }
    jacobi(pA, b1, TAU_SINGLE);
    s2g(g_VL, b1);
    colscale(b2, b1, pA, 1);   // V exp(d)
    gemm_nt(fr, b2, b1);       // E = expm(L)  (in fr)
    // b1, b2, pA now free
    g2s(b1, g_Ms);
    gemm_nn(b2, b1, fr);       // Ms E
    gemm_nn(pA, b2, b1);       // Ms E Ms
    for (int idx = threadIdx.x; idx < N*N; idx += NT) {
        int i = idx >> 6, j = idx & 63;
        g_M[idx] = 0.5f * (pA[i*LD + j] + pA[j*LD + i]);
    }
}

// C = expm(0.25 (bias + bias^T)) * invsqrtm(M)
__global__ void __launch_bounds__(NT) final_prep_kernel(const float* __restrict__ bias) {
    extern __shared__ float sm[];
    float *b0 = sm, *b1 = sm + TILE, *b2 = sm + 2*TILE, *b3 = sm + 3*TILE;
    // W = invsqrtm(M), warm-started from g_VM
    g2s(b0, g_M);
    g2s(b1, g_VM);
    gemm_nn(b2, b0, b1);
    gemm_tn(b3, b1, b2);
    symmetrize(b3);
    jacobi(b3, b1, TAU_SINGLE);
    colscale(b2, b1, b3, 3);
    gemm_nt(b0, b2, b1);       // W -> b0
    // stash W in b3 (b3's diag consumed)
    for (int idx = threadIdx.x; idx < N*LD; idx += NT) b3[idx] = b0[idx];
    __syncthreads();
    // Bs = expm(0.25 (bias + bias^T))
    for (int idx = threadIdx.x; idx < N*N; idx += NT) {
        int i = idx >> 6, j = idx & 63;
        b0[i*LD + j] = 0.25f * (bias[i*N + j] + bias[j*N + i]);
    }
    __syncthreads();
    set_identity(b1);
    jacobi(b0, b1, TAU_SINGLE);
    colscale(b2, b1, b0, 1);
    gemm_nt(b0, b2, b1);       // Bs -> b0
    gemm_nn(b2, b0, b3);       // C = Bs W
    s2g(g_C, b2);
}

// out_b = C X_b C^T
__global__ void __launch_bounds__(NT) apply_kernel(const float* __restrict__ data,
                                                   float* __restrict__ out) {
    extern __shared__ float sm[];
    float *b0 = sm, *b1 = sm + TILE, *b2 = sm + 2*TILE, *b3 = sm + 3*TILE;
    const size_t b = blockIdx.x;
    g2s(b1, g_C);
    g2s(b0, data + b * (N*N));
    gemm_nn(b2, b1, b0);       // C X
    gemm_nt(b3, b2, b1);       // (C X) C^T
    s2g(out + b * (N*N), b3);
}

// ----------------------------------------------------------------------------
// Host launcher (graph-capturable: kernel launches + symbol/attr queries only)
// ----------------------------------------------------------------------------
extern "C" void kernel_launch(void* const* d_in, const int* in_sizes, int n_in,
                              void* d_out, int out_size) {
    const float* data = (const float*)d_in[0];
    const float* bias = (const float*)d_in[1];
    int sz0 = in_sizes[0], sz1 = (n_in > 1) ? in_sizes[1] : 0;
    if (sz0 == N*N && sz1 > N*N) {        // defensive input-order swap
        data = (const float*)d_in[1];
        bias = (const float*)d_in[0];
        int t = sz0; sz0 = sz1; sz1 = t;
    }
    int Bsz = sz0 / (N*N);
    if (Bsz > MAXB) Bsz = MAXB;
    float* out = (float*)d_out;

    const size_t shmem = 4 * TILE * sizeof(float);   // 66,560 B
    cudaFuncSetAttribute(prep_M_kernel,     cudaFuncAttributeMaxDynamicSharedMemorySize, (int)shmem);
    cudaFuncSetAttribute(batch_log_kernel,  cudaFuncAttributeMaxDynamicSharedMemorySize, (int)shmem);
    cudaFuncSetAttribute(update_M_kernel,   cudaFuncAttributeMaxDynamicSharedMemorySize, (int)shmem);
    cudaFuncSetAttribute(final_prep_kernel, cudaFuncAttributeMaxDynamicSharedMemorySize, (int)shmem);
    cudaFuncSetAttribute(apply_kernel,      cudaFuncAttributeMaxDynamicSharedMemorySize, (int)shmem);

    float *pM, *pL, *pScr, *pPart;
    cudaGetSymbolAddress((void**)&pM,    g_M);
    cudaGetSymbolAddress((void**)&pL,    g_L);
    cudaGetSymbolAddress((void**)&pScr,  g_scratch);
    cudaGetSymbolAddress((void**)&pPart, g_partial);

    const int nb1 = (Bsz + 31) / 32;
    const float inv = 1.0f / (float)Bsz;

    // M0 = mean(data)
    reduce32_kernel    <<<nb1, NT>>>(data, pPart, Bsz);
    reduceFinal_kernel <<<16,  NT>>>(pPart, pM, nb1, inv);

    // 5 Karcher iterations
    for (int it = 0; it < 5; ++it) {
        prep_M_kernel    <<<1,   NT, shmem>>>(it > 0 ? 1 : 0);
        batch_log_kernel <<<Bsz, NT, shmem>>>(data, it > 0 ? 1 : 0);
        reduce32_kernel    <<<nb1, NT>>>(pScr, pPart, Bsz);
        reduceFinal_kernel <<<16,  NT>>>(pPart, pL, nb1, inv);
        update_M_kernel  <<<1,   NT, shmem>>>(it > 0 ? 1 : 0);
    }

    // C = Bs * invsqrtm(M); out = C X C^T
    final_prep_kernel <<<1,   NT, shmem>>>(bias);
    apply_kernel      <<<Bsz, NT, shmem>>>(data, out);
}

// round 6
// speedup vs baseline: 1.0022x; 1.0022x over previous
#include <cuda_runtime.h>
#include <math.h>

#define N    64
#define LD   65            // padded leading dim in shared (bank-conflict free columns)
#define NT   256           // threads per block
#define TILE (N*LD)        // floats per shared buffer
#define MAXB 8192

#define TAU_BATCH  1e-9f
#define TAU_SINGLE 1e-10f

// ----------------------------------------------------------------------------
// Global scratch (static __device__ arrays: no allocation in kernel_launch)
// ----------------------------------------------------------------------------
__device__ float g_M  [N*N];
__device__ float g_Ms [N*N];
__device__ float g_Mis[N*N];
__device__ float g_L  [N*N];
__device__ float g_C  [N*N];
__device__ float g_VM [N*N];                 // warm-start eigvecs of M
__device__ float g_VL [N*N];                 // warm-start eigvecs of L
__device__ float g_scratch[(size_t)MAXB*N*N];  // per-matrix logm
__device__ float g_Vw     [(size_t)MAXB*N*N];  // per-matrix eigvec warm start
__device__ float g_partial[(MAXB/32)*N*N];     // reduction partials

// ----------------------------------------------------------------------------
// Block-cooperative helpers (blockDim.x == NT). Every helper ends with
// __syncthreads() and assumes its inputs are ready on entry.
// ----------------------------------------------------------------------------
__device__ __forceinline__ void g2s(float* S, const float* __restrict__ G) {
    for (int idx = threadIdx.x; idx < N*N; idx += NT)
        S[(idx >> 6) * LD + (idx & 63)] = G[idx];
    __syncthreads();
}
__device__ __forceinline__ void s2g(float* __restrict__ G, const float* S) {
    for (int idx = threadIdx.x; idx < N*N; idx += NT)
        G[idx] = S[(idx >> 6) * LD + (idx & 63)];
    __syncthreads();
}
__device__ __forceinline__ void set_identity(float* S) {
    for (int idx = threadIdx.x; idx < N*N; idx += NT) {
        int i = idx >> 6, j = idx & 63;
        S[i * LD + j] = (i == j) ? 1.0f : 0.0f;
    }
    __syncthreads();
}
__device__ __forceinline__ void symmetrize(float* A) {
    for (int idx = threadIdx.x; idx < N*N; idx += NT) {
        int i = idx >> 6, j = idx & 63;
        if (i < j) {
            float t = 0.5f * (A[i*LD + j] + A[j*LD + i]);
            A[i*LD + j] = t;
            A[j*LD + i] = t;
        }
    }
    __syncthreads();
}

// D = A * B   (all shared, 64x64, LD-padded). D must not alias A or B.
__device__ __forceinline__ void gemm_nn(float* D, const float* A, const float* B) {
    const int tx = (threadIdx.x & 15) << 2;
    const int ty = (threadIdx.x >> 4) << 2;
    float acc[4][4] = {};
#pragma unroll 8
    for (int k = 0; k < N; ++k) {
        float a0 = A[(ty+0)*LD + k], a1 = A[(ty+1)*LD + k];
        float a2 = A[(ty+2)*LD + k], a3 = A[(ty+3)*LD + k];
        float b0 = B[k*LD + tx+0], b1 = B[k*LD + tx+1];
        float b2 = B[k*LD + tx+2], b3 = B[k*LD + tx+3];
        acc[0][0] += a0*b0; acc[0][1] += a0*b1; acc[0][2] += a0*b2; acc[0][3] += a0*b3;
        acc[1][0] += a1*b0; acc[1][1] += a1*b1; acc[1][2] += a1*b2; acc[1][3] += a1*b3;
        acc[2][0] += a2*b0; acc[2][1] += a2*b1; acc[2][2] += a2*b2; acc[2][3] += a2*b3;
        acc[3][0] += a3*b0; acc[3][1] += a3*b1; acc[3][2] += a3*b2; acc[3][3] += a3*b3;
    }
#pragma unroll
    for (int r = 0; r < 4; ++r)
#pragma unroll
        for (int c = 0; c < 4; ++c)
            D[(ty+r)*LD + tx + c] = acc[r][c];
    __syncthreads();
}

// D = A^T * B
__device__ __forceinline__ void gemm_tn(float* D, const float* A, const float* B) {
    const int tx = (threadIdx.x & 15) << 2;
    const int ty = (threadIdx.x >> 4) << 2;
    float acc[4][4] = {};
#pragma unroll 8
    for (int k = 0; k < N; ++k) {
        float a0 = A[k*LD + ty+0], a1 = A[k*LD + ty+1];
        float a2 = A[k*LD + ty+2], a3 = A[k*LD + ty+3];
        float b0 = B[k*LD + tx+0], b1 = B[k*LD + tx+1];
        float b2 = B[k*LD + tx+2], b3 = B[k*LD + tx+3];
        acc[0][0] += a0*b0; acc[0][1] += a0*b1; acc[0][2] += a0*b2; acc[0][3] += a0*b3;
        acc[1][0] += a1*b0; acc[1][1] += a1*b1; acc[1][2] += a1*b2; acc[1][3] += a1*b3;
        acc[2][0] += a2*b0; acc[2][1] += a2*b1; acc[2][2] += a2*b2; acc[2][3] += a2*b3;
        acc[3][0] += a3*b0; acc[3][1] += a3*b1; acc[3][2] += a3*b2; acc[3][3] += a3*b3;
    }
#pragma unroll
    for (int r = 0; r < 4; ++r)
#pragma unroll
        for (int c = 0; c < 4; ++c)
            D[(ty+r)*LD + tx + c] = acc[r][c];
    __syncthreads();
}

// D = A * B^T
__device__ __forceinline__ void gemm_nt(float* D, const float* A, const float* B) {
    const int tx = (threadIdx.x & 15) << 2;
    const int ty = (threadIdx.x >> 4) << 2;
    float acc[4][4] = {};
#pragma unroll 8
    for (int k = 0; k < N; ++k) {
        float a0 = A[(ty+0)*LD + k], a1 = A[(ty+1)*LD + k];
        float a2 = A[(ty+2)*LD + k], a3 = A[(ty+3)*LD + k];
        float b0 = B[(tx+0)*LD + k], b1 = B[(tx+1)*LD + k];
        float b2 = B[(tx+2)*LD + k], b3 = B[(tx+3)*LD + k];
        acc[0][0] += a0*b0; acc[0][1] += a0*b1; acc[0][2] += a0*b2; acc[0][3] += a0*b3;
        acc[1][0] += a1*b0; acc[1][1] += a1*b1; acc[1][2] += a1*b2; acc[1][3] += a1*b3;
        acc[2][0] += a2*b0; acc[2][1] += a2*b1; acc[2][2] += a2*b2; acc[2][3] += a2*b3;
        acc[3][0] += a3*b0; acc[3][1] += a3*b1; acc[3][2] += a3*b2; acc[3][3] += a3*b3;
    }
#pragma unroll
    for (int r = 0; r < 4; ++r)
#pragma unroll
        for (int c = 0; c < 4; ++c)
            D[(ty+r)*LD + tx + c] = acc[r][c];
    __syncthreads();
}

// D = V * diag(f(diag(A))).  mode: 0=log, 1=exp, 2=sqrt, 3=1/sqrt
__device__ __forceinline__ void colscale(float* D, const float* V, const float* A, int mode) {
    __shared__ float f[64];
    if (threadIdx.x < 64) {
        float d = A[threadIdx.x * LD + threadIdx.x];
        float v;
        if      (mode == 0) v = logf(fmaxf(d, 1e-30f));
        else if (mode == 1) v = expf(d);
        else if (mode == 2) v = sqrtf(fmaxf(d, 0.0f));
        else                v = 1.0f / sqrtf(fmaxf(d, 1e-30f));
        f[threadIdx.x] = v;
    }
    __syncthreads();
    for (int idx = threadIdx.x; idx < N*N; idx += NT) {
        int i = idx >> 6, k = idx & 63;
        D[i*LD + k] = V[i*LD + k] * f[k];
    }
    __syncthreads();
}

// ----------------------------------------------------------------------------
// Parallel cyclic threshold-Jacobi eigensolver. A (symmetric, LD-padded
// shared) is diagonalized in place; V accumulates rotations (A_in = V D V^T
// on exit, D = diag(A_out)). Per-pair skip is WARP-UNIFORM (pb = tid>>6 is
// constant within a warp), so skipped pairs cost zero shared traffic and
// no divergence. Skip threshold max(tau*tot, off2)/8192 guarantees the
// skipped off-diag mass per sweep is <= 0.49*off2 (convergence preserved).
// ----------------------------------------------------------------------------
__device__ void jacobi(float* A, float* V, float tau) {
    __shared__ float s_c[32], s_s[32];
    __shared__ int   s_p[32], s_q[32];
    __shared__ float s_red[8];
    __shared__ float s_tot, s_thr2;
    __shared__ int   s_go;
    const int tid   = threadIdx.x;
    const int lane6 = tid & 63;   // row/col owned in update phases
    const int pb    = tid >> 6;   // pair-group base (0..3), warp-uniform

    // --- total F-norm^2, once (invariant under the rotations) ---
    {
        float tot = 0.0f;
        for (int idx = tid; idx < N*N; idx += NT) {
            float v = A[(idx >> 6)*LD + (idx & 63)];
            tot += v * v;
        }
#pragma unroll
        for (int o = 16; o > 0; o >>= 1)
            tot += __shfl_down_sync(0xffffffffu, tot, o);
        if ((tid & 31) == 0) s_red[tid >> 5] = tot;
        __syncthreads();
        if (tid == 0) {
            float t = 0.0f;
            for (int w = 0; w < 8; ++w) t += s_red[w];
            s_tot = t;
        }
        __syncthreads();
    }

    for (int sweep = 0; sweep < 16; ++sweep) {
        // --- off-diagonal mass (fixed-order deterministic reduction) ---
        float off = 0.0f;
        for (int idx = tid; idx < N*N; idx += NT) {
            int i = idx >> 6, j = idx & 63;
            if (i != j) { float v = A[i*LD + j]; off += v * v; }
        }
#pragma unroll
        for (int o = 16; o > 0; o >>= 1)
            off += __shfl_down_sync(0xffffffffu, off, o);
        if ((tid & 31) == 0) s_red[tid >> 5] = off;
        __syncthreads();
        if (tid == 0) {
            float o = 0.0f;
            for (int w = 0; w < 8; ++w) o += s_red[w];
            float gate = tau * s_tot;
            s_go   = (o > gate) ? 1 : 0;
            s_thr2 = fmaxf(gate, o) * (1.0f / 8192.0f);
        }
        __syncthreads();
        if (!s_go) break;

        // --- one sweep: 63 rounds of 32 disjoint rotations ---
        for (int r = 0; r < 63; ++r) {
            if (tid < 32) {
                int i = tid, p, q;
                if (i == 0) { p = 63; q = r; }
                else        { p = (r + i) % 63; q = (r + 63 - i) % 63; }
                if (p > q) { int t2 = p; p = q; q = t2; }
                float apq = A[p*LD + q];
                float c = 1.0f, s = 0.0f;
                if (apq * apq > s_thr2) {   // threshold rotation
                    float app = A[p*LD + p], aqq = A[q*LD + q];
                    float tau2 = (aqq - app) / (2.0f * apq);
                    float t    = copysignf(1.0f, tau2) / (fabsf(tau2) + sqrtf(1.0f + tau2 * tau2));
                    c = 1.0f / sqrtf(1.0f + t * t);
                    s = t * c;
                }
                s_p[i] = p; s_q[i] = q; s_c[i] = c; s_s[i] = s;
            }
            __syncthreads();
            // column phase: A <- A * J  (skip is warp-uniform on s==0)
#pragma unroll
            for (int w = 0; w < 8; ++w) {
                int pi = pb + 4 * w;
                float s = s_s[pi];
                if (s != 0.0f) {
                    float c = s_c[pi];
                    int p = s_p[pi], q = s_q[pi];
                    float x = A[lane6*LD + p], y = A[lane6*LD + q];
                    A[lane6*LD + p] = c * x - s * y;
                    A[lane6*LD + q] = s * x + c * y;
                }
            }
            __syncthreads();
            // row phase (A <- J^T A) + V phase (V <- V J), merged
#pragma unroll
            for (int w = 0; w < 8; ++w) {
                int pi = pb + 4 * w;
                float s = s_s[pi];
                if (s != 0.0f) {
                    float c = s_c[pi];
                    int p = s_p[pi], q = s_q[pi];
                    float x = A[p*LD + lane6], y = A[q*LD + lane6];
                    A[p*LD + lane6] = c * x - s * y;
                    A[q*LD + lane6] = s * x + c * y;
                    float vx = V[lane6*LD + p], vy = V[lane6*LD + q];
                    V[lane6*LD + p] = c * vx - s * vy;
                    V[lane6*LD + q] = s * vx + c * vy;
                }
            }
            __syncthreads();
        }
    }
    __syncthreads();
}

// ----------------------------------------------------------------------------
// Kernels
// ----------------------------------------------------------------------------

// Stage-1 reduction: each block sums 32 consecutive matrices of src.
__global__ void __launch_bounds__(NT) reduce32_kernel(const float* __restrict__ src,
                                                      float* __restrict__ dst, int Bsz) {
    int j = blockIdx.x;
    int b0 = j * 32;
    int cnt = min(32, Bsz - b0);
    for (int i = threadIdx.x; i < N*N; i += NT) {
        float a = 0.0f;
        for (int k = 0; k < cnt; ++k)
            a += src[(size_t)(b0 + k) * (N*N) + i];
        dst[(size_t)j * (N*N) + i] = a;
    }
}

// Stage-2: dst[i] = scale * sum_j part[j][i].  Launch <<<16, 256>>>.
__global__ void __launch_bounds__(NT) reduceFinal_kernel(const float* __restrict__ part,
                                                         float* __restrict__ dst,
                                                         int nb, float scale) {
    int i = blockIdx.x * NT + threadIdx.x;
    float a = 0.0f;
    for (int j = 0; j < nb; ++j)
        a += part[(size_t)j * (N*N) + i];
    dst[i] = a * scale;
}

// eigh(M) -> Ms = sqrtm(M), Mis = invsqrtm(M). Warm-starts from g_VM.
__global__ void __launch_bounds__(NT) prep_M_kernel(int warm) {
    extern __shared__ float sm[];
    float *b0 = sm, *b1 = sm + TILE, *b2 = sm + 2*TILE, *b3 = sm + 3*TILE;
    g2s(b0, g_M);
    float *pA, *fr;
    if (warm) {
        g2s(b1, g_VM);
        gemm_nn(b2, b0, b1);   // M V
        gemm_tn(b3, b1, b2);   // V^T M V
        symmetrize(b3);
        pA = b3; fr = b0;
    } else {
        set_identity(b1);
        symmetrize(b0);
        pA = b0; fr = b3;
    }
    jacobi(pA, b1, TAU_SINGLE);
    s2g(g_VM, b1);
    colscale(b2, b1, pA, 2);   // V sqrt(d)
    gemm_nt(fr, b2, b1);
    s2g(g_Ms, fr);
    colscale(b2, b1, pA, 3);   // V / sqrt(d)
    gemm_nt(fr, b2, b1);
    s2g(g_Mis, fr);
}

// Per-matrix: Y = Mis X Mis; eigh(Y) (warm-started); logm -> g_scratch; V -> g_Vw.
__global__ void __launch_bounds__(NT) batch_log_kernel(const float* __restrict__ data, int warm) {
    extern __shared__ float sm[];
    float *b0 = sm, *b1 = sm + TILE, *b2 = sm + 2*TILE, *b3 = sm + 3*TILE;
    const size_t b = blockIdx.x;
    const float* X = data + b * (N*N);

    g2s(b1, g_Mis);
    g2s(b0, X);
    gemm_nn(b2, b1, b0);       // Mis X
    gemm_nn(b0, b2, b1);       // Y = Mis X Mis

    float *pA, *fr;
    if (warm) {
        g2s(b1, g_Vw + b * (N*N));   // previous eigvecs
        gemm_nn(b2, b0, b1);         // Y V
        gemm_tn(b3, b1, b2);         // V^T Y V  (near-diagonal)
        symmetrize(b3);
        pA = b3; fr = b0;
    } else {
        set_identity(b1);
        symmetrize(b0);
        pA = b0; fr = b3;
    }
    jacobi(pA, b1, TAU_BATCH);
    s2g(g_Vw + b * (N*N), b1);

    colscale(b2, b1, pA, 0);         // V log(d)
    gemm_nt(fr, b2, b1);             // logm(Y) = V log(d) V^T
    s2g(g_scratch + b * (N*N), fr);
}

// M <- sym(Ms expm(L) Ms).  Warm-starts L's eig from g_VL.
__global__ void __launch_bounds__(NT) update_M_kernel(int warm) {
    extern __shared__ float sm[];
    float *b0 = sm, *b1 = sm + TILE, *b2 = sm + 2*TILE, *b3 = sm + 3*TILE;
    g2s(b0, g_L);
    float *pA, *fr;
    if (warm) {
        g2s(b1, g_VL);
        gemm_nn(b2, b0, b1);
        gemm_tn(b3, b1, b2);
        symmetrize(b3);
        pA = b3; fr = b0;
    } else {
        set_identity(b1);
        symmetrize(b0);
        pA = b0; fr = b3;
    }
    jacobi(pA, b1, TAU_SINGLE);
    s2g(g_VL, b1);
    colscale(b2, b1, pA, 1);   // V exp(d)
    gemm_nt(fr, b2, b1);       // E = expm(L)  (in fr)
    // b1, b2, pA now free
    g2s(b1, g_Ms);
    gemm_nn(b2, b1, fr);       // Ms E
    gemm_nn(pA, b2, b1);       // Ms E Ms
    for (int idx = threadIdx.x; idx < N*N; idx += NT) {
        int i = idx >> 6, j = idx & 63;
        g_M[idx] = 0.5f * (pA[i*LD + j] + pA[j*LD + i]);
    }
}

// C = expm(0.25 (bias + bias^T)) * invsqrtm(M)
__global__ void __launch_bounds__(NT) final_prep_kernel(const float* __restrict__ bias) {
    extern __shared__ float sm[];
    float *b0 = sm, *b1 = sm + TILE, *b2 = sm + 2*TILE, *b3 = sm + 3*TILE;
    // W = invsqrtm(M), warm-started from g_VM
    g2s(b0, g_M);
    g2s(b1, g_VM);
    gemm_nn(b2, b0, b1);
    gemm_tn(b3, b1, b2);
    symmetrize(b3);
    jacobi(b3, b1, TAU_SINGLE);
    colscale(b2, b1, b3, 3);
    gemm_nt(b0, b2, b1);       // W -> b0
    // stash W in b3 (b3's diag consumed)
    for (int idx = threadIdx.x; idx < N*LD; idx += NT) b3[idx] = b0[idx];
    __syncthreads();
    // Bs = expm(0.25 (bias + bias^T))
    for (int idx = threadIdx.x; idx < N*N; idx += NT) {
        int i = idx >> 6, j = idx & 63;
        b0[i*LD + j] = 0.25f * (bias[i*N + j] + bias[j*N + i]);
    }
    __syncthreads();
    set_identity(b1);
    jacobi(b0, b1, TAU_SINGLE);
    colscale(b2, b1, b0, 1);
    gemm_nt(b0, b2, b1);       // Bs -> b0
    gemm_nn(b2, b0, b3);       // C = Bs W
    s2g(g_C, b2);
}

// out_b = C X_b C^T
__global__ void __launch_bounds__(NT) apply_kernel(const float* __restrict__ data,
                                                   float* __restrict__ out) {
    extern __shared__ float sm[];
    float *b0 = sm, *b1 = sm + TILE, *b2 = sm + 2*TILE, *b3 = sm + 3*TILE;
    const size_t b = blockIdx.x;
    g2s(b1, g_C);
    g2s(b0, data + b * (N*N));
    gemm_nn(b2, b1, b0);       // C X
    gemm_nt(b3, b2, b1);       // (C X) C^T
    s2g(out + b * (N*N), b3);
}

// ----------------------------------------------------------------------------
// Host launcher (graph-capturable: kernel launches + symbol/attr queries only)
// ----------------------------------------------------------------------------
extern "C" void kernel_launch(void* const* d_in, const int* in_sizes, int n_in,
                              void* d_out, int out_size) {
    const float* data = (const float*)d_in[0];
    const float* bias = (const float*)d_in[1];
    int sz0 = in_sizes[0], sz1 = (n_in > 1) ? in_sizes[1] : 0;
    if (sz0 == N*N && sz1 > N*N) {        // defensive input-order swap
        data = (const float*)d_in[1];
        bias = (const float*)d_in[0];
        int t = sz0; sz0 = sz1; sz1 = t;
    }
    int Bsz = sz0 / (N*N);
    if (Bsz > MAXB) Bsz = MAXB;
    float* out = (float*)d_out;

    const size_t shmem = 4 * TILE * sizeof(float);   // 66,560 B
    cudaFuncSetAttribute(prep_M_kernel,     cudaFuncAttributeMaxDynamicSharedMemorySize, (int)shmem);
    cudaFuncSetAttribute(batch_log_kernel,  cudaFuncAttributeMaxDynamicSharedMemorySize, (int)shmem);
    cudaFuncSetAttribute(update_M_kernel,   cudaFuncAttributeMaxDynamicSharedMemorySize, (int)shmem);
    cudaFuncSetAttribute(final_prep_kernel, cudaFuncAttributeMaxDynamicSharedMemorySize, (int)shmem);
    cudaFuncSetAttribute(apply_kernel,      cudaFuncAttributeMaxDynamicSharedMemorySize, (int)shmem);

    float *pM, *pL, *pScr, *pPart;
    cudaGetSymbolAddress((void**)&pM,    g_M);
    cudaGetSymbolAddress((void**)&pL,    g_L);
    cudaGetSymbolAddress((void**)&pScr,  g_scratch);
    cudaGetSymbolAddress((void**)&pPart, g_partial);

    const int nb1 = (Bsz + 31) / 32;
    const float inv = 1.0f / (float)Bsz;

    // M0 = mean(data)
    reduce32_kernel    <<<nb1, NT>>>(data, pPart, Bsz);
    reduceFinal_kernel <<<16,  NT>>>(pPart, pM, nb1, inv);

    // 5 Karcher iterations
    for (int it = 0; it < 5; ++it) {
        prep_M_kernel    <<<1,   NT, shmem>>>(it > 0 ? 1 : 0);
        batch_log_kernel <<<Bsz, NT, shmem>>>(data, it > 0 ? 1 : 0);
        reduce32_kernel    <<<nb1, NT>>>(pScr, pPart, Bsz);
        reduceFinal_kernel <<<16,  NT>>>(pPart, pL, nb1, inv);
        update_M_kernel  <<<1,   NT, shmem>>>(it > 0 ? 1 : 0);
    }

    // C = Bs * invsqrtm(M); out = C X C^T
    final_prep_kernel <<<1,   NT, shmem>>>(bias);
    apply_kernel      <<<Bsz, NT, shmem>>>(data, out);
}

// round 7
// speedup vs baseline: 2.0842x; 2.0797x over previous
#include <cuda_runtime.h>
#include <math.h>

#define N    64
#define LD   65            // padded leading dim in shared
#define NT   256
#define TILE (N*LD)
#define MAXB 8192

#define TAU_SINGLE 1e-10f

// ----------------------------------------------------------------------------
// Global scratch
// ----------------------------------------------------------------------------
__device__ float g_M  [N*N];
__device__ float g_Ms [N*N];
__device__ float g_Mis[N*N];
__device__ float g_L  [N*N];
__device__ float g_C  [N*N];
__device__ float g_VM [N*N];
__device__ float g_VL [N*N];
__device__ float g_scratch[(size_t)MAXB*N*N];  // per-matrix logm
__device__ float g_Vw     [(size_t)MAXB*N*N];  // per-matrix eigvecs, ROW-major V[k][c]
__device__ float g_partial[(MAXB/32)*N*N];

// ----------------------------------------------------------------------------
// Block-cooperative helpers (single-matrix kernels; blockDim.x == NT)
// ----------------------------------------------------------------------------
__device__ __forceinline__ void g2s(float* S, const float* __restrict__ G) {
    for (int idx = threadIdx.x; idx < N*N; idx += NT)
        S[(idx >> 6) * LD + (idx & 63)] = G[idx];
    __syncthreads();
}
__device__ __forceinline__ void s2g(float* __restrict__ G, const float* S) {
    for (int idx = threadIdx.x; idx < N*N; idx += NT)
        G[idx] = S[(idx >> 6) * LD + (idx & 63)];
    __syncthreads();
}
__device__ __forceinline__ void set_identity(float* S) {
    for (int idx = threadIdx.x; idx < N*N; idx += NT) {
        int i = idx >> 6, j = idx & 63;
        S[i * LD + j] = (i == j) ? 1.0f : 0.0f;
    }
    __syncthreads();
}
__device__ __forceinline__ void symmetrize(float* A) {
    for (int idx = threadIdx.x; idx < N*N; idx += NT) {
        int i = idx >> 6, j = idx & 63;
        if (i < j) {
            float t = 0.5f * (A[i*LD + j] + A[j*LD + i]);
            A[i*LD + j] = t;
            A[j*LD + i] = t;
        }
    }
    __syncthreads();
}

__device__ __forceinline__ void gemm_nn(float* D, const float* A, const float* B) {
    const int tx = (threadIdx.x & 15) << 2;
    const int ty = (threadIdx.x >> 4) << 2;
    float acc[4][4] = {};
#pragma unroll 8
    for (int k = 0; k < N; ++k) {
        float a0 = A[(ty+0)*LD + k], a1 = A[(ty+1)*LD + k];
        float a2 = A[(ty+2)*LD + k], a3 = A[(ty+3)*LD + k];
        float b0 = B[k*LD + tx+0], b1 = B[k*LD + tx+1];
        float b2 = B[k*LD + tx+2], b3 = B[k*LD + tx+3];
        acc[0][0] += a0*b0; acc[0][1] += a0*b1; acc[0][2] += a0*b2; acc[0][3] += a0*b3;
        acc[1][0] += a1*b0; acc[1][1] += a1*b1; acc[1][2] += a1*b2; acc[1][3] += a1*b3;
        acc[2][0] += a2*b0; acc[2][1] += a2*b1; acc[2][2] += a2*b2; acc[2][3] += a2*b3;
        acc[3][0] += a3*b0; acc[3][1] += a3*b1; acc[3][2] += a3*b2; acc[3][3] += a3*b3;
    }
#pragma unroll
    for (int r = 0; r < 4; ++r)
#pragma unroll
        for (int c = 0; c < 4; ++c)
            D[(ty+r)*LD + tx + c] = acc[r][c];
    __syncthreads();
}
__device__ __forceinline__ void gemm_tn(float* D, const float* A, const float* B) {
    const int tx = (threadIdx.x & 15) << 2;
    const int ty = (threadIdx.x >> 4) << 2;
    float acc[4][4] = {};
#pragma unroll 8
    for (int k = 0; k < N; ++k) {
        float a0 = A[k*LD + ty+0], a1 = A[k*LD + ty+1];
        float a2 = A[k*LD + ty+2], a3 = A[k*LD + ty+3];
        float b0 = B[k*LD + tx+0], b1 = B[k*LD + tx+1];
        float b2 = B[k*LD + tx+2], b3 = B[k*LD + tx+3];
        acc[0][0] += a0*b0; acc[0][1] += a0*b1; acc[0][2] += a0*b2; acc[0][3] += a0*b3;
        acc[1][0] += a1*b0; acc[1][1] += a1*b1; acc[1][2] += a1*b2; acc[1][3] += a1*b3;
        acc[2][0] += a2*b0; acc[2][1] += a2*b1; acc[2][2] += a2*b2; acc[2][3] += a2*b3;
        acc[3][0] += a3*b0; acc[3][1] += a3*b1; acc[3][2] += a3*b2; acc[3][3] += a3*b3;
    }
#pragma unroll
    for (int r = 0; r < 4; ++r)
#pragma unroll
        for (int c = 0; c < 4; ++c)
            D[(ty+r)*LD + tx + c] = acc[r][c];
    __syncthreads();
}
__device__ __forceinline__ void gemm_nt(float* D, const float* A, const float* B) {
    const int tx = (threadIdx.x & 15) << 2;
    const int ty = (threadIdx.x >> 4) << 2;
    float acc[4][4] = {};
#pragma unroll 8
    for (int k = 0; k < N; ++k) {
        float a0 = A[(ty+0)*LD + k], a1 = A[(ty+1)*LD + k];
        float a2 = A[(ty+2)*LD + k], a3 = A[(ty+3)*LD + k];
        float b0 = B[(tx+0)*LD + k], b1 = B[(tx+1)*LD + k];
        float b2 = B[(tx+2)*LD + k], b3 = B[(tx+3)*LD + k];
        acc[0][0] += a0*b0; acc[0][1] += a0*b1; acc[0][2] += a0*b2; acc[0][3] += a0*b3;
        acc[1][0] += a1*b0; acc[1][1] += a1*b1; acc[1][2] += a1*b2; acc[1][3] += a1*b3;
        acc[2][0] += a2*b0; acc[2][1] += a2*b1; acc[2][2] += a2*b2; acc[2][3] += a2*b3;
        acc[3][0] += a3*b0; acc[3][1] += a3*b1; acc[3][2] += a3*b2; acc[3][3] += a3*b3;
    }
#pragma unroll
    for (int r = 0; r < 4; ++r)
#pragma unroll
        for (int c = 0; c < 4; ++c)
            D[(ty+r)*LD + tx + c] = acc[r][c];
    __syncthreads();
}
__device__ __forceinline__ void colscale(float* D, const float* V, const float* A, int mode) {
    __shared__ float f[64];
    if (threadIdx.x < 64) {
        float d = A[threadIdx.x * LD + threadIdx.x];
        float v;
        if      (mode == 0) v = logf(fmaxf(d, 1e-30f));
        else if (mode == 1) v = expf(d);
        else if (mode == 2) v = sqrtf(fmaxf(d, 0.0f));
        else                v = 1.0f / sqrtf(fmaxf(d, 1e-30f));
        f[threadIdx.x] = v;
    }
    __syncthreads();
    for (int idx = threadIdx.x; idx < N*N; idx += NT) {
        int i = idx >> 6, k = idx & 63;
        D[i*LD + k] = V[i*LD + k] * f[k];
    }
    __syncthreads();
}

// ----------------------------------------------------------------------------
// Two-sided block Jacobi (kept for the single-matrix kernels only)
// ----------------------------------------------------------------------------
__device__ void jacobi(float* A, float* V, float tau) {
    __shared__ float s_c[32], s_s[32];
    __shared__ int   s_p[32], s_q[32];
    __shared__ float s_red[8];
    __shared__ float s_tot, s_thr2;
    __shared__ int   s_go;
    const int tid   = threadIdx.x;
    const int lane6 = tid & 63;
    const int pb    = tid >> 6;

    {
        float tot = 0.0f;
        for (int idx = tid; idx < N*N; idx += NT) {
            float v = A[(idx >> 6)*LD + (idx & 63)];
            tot += v * v;
        }
#pragma unroll
        for (int o = 16; o > 0; o >>= 1)
            tot += __shfl_down_sync(0xffffffffu, tot, o);
        if ((tid & 31) == 0) s_red[tid >> 5] = tot;
        __syncthreads();
        if (tid == 0) {
            float t = 0.0f;
            for (int w = 0; w < 8; ++w) t += s_red[w];
            s_tot = t;
        }
        __syncthreads();
    }

    for (int sweep = 0; sweep < 16; ++sweep) {
        float off = 0.0f;
        for (int idx = tid; idx < N*N; idx += NT) {
            int i = idx >> 6, j = idx & 63;
            if (i != j) { float v = A[i*LD + j]; off += v * v; }
        }
#pragma unroll
        for (int o = 16; o > 0; o >>= 1)
            off += __shfl_down_sync(0xffffffffu, off, o);
        if ((tid & 31) == 0) s_red[tid >> 5] = off;
        __syncthreads();
        if (tid == 0) {
            float o = 0.0f;
            for (int w = 0; w < 8; ++w) o += s_red[w];
            float gate = tau * s_tot;
            s_go   = (o > gate) ? 1 : 0;
            s_thr2 = fmaxf(gate, o) * (1.0f / 8192.0f);
        }
        __syncthreads();
        if (!s_go) break;

        for (int r = 0; r < 63; ++r) {
            if (tid < 32) {
                int i = tid, p, q;
                if (i == 0) { p = 63; q = r; }
                else        { p = (r + i) % 63; q = (r + 63 - i) % 63; }
                if (p > q) { int t2 = p; p = q; q = t2; }
                float apq = A[p*LD + q];
                float c = 1.0f, s = 0.0f;
                if (apq * apq > s_thr2) {
                    float app = A[p*LD + p], aqq = A[q*LD + q];
                    float tau2 = (aqq - app) / (2.0f * apq);
                    float t    = copysignf(1.0f, tau2) / (fabsf(tau2) + sqrtf(1.0f + tau2 * tau2));
                    c = 1.0f / sqrtf(1.0f + t * t);
                    s = t * c;
                }
                s_p[i] = p; s_q[i] = q; s_c[i] = c; s_s[i] = s;
            }
            __syncthreads();
#pragma unroll
            for (int w = 0; w < 8; ++w) {
                int pi = pb + 4 * w;
                float s = s_s[pi];
                if (s != 0.0f) {
                    float c = s_c[pi];
                    int p = s_p[pi], q = s_q[pi];
                    float x = A[lane6*LD + p], y = A[lane6*LD + q];
                    A[lane6*LD + p] = c * x - s * y;
                    A[lane6*LD + q] = s * x + c * y;
                }
            }
            __syncthreads();
#pragma unroll
            for (int w = 0; w < 8; ++w) {
                int pi = pb + 4 * w;
                float s = s_s[pi];
                if (s != 0.0f) {
                    float c = s_c[pi];
                    int p = s_p[pi], q = s_q[pi];
                    float x = A[p*LD + lane6], y = A[q*LD + lane6];
                    A[p*LD + lane6] = c * x - s * y;
                    A[q*LD + lane6] = s * x + c * y;
                    float vx = V[lane6*LD + p], vy = V[lane6*LD + q];
                    V[lane6*LD + p] = c * vx - s * vy;
                    V[lane6*LD + q] = s * vx + c * vy;
                }
            }
            __syncthreads();
        }
    }
    __syncthreads();
}

// ----------------------------------------------------------------------------
// Reductions
// ----------------------------------------------------------------------------
__global__ void __launch_bounds__(NT) reduce32_kernel(const float* __restrict__ src,
                                                      float* __restrict__ dst, int Bsz) {
    int j = blockIdx.x;
    int b0 = j * 32;
    int cnt = min(32, Bsz - b0);
    for (int i = threadIdx.x; i < N*N; i += NT) {
        float a = 0.0f;
        for (int k = 0; k < cnt; ++k)
            a += src[(size_t)(b0 + k) * (N*N) + i];
        dst[(size_t)j * (N*N) + i] = a;
    }
}
__global__ void __launch_bounds__(NT) reduceFinal_kernel(const float* __restrict__ part,
                                                         float* __restrict__ dst,
                                                         int nb, float scale) {
    int i = blockIdx.x * NT + threadIdx.x;
    float a = 0.0f;
    for (int j = 0; j < nb; ++j)
        a += part[(size_t)j * (N*N) + i];
    dst[i] = a * scale;
}

// ----------------------------------------------------------------------------
// Single-matrix kernels (unchanged structure)
// ----------------------------------------------------------------------------
__global__ void __launch_bounds__(NT) prep_M_kernel(int warm) {
    extern __shared__ float sm[];
    float *b0 = sm, *b1 = sm + TILE, *b2 = sm + 2*TILE, *b3 = sm + 3*TILE;
    g2s(b0, g_M);
    float *pA, *fr;
    if (warm) {
        g2s(b1, g_VM);
        gemm_nn(b2, b0, b1);
        gemm_tn(b3, b1, b2);
        symmetrize(b3);
        pA = b3; fr = b0;
    } else {
        set_identity(b1);
        symmetrize(b0);
        pA = b0; fr = b3;
    }
    jacobi(pA, b1, TAU_SINGLE);
    s2g(g_VM, b1);
    colscale(b2, b1, pA, 2);
    gemm_nt(fr, b2, b1);
    s2g(g_Ms, fr);
    colscale(b2, b1, pA, 3);
    gemm_nt(fr, b2, b1);
    s2g(g_Mis, fr);
}

__global__ void __launch_bounds__(NT) update_M_kernel(int warm) {
    extern __shared__ float sm[];
    float *b0 = sm, *b1 = sm + TILE, *b2 = sm + 2*TILE, *b3 = sm + 3*TILE;
    g2s(b0, g_L);
    float *pA, *fr;
    if (warm) {
        g2s(b1, g_VL);
        gemm_nn(b2, b0, b1);
        gemm_tn(b3, b1, b2);
        symmetrize(b3);
        pA = b3; fr = b0;
    } else {
        set_identity(b1);
        symmetrize(b0);
        pA = b0; fr = b3;
    }
    jacobi(pA, b1, TAU_SINGLE);
    s2g(g_VL, b1);
    colscale(b2, b1, pA, 1);
    gemm_nt(fr, b2, b1);
    g2s(b1, g_Ms);
    gemm_nn(b2, b1, fr);
    gemm_nn(pA, b2, b1);
    for (int idx = threadIdx.x; idx < N*N; idx += NT) {
        int i = idx >> 6, j = idx & 63;
        g_M[idx] = 0.5f * (pA[i*LD + j] + pA[j*LD + i]);
    }
}

__global__ void __launch_bounds__(NT) final_prep_kernel(const float* __restrict__ bias) {
    extern __shared__ float sm[];
    float *b0 = sm, *b1 = sm + TILE, *b2 = sm + 2*TILE, *b3 = sm + 3*TILE;
    g2s(b0, g_M);
    g2s(b1, g_VM);
    gemm_nn(b2, b0, b1);
    gemm_tn(b3, b1, b2);
    symmetrize(b3);
    jacobi(b3, b1, TAU_SINGLE);
    colscale(b2, b1, b3, 3);
    gemm_nt(b0, b2, b1);       // W -> b0
    for (int idx = threadIdx.x; idx < N*LD; idx += NT) b3[idx] = b0[idx];
    __syncthreads();
    for (int idx = threadIdx.x; idx < N*N; idx += NT) {
        int i = idx >> 6, j = idx & 63;
        b0[i*LD + j] = 0.25f * (bias[i*N + j] + bias[j*N + i]);
    }
    __syncthreads();
    set_identity(b1);
    jacobi(b0, b1, TAU_SINGLE);
    colscale(b2, b1, b0, 1);
    gemm_nt(b0, b2, b1);       // Bs
    gemm_nn(b2, b0, b3);       // C = Bs W
    s2g(g_C, b2);
}

__global__ void __launch_bounds__(NT) apply_kernel(const float* __restrict__ data,
                                                   float* __restrict__ out) {
    extern __shared__ float sm[];
    float *b0 = sm, *b1 = sm + TILE, *b2 = sm + 2*TILE, *b3 = sm + 3*TILE;
    const size_t b = blockIdx.x;
    g2s(b1, g_C);
    g2s(b0, data + b * (N*N));
    gemm_nn(b2, b1, b0);
    gemm_nt(b3, b2, b1);
    s2g(out + b * (N*N), b3);
}

// ----------------------------------------------------------------------------
// NEW: batch logm via register-resident one-sided (Hestenes) Jacobi.
// One warp per matrix, 8 matrices per block. Each lane holds 2 columns of W
// in registers. No block barriers after the Mis load; no shared traffic in
// the rotation loop. For PSD Y: at convergence w_k = lambda_k v_k, so
// logm(Y) = W diag(log(l)/l^2) W^T and V = W diag(1/l) — no V accumulation.
// ----------------------------------------------------------------------------
__global__ void __launch_bounds__(256) batch_log8_kernel(const float* __restrict__ data,
                                                         int warm, int store_v, int Bsz) {
    extern __shared__ float sm[];
    float* mis = sm;                         // 64 x LD, shared by all warps
    const int tid  = threadIdx.x;
    const int wid  = tid >> 5;
    const int lane = tid & 31;
    float* tile = sm + TILE * (1 + wid);     // per-warp 64 x LD scratch
    const unsigned FULL = 0xffffffffu;

    for (int idx = tid; idx < N*N; idx += 256)
        mis[(idx >> 6)*LD + (idx & 63)] = g_Mis[idx];
    __syncthreads();

    const int b = blockIdx.x * 8 + wid;
    if (b >= Bsz) return;

    const float* X = data + (size_t)b * (N*N);
    // stage X into tile (coalesced global read)
    for (int idx = lane; idx < 1024; idx += 32) {
        float4 v = ((const float4*)X)[idx];
        int r = idx >> 4, c = (idx & 15) << 2;
        tile[r*LD + c + 0] = v.x;
        tile[r*LD + c + 1] = v.y;
        tile[r*LD + c + 2] = v.z;
        tile[r*LD + c + 3] = v.w;
    }
    __syncwarp();

    const int c1 = lane, c2 = lane + 32;
    float wt[64], wb[64];

    // ---- GEMM1: Z = X * Mis (columns c1, c2) ----
#pragma unroll
    for (int j = 0; j < 64; ++j) { wt[j] = 0.0f; wb[j] = 0.0f; }
    for (int k = 0; k < 64; ++k) {
        float m1 = mis[k*LD + c1];
        float m2 = mis[k*LD + c2];
#pragma unroll
        for (int i = 0; i < 64; ++i) {
            float x = tile[i*LD + k];         // broadcast
            wt[i] = fmaf(x, m1, wt[i]);
            wb[i] = fmaf(x, m2, wb[i]);
        }
    }
    __syncwarp();
    // store Z as tile[k][c]
#pragma unroll
    for (int k = 0; k < 64; ++k) { tile[k*LD + c1] = wt[k]; tile[k*LD + c2] = wb[k]; }
    __syncwarp();

    // ---- GEMM2: Y = Mis * Z ----
#pragma unroll
    for (int j = 0; j < 64; ++j) { wt[j] = 0.0f; wb[j] = 0.0f; }
    for (int k = 0; k < 64; ++k) {
        float z1 = tile[k*LD + c1];
        float z2 = tile[k*LD + c2];
#pragma unroll
        for (int i = 0; i < 64; ++i) {
            float m = mis[i*LD + k];          // broadcast
            wt[i] = fmaf(m, z1, wt[i]);
            wb[i] = fmaf(m, z2, wb[i]);
        }
    }

    // ---- warm start: W0 = Y * Vprev ----
    if (warm) {
        __syncwarp();
#pragma unroll
        for (int i = 0; i < 64; ++i) { tile[i*LD + c1] = wt[i]; tile[i*LD + c2] = wb[i]; } // Y[i][c]
        __syncwarp();
        const float* Vp = g_Vw + (size_t)b * (N*N);   // row-major V[k][c]
#pragma unroll
        for (int j = 0; j < 64; ++j) { wt[j] = 0.0f; wb[j] = 0.0f; }
        for (int k = 0; k < 64; ++k) {
            float v1 = Vp[k*64 + c1];                 // coalesced
            float v2 = Vp[k*64 + c2];
#pragma unroll
            for (int i = 0; i < 64; ++i) {
                float y = tile[i*LD + k];             // broadcast
                wt[i] = fmaf(y, v1, wt[i]);
                wb[i] = fmaf(y, v2, wb[i]);
            }
        }
    }

    // ---- one-sided Jacobi sweeps (circle-method round robin) ----
    float dtt, dbb;
    for (int sweep = 0; sweep < 15; ++sweep) {
        // exact norms at sweep start (controls drift)
        {
            float a0=0,a1=0,a2=0,a3=0, e0=0,e1=0,e2=0,e3=0;
#pragma unroll
            for (int j = 0; j < 64; j += 4) {
                a0 = fmaf(wt[j],   wt[j],   a0);
                a1 = fmaf(wt[j+1], wt[j+1], a1);
                a2 = fmaf(wt[j+2], wt[j+2], a2);
                a3 = fmaf(wt[j+3], wt[j+3], a3);
                e0 = fmaf(wb[j],   wb[j],   e0);
                e1 = fmaf(wb[j+1], wb[j+1], e1);
                e2 = fmaf(wb[j+2], wb[j+2], e2);
                e3 = fmaf(wb[j+3], wb[j+3], e3);
            }
            dtt = (a0+a1)+(a2+a3);
            dbb = (e0+e1)+(e2+e3);
        }
        int rotated = 0;
        for (int r = 0; r < 63; ++r) {
            float p0=0,p1=0,p2=0,p3=0;
#pragma unroll
            for (int j = 0; j < 64; j += 4) {
                p0 = fmaf(wt[j],   wb[j],   p0);
                p1 = fmaf(wt[j+1], wb[j+1], p1);
                p2 = fmaf(wt[j+2], wb[j+2], p2);
                p3 = fmaf(wt[j+3], wb[j+3], p3);
            }
            float dtb = (p0+p1)+(p2+p3);
            bool rot = (dtb*dtb > 1e-10f * dtt * dbb);
            if (__any_sync(FULL, rot)) {
                rotated = 1;
                float c = 1.0f, s = 0.0f;
                if (rot) {
                    float ta = (dbb - dtt) / (2.0f * dtb);
                    float t  = copysignf(1.0f, ta) / (fabsf(ta) + sqrtf(fmaf(ta, ta, 1.0f)));
                    c = rsqrtf(fmaf(t, t, 1.0f));
                    s = t * c;
                }
#pragma unroll
                for (int j = 0; j < 64; ++j) {
                    float x = wt[j], y = wb[j];
                    wt[j] = fmaf(c, x, -s * y);
                    wb[j] = fmaf(s, x,  c * y);
                }
                float cc = c*c, ss = s*s, cs2 = 2.0f*c*s;
                float ntt = cc*dtt - cs2*dtb + ss*dbb;
                float nbb = ss*dtt + cs2*dtb + cc*dbb;
                dtt = ntt; dbb = nbb;
            }
            // circle-method exchange: top stream shifts +1 (pos 0 fixed),
            // bottom stream shifts -1; boundary fixups at lanes 0/1/31.
#pragma unroll
            for (int j = 0; j < 64; ++j) {
                float sv = (lane == 0) ? wb[j] : wt[j];
                float ut = __shfl_up_sync(FULL, sv, 1);
                float db = __shfl_down_sync(FULL, wb[j], 1);
                float oldt = wt[j];
                wt[j] = (lane == 0)  ? oldt : ut;
                wb[j] = (lane == 31) ? oldt : db;
            }
            {
                float sv = (lane == 0) ? dbb : dtt;
                float ut = __shfl_up_sync(FULL, sv, 1);
                float db = __shfl_down_sync(FULL, dbb, 1);
                float oldt = dtt;
                dtt = (lane == 0)  ? oldt : ut;
                dbb = (lane == 31) ? oldt : db;
            }
        }
        if (!rotated) break;
    }

    // ---- extract lambda, write W^T + g into tile ----
    float n1 = 0.0f, n2 = 0.0f;
    {
        float a0=0,a1=0, e0=0,e1=0;
#pragma unroll
        for (int j = 0; j < 64; j += 2) {
            a0 = fmaf(wt[j],   wt[j],   a0);
            a1 = fmaf(wt[j+1], wt[j+1], a1);
            e0 = fmaf(wb[j],   wb[j],   e0);
            e1 = fmaf(wb[j+1], wb[j+1], e1);
        }
        n1 = a0 + a1; n2 = e0 + e1;
    }
    n1 = fmaxf(n1, 1e-30f);
    n2 = fmaxf(n2, 1e-30f);
    float inv1 = rsqrtf(n1), inv2 = rsqrtf(n2);
    float g1 = 0.5f * logf(n1) / n1;     // log(lambda)/lambda^2
    float g2 = 0.5f * logf(n2) / n2;

    __syncwarp();
#pragma unroll
    for (int j = 0; j < 64; ++j) { tile[c1*LD + j] = wt[j]; tile[c2*LD + j] = wb[j]; }
    tile[c1*LD + 64] = g1;
    tile[c2*LD + 64] = g2;
    __syncwarp();

    // ---- O = W diag(g) W^T  (output columns c1, c2; O symmetric) ----
#pragma unroll
    for (int j = 0; j < 64; ++j) { wt[j] = 0.0f; wb[j] = 0.0f; }
    for (int k = 0; k < 64; ++k) {
        float gk = tile[k*LD + 64];               // broadcast
        float a1 = gk * tile[k*LD + c1];          // conflict-free (stride 65)
        float a2 = gk * tile[k*LD + c2];
#pragma unroll
        for (int i = 0; i < 64; ++i) {
            float s = tile[k*LD + i];             // broadcast
            wt[i] = fmaf(s, a1, wt[i]);
            wb[i] = fmaf(s, a2, wb[i]);
        }
    }
    float* Ob = g_scratch + (size_t)b * (N*N);
#pragma unroll
    for (int j = 0; j < 16; ++j) {
        ((float4*)Ob)[c1*16 + j] = make_float4(wt[4*j], wt[4*j+1], wt[4*j+2], wt[4*j+3]);
        ((float4*)Ob)[c2*16 + j] = make_float4(wb[4*j], wb[4*j+1], wb[4*j+2], wb[4*j+3]);
    }

    // ---- store V row-major for next iteration's warm start ----
    if (store_v) {
        float* Vd = g_Vw + (size_t)b * (N*N);
#pragma unroll
        for (int k = 0; k < 64; ++k) {
            Vd[k*64 + c1] = tile[c1*LD + k] * inv1;   // coalesced stores
            Vd[k*64 + c2] = tile[c2*LD + k] * inv2;
        }
    }
}

// ----------------------------------------------------------------------------
// Host launcher
// ----------------------------------------------------------------------------
extern "C" void kernel_launch(void* const* d_in, const int* in_sizes, int n_in,
                              void* d_out, int out_size) {
    const float* data = (const float*)d_in[0];
    const float* bias = (const float*)d_in[1];
    int sz0 = in_sizes[0], sz1 = (n_in > 1) ? in_sizes[1] : 0;
    if (sz0 == N*N && sz1 > N*N) {
        data = (const float*)d_in[1];
        bias = (const float*)d_in[0];
        int t = sz0; sz0 = sz1; sz1 = t;
    }
    int Bsz = sz0 / (N*N);
    if (Bsz > MAXB) Bsz = MAXB;
    float* out = (float*)d_out;

    const size_t shmem  = 4 * TILE * sizeof(float);   // 66,560 B
    const size_t shmem8 = 9 * TILE * sizeof(float);   // 149,760 B
    cudaFuncSetAttribute(prep_M_kernel,     cudaFuncAttributeMaxDynamicSharedMemorySize, (int)shmem);
    cudaFuncSetAttribute(batch_log8_kernel, cudaFuncAttributeMaxDynamicSharedMemorySize, (int)shmem8);
    cudaFuncSetAttribute(update_M_kernel,   cudaFuncAttributeMaxDynamicSharedMemorySize, (int)shmem);
    cudaFuncSetAttribute(final_prep_kernel, cudaFuncAttributeMaxDynamicSharedMemorySize, (int)shmem);
    cudaFuncSetAttribute(apply_kernel,      cudaFuncAttributeMaxDynamicSharedMemorySize, (int)shmem);

    float *pM, *pL, *pScr, *pPart;
    cudaGetSymbolAddress((void**)&pM,    g_M);
    cudaGetSymbolAddress((void**)&pL,    g_L);
    cudaGetSymbolAddress((void**)&pScr,  g_scratch);
    cudaGetSymbolAddress((void**)&pPart, g_partial);

    const int nb1 = (Bsz + 31) / 32;
    const int nb8 = (Bsz + 7) / 8;
    const float inv = 1.0f / (float)Bsz;

    reduce32_kernel    <<<nb1, NT>>>(data, pPart, Bsz);
    reduceFinal_kernel <<<16,  NT>>>(pPart, pM, nb1, inv);

    for (int it = 0; it < 5; ++it) {
        prep_M_kernel     <<<1,   NT, shmem>>>(it > 0 ? 1 : 0);
        batch_log8_kernel <<<nb8, 256, shmem8>>>(data, it > 0 ? 1 : 0, it < 4 ? 1 : 0, Bsz);
        reduce32_kernel    <<<nb1, NT>>>(pScr, pPart, Bsz);
        reduceFinal_kernel <<<16,  NT>>>(pPart, pL, nb1, inv);
        update_M_kernel   <<<1,   NT, shmem>>>(it > 0 ? 1 : 0);
    }

    final_prep_kernel <<<1,   NT, shmem>>>(bias);
    apply_kernel      <<<Bsz, NT, shmem>>>(data, out);
}

// round 8
// speedup vs baseline: 2.7758x; 1.3318x over previous
#include <cuda_runtime.h>
#include <math.h>

#define N    64
#define LD   65            // padded leading dim in shared
#define NT   256
#define TILE (N*LD)
#define MAXB 8192

// ----------------------------------------------------------------------------
// Global scratch
// ----------------------------------------------------------------------------
__device__ float g_M  [N*N];
__device__ float g_Ms [N*N];
__device__ float g_Mis[N*N];
__device__ float g_L  [N*N];
__device__ float g_C  [N*N];
__device__ float g_VM [N*N];                   // warm-start eigvecs of M (row-major [k][c])
__device__ float g_VL [N*N];                   // warm-start eigvecs of L+sI
__device__ float g_scratch[(size_t)MAXB*N*N];  // per-matrix logm
__device__ float g_Vw     [(size_t)MAXB*N*N];  // per-matrix eigvecs, row-major [k][c]
__device__ float g_partial[(MAXB/32)*N*N];

// ----------------------------------------------------------------------------
// Warp-level one-sided (Hestenes) Jacobi with odd-even (brick-wall) ordering.
// Lane l holds the columns at positions 2l (A) and 2l+1 (B), 64 floats each.
// Even rounds: intra-lane pair (A,B), rotate then swap (register rename).
// Odd rounds:  pair (B_l, A_{l+1}) via shfl; positions swap across the lane
// boundary. 64 rounds/sweep covers all C(64,2) pairs exactly once.
// On exit columns satisfy w_k = lambda_k v_k (PSD input).
// ----------------------------------------------------------------------------
__device__ __forceinline__ void hestenes(float (&A)[64], float (&B)[64],
                                         int lane, int max_sweeps) {
    const unsigned FULL = 0xffffffffu;
    for (int sweep = 0; sweep < max_sweeps; ++sweep) {
        // fresh squared norms (controls drift)
        float nA, nB;
        {
            float a0=0,a1=0,b0=0,b1=0;
#pragma unroll
            for (int j = 0; j < 64; j += 2) {
                a0 = fmaf(A[j],A[j],a0);   a1 = fmaf(A[j+1],A[j+1],a1);
                b0 = fmaf(B[j],B[j],b0);   b1 = fmaf(B[j+1],B[j+1],b1);
            }
            nA = a0+a1; nB = b0+b1;
        }
        int rotated = 0;
        for (int rr = 0; rr < 32; ++rr) {
            // ---- even round: pair (A,B) within lane ----
            {
                float d0=0,d1=0,d2=0,d3=0;
#pragma unroll
                for (int j = 0; j < 64; j += 4) {
                    d0 = fmaf(A[j],  B[j],  d0);
                    d1 = fmaf(A[j+1],B[j+1],d1);
                    d2 = fmaf(A[j+2],B[j+2],d2);
                    d3 = fmaf(A[j+3],B[j+3],d3);
                }
                float d = (d0+d1)+(d2+d3);
                bool rot = d*d > 1e-10f*nA*nB;
                if (__any_sync(FULL, rot)) {
                    rotated = 1;
                    float c = 1.0f, s = 0.0f;
                    if (rot) {
                        float ta = (nB-nA)/(2.0f*d);
                        float t  = copysignf(1.0f,ta)/(fabsf(ta)+sqrtf(fmaf(ta,ta,1.0f)));
                        c = rsqrtf(fmaf(t,t,1.0f)); s = t*c;
                    }
#pragma unroll
                    for (int j = 0; j < 64; ++j) {
                        float x = A[j], y = B[j];
                        A[j] = fmaf(s,x, c*y);    // v -> pos 2l   (swap)
                        B[j] = fmaf(c,x,-s*y);    // u -> pos 2l+1
                    }
                    float cc=c*c, ss=s*s, cs2=2.0f*c*s;
                    float nu = cc*nA - cs2*d + ss*nB;
                    float nv = ss*nA + cs2*d + cc*nB;
                    nA = nv; nB = nu;
                } else {
#pragma unroll
                    for (int j = 0; j < 64; ++j) { float x=A[j]; A[j]=B[j]; B[j]=x; }
                    float t = nA; nA = nB; nB = t;
                }
            }
            // ---- odd round: pair (B_l, A_{l+1}); positions 0 and 63 idle ----
            {
                float ny = __shfl_down_sync(FULL, nA, 1);
                float d0=0,d1=0;
#pragma unroll
                for (int j = 0; j < 64; j += 2) {
                    float y0 = __shfl_down_sync(FULL, A[j],   1);
                    float y1 = __shfl_down_sync(FULL, A[j+1], 1);
                    d0 = fmaf(B[j],  y0, d0);
                    d1 = fmaf(B[j+1],y1, d1);
                }
                float d = d0+d1;
                bool rot = (lane < 31) && (d*d > 1e-10f*nB*ny);
                if (__any_sync(FULL, rot)) rotated = 1;
                float c = 1.0f, s = 0.0f;
                if (rot) {
                    float ta = (ny-nB)/(2.0f*d);
                    float t  = copysignf(1.0f,ta)/(fabsf(ta)+sqrtf(fmaf(ta,ta,1.0f)));
                    c = rsqrtf(fmaf(t,t,1.0f)); s = t*c;
                }
                // rotate + swap: pos 2l+1 <- v, pos 2l+2 <- u (quiet lanes: pure swap)
#pragma unroll
                for (int j = 0; j < 64; ++j) {
                    float x = B[j];
                    float y = __shfl_down_sync(FULL, A[j], 1);
                    float u = fmaf(c,x,-s*y);
                    float v = fmaf(s,x, c*y);
                    float us = __shfl_up_sync(FULL, u, 1);
                    B[j] = (lane==31) ? B[j] : v;
                    A[j] = (lane==0)  ? A[j] : us;
                }
                float cc=c*c, ss=s*s, cs2=2.0f*c*s;
                float nu = cc*nB - cs2*d + ss*ny;
                float nv = ss*nB + cs2*d + cc*ny;
                float nus = __shfl_up_sync(FULL, nu, 1);
                nB = (lane==31) ? nB : nv;
                nA = (lane==0)  ? nA : nus;
            }
        }
        if (!rotated) break;
    }
}

// ----------------------------------------------------------------------------
// Warp GEMM helpers (1 warp computes two output columns: c=lane, c=lane+32)
// ----------------------------------------------------------------------------
// o[:,c] = Ash * Bsh[:,c]   (Ash broadcast rows, Bsh columns, LD-padded shared)
__device__ __forceinline__ void wgemm_cols(float (&o1)[64], float (&o2)[64],
                                           const float* Ash, const float* Bsh, int lane) {
#pragma unroll
    for (int j = 0; j < 64; ++j) { o1[j] = 0.0f; o2[j] = 0.0f; }
    for (int k = 0; k < 64; ++k) {
        float b1 = Bsh[k*LD + lane];
        float b2 = Bsh[k*LD + lane + 32];
#pragma unroll
        for (int i = 0; i < 64; ++i) {
            float a = Ash[i*LD + k];
            o1[i] = fmaf(a, b1, o1[i]);
            o2[i] = fmaf(a, b2, o2[i]);
        }
    }
}
// o[:,c] = sum_k g[k] * W[:,k] * W[c,k], with Wt[k][j] = W[j][k] in shared
__device__ __forceinline__ void wouter_cols(float (&o1)[64], float (&o2)[64],
                                            const float* Wt, const float* g, int lane) {
#pragma unroll
    for (int j = 0; j < 64; ++j) { o1[j] = 0.0f; o2[j] = 0.0f; }
    for (int k = 0; k < 64; ++k) {
        float gk = g[k];
        float a1 = gk * Wt[k*LD + lane];
        float a2 = gk * Wt[k*LD + lane + 32];
#pragma unroll
        for (int i = 0; i < 64; ++i) {
            float s = Wt[k*LD + i];
            o1[i] = fmaf(s, a1, o1[i]);
            o2[i] = fmaf(s, a2, o2[i]);
        }
    }
}

// ----------------------------------------------------------------------------
// Block helpers for apply_kernel
// ----------------------------------------------------------------------------
__device__ __forceinline__ void g2s(float* S, const float* __restrict__ G) {
    for (int idx = threadIdx.x; idx < N*N; idx += NT)
        S[(idx >> 6) * LD + (idx & 63)] = G[idx];
    __syncthreads();
}
__device__ __forceinline__ void s2g(float* __restrict__ G, const float* S) {
    for (int idx = threadIdx.x; idx < N*N; idx += NT)
        G[idx] = S[(idx >> 6) * LD + (idx & 63)];
    __syncthreads();
}
__device__ __forceinline__ void gemm_nn(float* D, const float* A, const float* B) {
    const int tx = (threadIdx.x & 15) << 2;
    const int ty = (threadIdx.x >> 4) << 2;
    float acc[4][4] = {};
#pragma unroll 8
    for (int k = 0; k < N; ++k) {
        float a0 = A[(ty+0)*LD + k], a1 = A[(ty+1)*LD + k];
        float a2 = A[(ty+2)*LD + k], a3 = A[(ty+3)*LD + k];
        float b0 = B[k*LD + tx+0], b1 = B[k*LD + tx+1];
        float b2 = B[k*LD + tx+2], b3 = B[k*LD + tx+3];
        acc[0][0]+=a0*b0; acc[0][1]+=a0*b1; acc[0][2]+=a0*b2; acc[0][3]+=a0*b3;
        acc[1][0]+=a1*b0; acc[1][1]+=a1*b1; acc[1][2]+=a1*b2; acc[1][3]+=a1*b3;
        acc[2][0]+=a2*b0; acc[2][1]+=a2*b1; acc[2][2]+=a2*b2; acc[2][3]+=a2*b3;
        acc[3][0]+=a3*b0; acc[3][1]+=a3*b1; acc[3][2]+=a3*b2; acc[3][3]+=a3*b3;
    }
#pragma unroll
    for (int r = 0; r < 4; ++r)
#pragma unroll
        for (int c = 0; c < 4; ++c)
            D[(ty+r)*LD + tx + c] = acc[r][c];
    __syncthreads();
}
__device__ __forceinline__ void gemm_nt(float* D, const float* A, const float* B) {
    const int tx = (threadIdx.x & 15) << 2;
    const int ty = (threadIdx.x >> 4) << 2;
    float acc[4][4] = {};
#pragma unroll 8
    for (int k = 0; k < N; ++k) {
        float a0 = A[(ty+0)*LD + k], a1 = A[(ty+1)*LD + k];
        float a2 = A[(ty+2)*LD + k], a3 = A[(ty+3)*LD + k];
        float b0 = B[(tx+0)*LD + k], b1 = B[(tx+1)*LD + k];
        float b2 = B[(tx+2)*LD + k], b3 = B[(tx+3)*LD + k];
        acc[0][0]+=a0*b0; acc[0][1]+=a0*b1; acc[0][2]+=a0*b2; acc[0][3]+=a0*b3;
        acc[1][0]+=a1*b0; acc[1][1]+=a1*b1; acc[1][2]+=a1*b2; acc[1][3]+=a1*b3;
        acc[2][0]+=a2*b0; acc[2][1]+=a2*b1; acc[2][2]+=a2*b2; acc[2][3]+=a2*b3;
        acc[3][0]+=a3*b0; acc[3][1]+=a3*b1; acc[3][2]+=a3*b2; acc[3][3]+=a3*b3;
    }
#pragma unroll
    for (int r = 0; r < 4; ++r)
#pragma unroll
        for (int c = 0; c < 4; ++c)
            D[(ty+r)*LD + tx + c] = acc[r][c];
    __syncthreads();
}

// ----------------------------------------------------------------------------
// Reductions
// ----------------------------------------------------------------------------
__global__ void __launch_bounds__(NT) reduce32_kernel(const float* __restrict__ src,
                                                      float* __restrict__ dst, int Bsz) {
    int j = blockIdx.x;
    int b0 = j * 32;
    int cnt = min(32, Bsz - b0);
    for (int i = threadIdx.x; i < N*N; i += NT) {
        float a = 0.0f;
        for (int k = 0; k < cnt; ++k)
            a += src[(size_t)(b0 + k) * (N*N) + i];
        dst[(size_t)j * (N*N) + i] = a;
    }
}
__global__ void __launch_bounds__(NT) reduceFinal_kernel(const float* __restrict__ part,
                                                         float* __restrict__ dst,
                                                         int nb, float scale) {
    int i = blockIdx.x * NT + threadIdx.x;
    float a = 0.0f;
    for (int j = 0; j < nb; ++j)
        a += part[(size_t)j * (N*N) + i];
    dst[i] = a * scale;
}

// ----------------------------------------------------------------------------
// Single-matrix warp kernels (1 warp = 32 threads)
// ----------------------------------------------------------------------------

// eig(M) -> g_Ms = M^{1/2}, g_Mis = M^{-1/2}, V -> g_VM.  Warm from g_VM.
__global__ void __launch_bounds__(32) prep_M_kernel(int warm) {
    __shared__ float t0[TILE], t1[TILE];
    __shared__ float sG[64], sI[64];
    const int lane = threadIdx.x;
    float A[64], B[64];

    for (int idx = lane; idx < N*N; idx += 32)
        t0[(idx>>6)*LD + (idx&63)] = g_M[idx];
    __syncwarp();

    if (warm) {
        for (int idx = lane; idx < N*N; idx += 32)
            t1[(idx>>6)*LD + (idx&63)] = g_VM[idx];          // [k][c]
        __syncwarp();
        wgemm_cols(A, B, t0, t1, lane);                      // W0 = M * Vp (cols lane, lane+32)
#pragma unroll
        for (int j = 0; j < 64; ++j) { t1[j*LD + lane] = A[j]; t1[j*LD + lane + 32] = B[j]; }
        __syncwarp();
#pragma unroll
        for (int j = 0; j < 64; ++j) { A[j] = t1[j*LD + 2*lane]; B[j] = t1[j*LD + 2*lane + 1]; }
    } else {
#pragma unroll
        for (int j = 0; j < 64; ++j) { A[j] = t0[j*LD + 2*lane]; B[j] = t0[j*LD + 2*lane + 1]; }
    }

    hestenes(A, B, lane, 24);

    float n1 = 0.0f, n2 = 0.0f;
#pragma unroll
    for (int j = 0; j < 64; ++j) { n1 = fmaf(A[j],A[j],n1); n2 = fmaf(B[j],B[j],n2); }
    n1 = fmaxf(n1, 1e-30f); n2 = fmaxf(n2, 1e-30f);

#pragma unroll
    for (int j = 0; j < 64; ++j) { t1[(2*lane)*LD + j] = A[j]; t1[(2*lane+1)*LD + j] = B[j]; }
    sI[2*lane]   = rsqrtf(n1);
    sI[2*lane+1] = rsqrtf(n2);
    // Ms: g = lambda^{-3/2} = n^{-3/4}
    sG[2*lane]   = expf(-0.75f * logf(n1));
    sG[2*lane+1] = expf(-0.75f * logf(n2));
    __syncwarp();

    // V -> g_VM (row-major [k][c]): V[:,c] = W[:,c]/lambda_c
    for (int k = 0; k < 64; ++k) {
        g_VM[k*64 + lane]      = t1[lane*LD + k]      * sI[lane];
        g_VM[k*64 + lane + 32] = t1[(lane+32)*LD + k] * sI[lane+32];
    }
    wouter_cols(A, B, t1, sG, lane);                          // Ms (symmetric)
#pragma unroll
    for (int j = 0; j < 16; ++j) {
        ((float4*)g_Ms)[lane*16 + j]      = make_float4(A[4*j],A[4*j+1],A[4*j+2],A[4*j+3]);
        ((float4*)g_Ms)[(lane+32)*16 + j] = make_float4(B[4*j],B[4*j+1],B[4*j+2],B[4*j+3]);
    }
    // Mis: g = n^{-5/4}
    sG[2*lane]   = expf(-1.25f * logf(n1));
    sG[2*lane+1] = expf(-1.25f * logf(n2));
    __syncwarp();
    wouter_cols(A, B, t1, sG, lane);
#pragma unroll
    for (int j = 0; j < 16; ++j) {
        ((float4*)g_Mis)[lane*16 + j]      = make_float4(A[4*j],A[4*j+1],A[4*j+2],A[4*j+3]);
        ((float4*)g_Mis)[(lane+32)*16 + j] = make_float4(B[4*j],B[4*j+1],B[4*j+2],B[4*j+3]);
    }
}

// M <- sym(Ms expm(L) Ms).  eig(L + sigma I) warm from g_VL.
__global__ void __launch_bounds__(32) update_M_kernel(int warm) {
    __shared__ float t0[TILE], t1[TILE];
    __shared__ float sG[64], sI[64];
    __shared__ float s_sigma;
    const int lane = threadIdx.x;
    const unsigned FULL = 0xffffffffu;
    float A[64], B[64];

    float fro2 = 0.0f;
    for (int idx = lane; idx < N*N; idx += 32) {
        float v = g_L[idx];
        t0[(idx>>6)*LD + (idx&63)] = v;
        fro2 = fmaf(v, v, fro2);
    }
#pragma unroll
    for (int o = 16; o > 0; o >>= 1) fro2 += __shfl_down_sync(FULL, fro2, o);
    if (lane == 0) s_sigma = 1.05f * sqrtf(fro2) + 1e-12f;
    __syncwarp();
    const float sigma = s_sigma;

    if (warm) {
        for (int idx = lane; idx < N*N; idx += 32)
            t1[(idx>>6)*LD + (idx&63)] = g_VL[idx];
        __syncwarp();
        wgemm_cols(A, B, t0, t1, lane);                      // L*Vp
#pragma unroll
        for (int j = 0; j < 64; ++j) {                       // + sigma*Vp
            A[j] = fmaf(sigma, t1[j*LD + lane],      A[j]);
            B[j] = fmaf(sigma, t1[j*LD + lane + 32], B[j]);
        }
        __syncwarp();
#pragma unroll
        for (int j = 0; j < 64; ++j) { t1[j*LD + lane] = A[j]; t1[j*LD + lane + 32] = B[j]; }
        __syncwarp();
#pragma unroll
        for (int j = 0; j < 64; ++j) { A[j] = t1[j*LD + 2*lane]; B[j] = t1[j*LD + 2*lane + 1]; }
    } else {
#pragma unroll
        for (int j = 0; j < 64; ++j) {
            A[j] = t0[j*LD + 2*lane]   + ((j == 2*lane)   ? sigma : 0.0f);
            B[j] = t0[j*LD + 2*lane+1] + ((j == 2*lane+1) ? sigma : 0.0f);
        }
    }

    hestenes(A, B, lane, 24);

    float n1 = 0.0f, n2 = 0.0f;
#pragma unroll
    for (int j = 0; j < 64; ++j) { n1 = fmaf(A[j],A[j],n1); n2 = fmaf(B[j],B[j],n2); }
    n1 = fmaxf(n1, 1e-30f); n2 = fmaxf(n2, 1e-30f);

    __syncwarp();
#pragma unroll
    for (int j = 0; j < 64; ++j) { t0[(2*lane)*LD + j] = A[j]; t0[(2*lane+1)*LD + j] = B[j]; }
    sI[2*lane]   = rsqrtf(n1);
    sI[2*lane+1] = rsqrtf(n2);
    sG[2*lane]   = expf(sqrtf(n1) - sigma) / n1;             // e^{lambda}/lambda'^2
    sG[2*lane+1] = expf(sqrtf(n2) - sigma) / n2;
    __syncwarp();
    for (int k = 0; k < 64; ++k) {                           // V -> g_VL
        g_VL[k*64 + lane]      = t0[lane*LD + k]      * sI[lane];
        g_VL[k*64 + lane + 32] = t0[(lane+32)*LD + k] * sI[lane+32];
    }
    wouter_cols(A, B, t0, sG, lane);                          // E = expm(L)
    __syncwarp();
#pragma unroll
    for (int j = 0; j < 64; ++j) { t0[j*LD + lane] = A[j]; t0[j*LD + lane + 32] = B[j]; }  // t0 = E
    for (int idx = lane; idx < N*N; idx += 32)
        t1[(idx>>6)*LD + (idx&63)] = g_Ms[idx];               // t1 = Ms
    __syncwarp();
    wgemm_cols(A, B, t1, t0, lane);                           // T = Ms*E
    __syncwarp();
#pragma unroll
    for (int j = 0; j < 64; ++j) { t0[j*LD + lane] = A[j]; t0[j*LD + lane + 32] = B[j]; }  // t0 = T
    __syncwarp();
    wgemm_cols(A, B, t0, t1, lane);                           // Mn = T*Ms
    __syncwarp();
#pragma unroll
    for (int j = 0; j < 64; ++j) { t0[j*LD + lane] = A[j]; t0[j*LD + lane + 32] = B[j]; }  // t0 = Mn
    __syncwarp();
    for (int idx = lane; idx < N*N; idx += 32) {
        int i = idx >> 6, j = idx & 63;
        g_M[idx] = 0.5f * (t0[i*LD + j] + t0[j*LD + i]);
    }
}

// C = expm(0.25 (bias + bias^T)) * invsqrtm(M)
__global__ void __launch_bounds__(32) final_prep_kernel(const float* __restrict__ bias) {
    __shared__ float t0[TILE], t1[TILE];
    __shared__ float sG[64], sI[64];
    __shared__ float s_sigma;
    const int lane = threadIdx.x;
    const unsigned FULL = 0xffffffffu;
    float A[64], B[64];

    // ---- eig(M), warm from g_VM -> Mis into t0 ----
    for (int idx = lane; idx < N*N; idx += 32)
        t0[(idx>>6)*LD + (idx&63)] = g_M[idx];
    for (int idx = lane; idx < N*N; idx += 32)
        t1[(idx>>6)*LD + (idx&63)] = g_VM[idx];
    __syncwarp();
    wgemm_cols(A, B, t0, t1, lane);
    __syncwarp();
#pragma unroll
    for (int j = 0; j < 64; ++j) { t1[j*LD + lane] = A[j]; t1[j*LD + lane + 32] = B[j]; }
    __syncwarp();
#pragma unroll
    for (int j = 0; j < 64; ++j) { A[j] = t1[j*LD + 2*lane]; B[j] = t1[j*LD + 2*lane + 1]; }
    hestenes(A, B, lane, 24);
    float n1 = 0.0f, n2 = 0.0f;
#pragma unroll
    for (int j = 0; j < 64; ++j) { n1 = fmaf(A[j],A[j],n1); n2 = fmaf(B[j],B[j],n2); }
    n1 = fmaxf(n1, 1e-30f); n2 = fmaxf(n2, 1e-30f);
    __syncwarp();
#pragma unroll
    for (int j = 0; j < 64; ++j) { t1[(2*lane)*LD + j] = A[j]; t1[(2*lane+1)*LD + j] = B[j]; }
    sG[2*lane]   = expf(-1.25f * logf(n1));
    sG[2*lane+1] = expf(-1.25f * logf(n2));
    __syncwarp();
    wouter_cols(A, B, t1, sG, lane);                          // Mis
    __syncwarp();
#pragma unroll
    for (int j = 0; j < 64; ++j) { t0[j*LD + lane] = A[j]; t0[j*LD + lane + 32] = B[j]; }  // t0 = Mis
    __syncwarp();

    // ---- eig(0.25(b+b^T) + sigma I) -> Bs ----
    float fro2 = 0.0f;
    for (int idx = lane; idx < N*N; idx += 32) {
        int i = idx >> 6, j = idx & 63;
        float v = 0.25f * (bias[i*64 + j] + bias[j*64 + i]);
        t1[i*LD + j] = v;
        fro2 = fmaf(v, v, fro2);
    }
#pragma unroll
    for (int o = 16; o > 0; o >>= 1) fro2 += __shfl_down_sync(FULL, fro2, o);
    if (lane == 0) s_sigma = 1.05f * sqrtf(fro2) + 1e-12f;
    __syncwarp();
    const float sb = s_sigma;
#pragma unroll
    for (int j = 0; j < 64; ++j) {
        A[j] = t1[j*LD + 2*lane]   + ((j == 2*lane)   ? sb : 0.0f);
        B[j] = t1[j*LD + 2*lane+1] + ((j == 2*lane+1) ? sb : 0.0f);
    }
    hestenes(A, B, lane, 24);
    n1 = 0.0f; n2 = 0.0f;
#pragma unroll
    for (int j = 0; j < 64; ++j) { n1 = fmaf(A[j],A[j],n1); n2 = fmaf(B[j],B[j],n2); }
    n1 = fmaxf(n1, 1e-30f); n2 = fmaxf(n2, 1e-30f);
    __syncwarp();
#pragma unroll
    for (int j = 0; j < 64; ++j) { t1[(2*lane)*LD + j] = A[j]; t1[(2*lane+1)*LD + j] = B[j]; }
    sG[2*lane]   = expf(sqrtf(n1) - sb) / n1;
    sG[2*lane+1] = expf(sqrtf(n2) - sb) / n2;
    __syncwarp();
    wouter_cols(A, B, t1, sG, lane);                          // Bs
    __syncwarp();
#pragma unroll
    for (int j = 0; j < 64; ++j) { t1[j*LD + lane] = A[j]; t1[j*LD + lane + 32] = B[j]; }  // t1 = Bs
    __syncwarp();
    wgemm_cols(A, B, t1, t0, lane);                           // C = Bs * Mis
    for (int i = 0; i < 64; ++i) {
        g_C[i*64 + lane]      = A[i];
        g_C[i*64 + lane + 32] = B[i];
    }
}

// ----------------------------------------------------------------------------
// Batch logm: one warp per matrix, 8 per block, odd-even Hestenes in registers.
// ----------------------------------------------------------------------------
__global__ void __launch_bounds__(256) batch_log8_kernel(const float* __restrict__ data,
                                                         int warm, int store_v, int Bsz) {
    extern __shared__ float sm[];
    float* mis = sm;                          // 64 x LD, shared by all warps
    const int tid  = threadIdx.x;
    const int wid  = tid >> 5;
    const int lane = tid & 31;
    float* tile = sm + TILE * (1 + wid);
    float* sG = sm + 9*TILE + wid*64;
    float* sI = sm + 9*TILE + 512 + wid*64;

    for (int idx = tid; idx < N*N; idx += 256)
        mis[(idx >> 6)*LD + (idx & 63)] = g_Mis[idx];
    __syncthreads();

    const int b = blockIdx.x * 8 + wid;
    if (b >= Bsz) return;

    const float* X = data + (size_t)b * (N*N);
    for (int idx = lane; idx < 1024; idx += 32) {
        float4 v = ((const float4*)X)[idx];
        int r = idx >> 4, c = (idx & 15) << 2;
        tile[r*LD + c + 0] = v.x;
        tile[r*LD + c + 1] = v.y;
        tile[r*LD + c + 2] = v.z;
        tile[r*LD + c + 3] = v.w;
    }
    __syncwarp();

    const int c1 = lane, c2 = lane + 32;
    float A[64], B[64];

    // GEMM1: Z = X * Mis
#pragma unroll
    for (int j = 0; j < 64; ++j) { A[j] = 0.0f; B[j] = 0.0f; }
    for (int k = 0; k < 64; ++k) {
        float m1 = mis[k*LD + c1];
        float m2 = mis[k*LD + c2];
#pragma unroll
        for (int i = 0; i < 64; ++i) {
            float x = tile[i*LD + k];
            A[i] = fmaf(x, m1, A[i]);
            B[i] = fmaf(x, m2, B[i]);
        }
    }
    __syncwarp();
#pragma unroll
    for (int k = 0; k < 64; ++k) { tile[k*LD + c1] = A[k]; tile[k*LD + c2] = B[k]; }
    __syncwarp();

    // GEMM2: Y = Mis * Z
#pragma unroll
    for (int j = 0; j < 64; ++j) { A[j] = 0.0f; B[j] = 0.0f; }
    for (int k = 0; k < 64; ++k) {
        float z1 = tile[k*LD + c1];
        float z2 = tile[k*LD + c2];
#pragma unroll
        for (int i = 0; i < 64; ++i) {
            float m = mis[i*LD + k];
            A[i] = fmaf(m, z1, A[i]);
            B[i] = fmaf(m, z2, B[i]);
        }
    }

    if (warm) {
        __syncwarp();
#pragma unroll
        for (int i = 0; i < 64; ++i) { tile[i*LD + c1] = A[i]; tile[i*LD + c2] = B[i]; }  // Y
        __syncwarp();
        const float* Vp = g_Vw + (size_t)b * (N*N);
#pragma unroll
        for (int j = 0; j < 64; ++j) { A[j] = 0.0f; B[j] = 0.0f; }
        for (int k = 0; k < 64; ++k) {
            float v1 = Vp[k*64 + c1];
            float v2 = Vp[k*64 + c2];
#pragma unroll
            for (int i = 0; i < 64; ++i) {
                float y = tile[i*LD + k];
                A[i] = fmaf(y, v1, A[i]);
                B[i] = fmaf(y, v2, B[i]);
            }
        }
    }

    // relabel columns (c1,c2) -> positions (2*lane, 2*lane+1)
    __syncwarp();
#pragma unroll
    for (int j = 0; j < 64; ++j) { tile[j*LD + c1] = A[j]; tile[j*LD + c2] = B[j]; }
    __syncwarp();
#pragma unroll
    for (int j = 0; j < 64; ++j) { A[j] = tile[j*LD + 2*lane]; B[j] = tile[j*LD + 2*lane + 1]; }

    hestenes(A, B, lane, 16);

    float n1 = 0.0f, n2 = 0.0f;
#pragma unroll
    for (int j = 0; j < 64; ++j) { n1 = fmaf(A[j],A[j],n1); n2 = fmaf(B[j],B[j],n2); }
    n1 = fmaxf(n1, 1e-30f); n2 = fmaxf(n2, 1e-30f);

    __syncwarp();
#pragma unroll
    for (int j = 0; j < 64; ++j) { tile[(2*lane)*LD + j] = A[j]; tile[(2*lane+1)*LD + j] = B[j]; }
    sG[2*lane]   = 0.5f * logf(n1) / n1;     // log(lambda)/lambda^2
    sG[2*lane+1] = 0.5f * logf(n2) / n2;
    sI[2*lane]   = rsqrtf(n1);
    sI[2*lane+1] = rsqrtf(n2);
    __syncwarp();

    // O = W diag(g) W^T
    wouter_cols(A, B, tile, sG, lane);
    float* Ob = g_scratch + (size_t)b * (N*N);
#pragma unroll
    for (int j = 0; j < 16; ++j) {
        ((float4*)Ob)[c1*16 + j] = make_float4(A[4*j], A[4*j+1], A[4*j+2], A[4*j+3]);
        ((float4*)Ob)[c2*16 + j] = make_float4(B[4*j], B[4*j+1], B[4*j+2], B[4*j+3]);
    }

    if (store_v) {
        float* Vd = g_Vw + (size_t)b * (N*N);
#pragma unroll
        for (int k = 0; k < 64; ++k) {
            Vd[k*64 + c1] = tile[c1*LD + k] * sI[c1];
            Vd[k*64 + c2] = tile[c2*LD + k] * sI[c2];
        }
    }
}

// out_b = C X_b C^T
__global__ void __launch_bounds__(NT) apply_kernel(const float* __restrict__ data,
                                                   float* __restrict__ out) {
    extern __shared__ float sm[];
    float *b0 = sm, *b1 = sm + TILE, *b2 = sm + 2*TILE, *b3 = sm + 3*TILE;
    const size_t b = blockIdx.x;
    g2s(b1, g_C);
    g2s(b0, data + b * (N*N));
    gemm_nn(b2, b1, b0);
    gemm_nt(b3, b2, b1);
    s2g(out + b * (N*N), b3);
}

// ----------------------------------------------------------------------------
// Host launcher (graph-capturable)
// ----------------------------------------------------------------------------
extern "C" void kernel_launch(void* const* d_in, const int* in_sizes, int n_in,
                              void* d_out, int out_size) {
    const float* data = (const float*)d_in[0];
    const float* bias = (const float*)d_in[1];
    int sz0 = in_sizes[0], sz1 = (n_in > 1) ? in_sizes[1] : 0;
    if (sz0 == N*N && sz1 > N*N) {
        data = (const float*)d_in[1];
        bias = (const float*)d_in[0];
        int t = sz0; sz0 = sz1; sz1 = t;
    }
    int Bsz = sz0 / (N*N);
    if (Bsz > MAXB) Bsz = MAXB;
    float* out = (float*)d_out;

    const size_t shmem4 = 4 * TILE * sizeof(float);             // apply
    const size_t shmem8 = (9 * TILE + 1024) * sizeof(float);    // batch
    cudaFuncSetAttribute(batch_log8_kernel, cudaFuncAttributeMaxDynamicSharedMemorySize, (int)shmem8);
    cudaFuncSetAttribute(apply_kernel,      cudaFuncAttributeMaxDynamicSharedMemorySize, (int)shmem4);

    float *pM, *pL, *pScr, *pPart;
    cudaGetSymbolAddress((void**)&pM,    g_M);
    cudaGetSymbolAddress((void**)&pL,    g_L);
    cudaGetSymbolAddress((void**)&pScr,  g_scratch);
    cudaGetSymbolAddress((void**)&pPart, g_partial);

    const int nb1 = (Bsz + 31) / 32;
    const int nb8 = (Bsz + 7) / 8;
    const float inv = 1.0f / (float)Bsz;

    reduce32_kernel    <<<nb1, NT>>>(data, pPart, Bsz);
    reduceFinal_kernel <<<16,  NT>>>(pPart, pM, nb1, inv);

    for (int it = 0; it < 5; ++it) {
        prep_M_kernel     <<<1,   32>>>(it > 0 ? 1 : 0);
        batch_log8_kernel <<<nb8, 256, shmem8>>>(data, it > 0 ? 1 : 0, it < 4 ? 1 : 0, Bsz);
        reduce32_kernel    <<<nb1, NT>>>(pScr, pPart, Bsz);
        reduceFinal_kernel <<<16,  NT>>>(pPart, pL, nb1, inv);
        update_M_kernel   <<<1,   32>>>(it > 0 ? 1 : 0);
    }

    final_prep_kernel <<<1,   32>>>(bias);
    apply_kernel      <<<Bsz, NT, shmem4>>>(data, out);
}

// round 9
// speedup vs baseline: 2.8759x; 1.0360x over previous
#include <cuda_runtime.h>
#include <math.h>

#define N    64
#define LD   65            // padded leading dim in shared
#define NT   256
#define TILE (N*LD)
#define MAXB 8192

typedef unsigned long long u64;

// ----------------------------------------------------------------------------
// f32x2 packed helpers (sm_103a packed FP32 pipe; only reachable via PTX)
// ----------------------------------------------------------------------------
__device__ __forceinline__ u64 pk2(float lo, float hi) {
    u64 r; asm("mov.b64 %0,{%1,%2};" : "=l"(r) : "f"(lo), "f"(hi)); return r;
}
__device__ __forceinline__ void up2(u64 v, float& lo, float& hi) {
    asm("mov.b64 {%0,%1},%2;" : "=f"(lo), "=f"(hi) : "l"(v));
}
__device__ __forceinline__ u64 fma2(u64 a, u64 b, u64 c) {
    u64 r; asm("fma.rn.f32x2 %0,%1,%2,%3;" : "=l"(r) : "l"(a), "l"(b), "l"(c)); return r;
}
__device__ __forceinline__ u64 mul2(u64 a, u64 b) {
    u64 r; asm("mul.rn.f32x2 %0,%1,%2;" : "=l"(r) : "l"(a), "l"(b)); return r;
}

// ----------------------------------------------------------------------------
// Global scratch
// ----------------------------------------------------------------------------
__device__ float g_M  [N*N];
__device__ float g_Ms [N*N];
__device__ float g_Mis[N*N];
__device__ float g_L  [N*N];
__device__ float g_C  [N*N];
__device__ float g_VM [N*N];                   // warm-start eigvecs of M (row-major [k][c])
__device__ float g_VL [N*N];                   // warm-start eigvecs of L+sI
__device__ float g_scratch[(size_t)MAXB*N*N];  // per-matrix logm
__device__ float g_Vw     [(size_t)MAXB*N*N];  // per-matrix eigvecs, row-major [k][c]
__device__ float g_partial[(MAXB/32)*N*N];

// ----------------------------------------------------------------------------
// Packed one-sided (Hestenes) Jacobi, odd-even ordering. Lane l holds columns
// at positions 2l (A) and 2l+1 (B); each column is 32 packed f32x2 values
// (element j lives in A[j>>1] half j&1). Even rounds pair (A,B) in-lane and
// swap; odd rounds pair (B_l, A_{l+1}) via shfl and swap across the boundary.
// 64 rounds/sweep covers all C(64,2) pairs once. PSD input: on exit
// w_k = lambda_k v_k.
// ----------------------------------------------------------------------------
__device__ __forceinline__ void hestenes_p(u64 (&A)[32], u64 (&B)[32],
                                           int lane, int max_sweeps) {
    const unsigned FULL = 0xffffffffu;
    for (int sweep = 0; sweep < max_sweeps; ++sweep) {
        float nA, nB;
        {
            u64 aa = 0ull, bb = 0ull;
#pragma unroll
            for (int i = 0; i < 32; ++i) {
                aa = fma2(A[i], A[i], aa);
                bb = fma2(B[i], B[i], bb);
            }
            float a0,a1,b0,b1; up2(aa,a0,a1); up2(bb,b0,b1);
            nA = a0+a1; nB = b0+b1;
        }
        int rotated = 0;
        for (int rr = 0; rr < 32; ++rr) {
            // ---- even round: pair (A,B) within lane ----
            {
                u64 acc = 0ull;
#pragma unroll
                for (int i = 0; i < 32; ++i) acc = fma2(A[i], B[i], acc);
                float d0,d1; up2(acc,d0,d1);
                float d = d0+d1;
                bool rot = d*d > 1e-10f*nA*nB;
                if (__any_sync(FULL, rot)) {
                    rotated = 1;
                    float c = 1.0f, s = 0.0f;
                    if (rot) {
                        float ta = (nB-nA)/(2.0f*d);
                        float t  = copysignf(1.0f,ta)/(fabsf(ta)+sqrtf(fmaf(ta,ta,1.0f)));
                        c = rsqrtf(fmaf(t,t,1.0f)); s = t*c;
                    }
                    u64 cp = pk2(c,c), sp = pk2(s,s), np = pk2(-s,-s);
#pragma unroll
                    for (int i = 0; i < 32; ++i) {
                        u64 x = A[i], y = B[i];
                        A[i] = fma2(sp, x, mul2(cp, y));   // v -> pos 2l (swap)
                        B[i] = fma2(cp, x, mul2(np, y));   // u -> pos 2l+1
                    }
                    float cc=c*c, ss=s*s, cs2=2.0f*c*s;
                    float nu = cc*nA - cs2*d + ss*nB;
                    float nv = ss*nA + cs2*d + cc*nB;
                    nA = nv; nB = nu;
                } else {
#pragma unroll
                    for (int i = 0; i < 32; ++i) { u64 t=A[i]; A[i]=B[i]; B[i]=t; }
                    float t = nA; nA = nB; nB = t;
                }
            }
            // ---- odd round: pair (B_l, A_{l+1}); positions 0 and 63 idle ----
            {
                float ny = __shfl_down_sync(FULL, nA, 1);
                u64 acc = 0ull;
#pragma unroll
                for (int i = 0; i < 32; ++i) {
                    u64 y = __shfl_down_sync(FULL, A[i], 1);
                    acc = fma2(B[i], y, acc);
                }
                float d0,d1; up2(acc,d0,d1);
                float d = d0+d1;
                bool rot = (lane < 31) && (d*d > 1e-10f*nB*ny);
                if (__any_sync(FULL, rot)) {
                    rotated = 1;
                    float c = 1.0f, s = 0.0f;
                    if (rot) {
                        float ta = (ny-nB)/(2.0f*d);
                        float t  = copysignf(1.0f,ta)/(fabsf(ta)+sqrtf(fmaf(ta,ta,1.0f)));
                        c = rsqrtf(fmaf(t,t,1.0f)); s = t*c;
                    }
                    u64 cp = pk2(c,c), sp = pk2(s,s), np = pk2(-s,-s);
#pragma unroll
                    for (int i = 0; i < 32; ++i) {
                        u64 x = B[i];
                        u64 y = __shfl_down_sync(FULL, A[i], 1);
                        u64 u = fma2(cp, x, mul2(np, y));
                        u64 v = fma2(sp, x, mul2(cp, y));
                        u64 us = __shfl_up_sync(FULL, u, 1);
                        B[i] = (lane==31) ? B[i] : v;
                        A[i] = (lane==0)  ? A[i] : us;
                    }
                    float cc=c*c, ss=s*s, cs2=2.0f*c*s;
                    float nu = cc*nB - cs2*d + ss*ny;
                    float nv = ss*nB + cs2*d + cc*ny;
                    float nus = __shfl_up_sync(FULL, nu, 1);
                    nB = (lane==31) ? nB : nv;
                    nA = (lane==0)  ? nA : nus;
                } else {
                    // quiet fast-path: pure positional swap across lane boundary
#pragma unroll
                    for (int i = 0; i < 32; ++i) {
                        u64 y  = __shfl_down_sync(FULL, A[i], 1);
                        u64 xs = __shfl_up_sync(FULL, B[i], 1);
                        B[i] = (lane==31) ? B[i] : y;
                        A[i] = (lane==0)  ? A[i] : xs;
                    }
                    float nus = __shfl_up_sync(FULL, nB, 1);
                    nB = (lane==31) ? nB : ny;
                    nA = (lane==0)  ? nA : nus;
                }
            }
        }
        if (!rotated) break;
    }
}

// pack columns (2*lane, 2*lane+1) of an LD-padded shared matrix into registers
__device__ __forceinline__ void pack_cols(u64 (&A)[32], u64 (&B)[32],
                                          const float* S, int lane) {
#pragma unroll
    for (int i = 0; i < 32; ++i) {
        A[i] = pk2(S[(2*i)*LD + 2*lane],     S[(2*i+1)*LD + 2*lane]);
        B[i] = pk2(S[(2*i)*LD + 2*lane + 1], S[(2*i+1)*LD + 2*lane + 1]);
    }
}
// packed squared norms of the two held columns
__device__ __forceinline__ void norms_p(const u64 (&A)[32], const u64 (&B)[32],
                                        float& n1, float& n2) {
    u64 aa = 0ull, bb = 0ull;
#pragma unroll
    for (int i = 0; i < 32; ++i) {
        aa = fma2(A[i], A[i], aa);
        bb = fma2(B[i], B[i], bb);
    }
    float a0,a1,b0,b1; up2(aa,a0,a1); up2(bb,b0,b1);
    n1 = fmaxf(a0+a1, 1e-30f);
    n2 = fmaxf(b0+b1, 1e-30f);
}
// write held columns as ROWS 2*lane, 2*lane+1 of an LD-padded shared matrix (W^T)
__device__ __forceinline__ void unpack_rows(const u64 (&A)[32], const u64 (&B)[32],
                                            float* S, int lane) {
#pragma unroll
    for (int i = 0; i < 32; ++i) {
        float x0,x1,y0,y1;
        up2(A[i],x0,x1); up2(B[i],y0,y1);
        S[(2*lane)*LD   + 2*i]     = x0;
        S[(2*lane)*LD   + 2*i + 1] = x1;
        S[(2*lane+1)*LD + 2*i]     = y0;
        S[(2*lane+1)*LD + 2*i + 1] = y1;
    }
}

// ----------------------------------------------------------------------------
// Warp GEMM helpers (1 warp computes two output columns: c=lane, c=lane+32)
// ----------------------------------------------------------------------------
__device__ __forceinline__ void wgemm_cols(float (&o1)[64], float (&o2)[64],
                                           const float* Ash, const float* Bsh, int lane) {
#pragma unroll
    for (int j = 0; j < 64; ++j) { o1[j] = 0.0f; o2[j] = 0.0f; }
    for (int k = 0; k < 64; ++k) {
        float b1 = Bsh[k*LD + lane];
        float b2 = Bsh[k*LD + lane + 32];
#pragma unroll
        for (int i = 0; i < 64; ++i) {
            float a = Ash[i*LD + k];
            o1[i] = fmaf(a, b1, o1[i]);
            o2[i] = fmaf(a, b2, o2[i]);
        }
    }
}
// o[:,c] = sum_k g[k] * W[:,k] * W[c,k], with Wt[k][j] = W[j][k] in shared
__device__ __forceinline__ void wouter_cols(float (&o1)[64], float (&o2)[64],
                                            const float* Wt, const float* g, int lane) {
#pragma unroll
    for (int j = 0; j < 64; ++j) { o1[j] = 0.0f; o2[j] = 0.0f; }
    for (int k = 0; k < 64; ++k) {
        float gk = g[k];
        float a1 = gk * Wt[k*LD + lane];
        float a2 = gk * Wt[k*LD + lane + 32];
#pragma unroll
        for (int i = 0; i < 64; ++i) {
            float s = Wt[k*LD + i];
            o1[i] = fmaf(s, a1, o1[i]);
            o2[i] = fmaf(s, a2, o2[i]);
        }
    }
}

// ----------------------------------------------------------------------------
// Block helpers for apply_kernel
// ----------------------------------------------------------------------------
__device__ __forceinline__ void g2s(float* S, const float* __restrict__ G) {
    for (int idx = threadIdx.x; idx < N*N; idx += NT)
        S[(idx >> 6) * LD + (idx & 63)] = G[idx];
    __syncthreads();
}
__device__ __forceinline__ void s2g(float* __restrict__ G, const float* S) {
    for (int idx = threadIdx.x; idx < N*N; idx += NT)
        G[idx] = S[(idx >> 6) * LD + (idx & 63)];
    __syncthreads();
}
__device__ __forceinline__ void gemm_nn(float* D, const float* A, const float* B) {
    const int tx = (threadIdx.x & 15) << 2;
    const int ty = (threadIdx.x >> 4) << 2;
    float acc[4][4] = {};
#pragma unroll 8
    for (int k = 0; k < N; ++k) {
        float a0 = A[(ty+0)*LD + k], a1 = A[(ty+1)*LD + k];
        float a2 = A[(ty+2)*LD + k], a3 = A[(ty+3)*LD + k];
        float b0 = B[k*LD + tx+0], b1 = B[k*LD + tx+1];
        float b2 = B[k*LD + tx+2], b3 = B[k*LD + tx+3];
        acc[0][0]+=a0*b0; acc[0][1]+=a0*b1; acc[0][2]+=a0*b2; acc[0][3]+=a0*b3;
        acc[1][0]+=a1*b0; acc[1][1]+=a1*b1; acc[1][2]+=a1*b2; acc[1][3]+=a1*b3;
        acc[2][0]+=a2*b0; acc[2][1]+=a2*b1; acc[2][2]+=a2*b2; acc[2][3]+=a2*b3;
        acc[3][0]+=a3*b0; acc[3][1]+=a3*b1; acc[3][2]+=a3*b2; acc[3][3]+=a3*b3;
    }
#pragma unroll
    for (int r = 0; r < 4; ++r)
#pragma unroll
        for (int c = 0; c < 4; ++c)
            D[(ty+r)*LD + tx + c] = acc[r][c];
    __syncthreads();
}
__device__ __forceinline__ void gemm_nt(float* D, const float* A, const float* B) {
    const int tx = (threadIdx.x & 15) << 2;
    const int ty = (threadIdx.x >> 4) << 2;
    float acc[4][4] = {};
#pragma unroll 8
    for (int k = 0; k < N; ++k) {
        float a0 = A[(ty+0)*LD + k], a1 = A[(ty+1)*LD + k];
        float a2 = A[(ty+2)*LD + k], a3 = A[(ty+3)*LD + k];
        float b0 = B[(tx+0)*LD + k], b1 = B[(tx+1)*LD + k];
        float b2 = B[(tx+2)*LD + k], b3 = B[(tx+3)*LD + k];
        acc[0][0]+=a0*b0; acc[0][1]+=a0*b1; acc[0][2]+=a0*b2; acc[0][3]+=a0*b3;
        acc[1][0]+=a1*b0; acc[1][1]+=a1*b1; acc[1][2]+=a1*b2; acc[1][3]+=a1*b3;
        acc[2][0]+=a2*b0; acc[2][1]+=a2*b1; acc[2][2]+=a2*b2; acc[2][3]+=a2*b3;
        acc[3][0]+=a3*b0; acc[3][1]+=a3*b1; acc[3][2]+=a3*b2; acc[3][3]+=a3*b3;
    }
#pragma unroll
    for (int r = 0; r < 4; ++r)
#pragma unroll
        for (int c = 0; c < 4; ++c)
            D[(ty+r)*LD + tx + c] = acc[r][c];
    __syncthreads();
}

// ----------------------------------------------------------------------------
// Reductions
// ----------------------------------------------------------------------------
__global__ void __launch_bounds__(NT) reduce32_kernel(const float* __restrict__ src,
                                                      float* __restrict__ dst, int Bsz) {
    int j = blockIdx.x;
    int b0 = j * 32;
    int cnt = min(32, Bsz - b0);
    for (int i = threadIdx.x; i < N*N; i += NT) {
        float a = 0.0f;
        for (int k = 0; k < cnt; ++k)
            a += src[(size_t)(b0 + k) * (N*N) + i];
        dst[(size_t)j * (N*N) + i] = a;
    }
}
__global__ void __launch_bounds__(NT) reduceFinal_kernel(const float* __restrict__ part,
                                                         float* __restrict__ dst,
                                                         int nb, float scale) {
    int i = blockIdx.x * NT + threadIdx.x;
    float a = 0.0f;
    for (int j = 0; j < nb; ++j)
        a += part[(size_t)j * (N*N) + i];
    dst[i] = a * scale;
}

// ----------------------------------------------------------------------------
// Single-matrix warp kernels (1 warp = 32 threads)
// ----------------------------------------------------------------------------

// eig(M) -> g_Ms = M^{1/2}, g_Mis = M^{-1/2}, V -> g_VM.  Warm from g_VM.
__global__ void __launch_bounds__(32) prep_M_kernel(int warm) {
    __shared__ float t0[TILE], t1[TILE];
    __shared__ float sG[64], sI[64];
    const int lane = threadIdx.x;
    float A[64], B[64];
    u64 A2[32], B2[32];

    for (int idx = lane; idx < N*N; idx += 32)
        t0[(idx>>6)*LD + (idx&63)] = g_M[idx];
    __syncwarp();

    if (warm) {
        for (int idx = lane; idx < N*N; idx += 32)
            t1[(idx>>6)*LD + (idx&63)] = g_VM[idx];          // [k][c]
        __syncwarp();
        wgemm_cols(A, B, t0, t1, lane);                      // W0 = M * Vp
        __syncwarp();
#pragma unroll
        for (int j = 0; j < 64; ++j) { t1[j*LD + lane] = A[j]; t1[j*LD + lane + 32] = B[j]; }
        __syncwarp();
        pack_cols(A2, B2, t1, lane);
    } else {
        pack_cols(A2, B2, t0, lane);
    }

    hestenes_p(A2, B2, lane, 24);

    float n1, n2;
    norms_p(A2, B2, n1, n2);
    __syncwarp();
    unpack_rows(A2, B2, t1, lane);                            // t1 = W^T
    sI[2*lane]   = rsqrtf(n1);
    sI[2*lane+1] = rsqrtf(n2);
    // Ms: g = lambda^{-3/2} = n^{-3/4}
    sG[2*lane]   = expf(-0.75f * logf(n1));
    sG[2*lane+1] = expf(-0.75f * logf(n2));
    __syncwarp();

    // V -> g_VM (row-major [k][c]): V[:,c] = W[:,c]/lambda_c
    for (int k = 0; k < 64; ++k) {
        g_VM[k*64 + lane]      = t1[lane*LD + k]      * sI[lane];
        g_VM[k*64 + lane + 32] = t1[(lane+32)*LD + k] * sI[lane+32];
    }
    wouter_cols(A, B, t1, sG, lane);                          // Ms (symmetric)
#pragma unroll
    for (int j = 0; j < 16; ++j) {
        ((float4*)g_Ms)[lane*16 + j]      = make_float4(A[4*j],A[4*j+1],A[4*j+2],A[4*j+3]);
        ((float4*)g_Ms)[(lane+32)*16 + j] = make_float4(B[4*j],B[4*j+1],B[4*j+2],B[4*j+3]);
    }
    // Mis: g = n^{-5/4}
    sG[2*lane]   = expf(-1.25f * logf(n1));
    sG[2*lane+1] = expf(-1.25f * logf(n2));
    __syncwarp();
    wouter_cols(A, B, t1, sG, lane);
#pragma unroll
    for (int j = 0; j < 16; ++j) {
        ((float4*)g_Mis)[lane*16 + j]      = make_float4(A[4*j],A[4*j+1],A[4*j+2],A[4*j+3]);
        ((float4*)g_Mis)[(lane+32)*16 + j] = make_float4(B[4*j],B[4*j+1],B[4*j+2],B[4*j+3]);
    }
}

// M <- sym(Ms expm(L) Ms).  eig(L + sigma I) warm from g_VL.
__global__ void __launch_bounds__(32) update_M_kernel(int warm) {
    __shared__ float t0[TILE], t1[TILE];
    __shared__ float sG[64], sI[64];
    __shared__ float s_sigma;
    const int lane = threadIdx.x;
    const unsigned FULL = 0xffffffffu;
    float A[64], B[64];
    u64 A2[32], B2[32];

    float fro2 = 0.0f;
    for (int idx = lane; idx < N*N; idx += 32) {
        float v = g_L[idx];
        t0[(idx>>6)*LD + (idx&63)] = v;
        fro2 = fmaf(v, v, fro2);
    }
#pragma unroll
    for (int o = 16; o > 0; o >>= 1) fro2 += __shfl_down_sync(FULL, fro2, o);
    if (lane == 0) s_sigma = 1.05f * sqrtf(fro2) + 1e-12f;
    __syncwarp();
    const float sigma = s_sigma;

    if (warm) {
        for (int idx = lane; idx < N*N; idx += 32)
            t1[(idx>>6)*LD + (idx&63)] = g_VL[idx];
        __syncwarp();
        wgemm_cols(A, B, t0, t1, lane);                      // L*Vp
#pragma unroll
        for (int j = 0; j < 64; ++j) {                       // + sigma*Vp
            A[j] = fmaf(sigma, t1[j*LD + lane],      A[j]);
            B[j] = fmaf(sigma, t1[j*LD + lane + 32], B[j]);
        }
        __syncwarp();
#pragma unroll
        for (int j = 0; j < 64; ++j) { t1[j*LD + lane] = A[j]; t1[j*LD + lane + 32] = B[j]; }
        __syncwarp();
        pack_cols(A2, B2, t1, lane);
    } else {
#pragma unroll
        for (int i = 0; i < 32; ++i) {
            float a0 = t0[(2*i)*LD + 2*lane]     + ((i == lane) ? sigma : 0.0f);
            float a1 = t0[(2*i+1)*LD + 2*lane];
            float b0 = t0[(2*i)*LD + 2*lane + 1];
            float b1 = t0[(2*i+1)*LD + 2*lane+1] + ((i == lane) ? sigma : 0.0f);
            A2[i] = pk2(a0, a1);
            B2[i] = pk2(b0, b1);
        }
    }

    hestenes_p(A2, B2, lane, 24);

    float n1, n2;
    norms_p(A2, B2, n1, n2);
    __syncwarp();
    unpack_rows(A2, B2, t0, lane);                            // t0 = W^T
    sI[2*lane]   = rsqrtf(n1);
    sI[2*lane+1] = rsqrtf(n2);
    sG[2*lane]   = expf(sqrtf(n1) - sigma) / n1;              // e^{lambda}/lambda'^2
    sG[2*lane+1] = expf(sqrtf(n2) - sigma) / n2;
    __syncwarp();
    for (int k = 0; k < 64; ++k) {                            // V -> g_VL
        g_VL[k*64 + lane]      = t0[lane*LD + k]      * sI[lane];
        g_VL[k*64 + lane + 32] = t0[(lane+32)*LD + k] * sI[lane+32];
    }
    wouter_cols(A, B, t0, sG, lane);                          // E = expm(L)
    __syncwarp();
#pragma unroll
    for (int j = 0; j < 64; ++j) { t0[j*LD + lane] = A[j]; t0[j*LD + lane + 32] = B[j]; }  // t0 = E
    for (int idx = lane; idx < N*N; idx += 32)
        t1[(idx>>6)*LD + (idx&63)] = g_Ms[idx];               // t1 = Ms
    __syncwarp();
    wgemm_cols(A, B, t1, t0, lane);                           // T = Ms*E
    __syncwarp();
#pragma unroll
    for (int j = 0; j < 64; ++j) { t0[j*LD + lane] = A[j]; t0[j*LD + lane + 32] = B[j]; }  // t0 = T
    __syncwarp();
    wgemm_cols(A, B, t0, t1, lane);                           // Mn = T*Ms
    __syncwarp();
#pragma unroll
    for (int j = 0; j < 64; ++j) { t0[j*LD + lane] = A[j]; t0[j*LD + lane + 32] = B[j]; }  // t0 = Mn
    __syncwarp();
    for (int idx = lane; idx < N*N; idx += 32) {
        int i = idx >> 6, j = idx & 63;
        g_M[idx] = 0.5f * (t0[i*LD + j] + t0[j*LD + i]);
    }
}

// C = expm(0.25 (bias + bias^T)) * invsqrtm(M)
__global__ void __launch_bounds__(32) final_prep_kernel(const float* __restrict__ bias) {
    __shared__ float t0[TILE], t1[TILE];
    __shared__ float sG[64];
    __shared__ float s_sigma;
    const int lane = threadIdx.x;
    const unsigned FULL = 0xffffffffu;
    float A[64], B[64];
    u64 A2[32], B2[32];

    // ---- eig(M), warm from g_VM -> Mis into t0 ----
    for (int idx = lane; idx < N*N; idx += 32)
        t0[(idx>>6)*LD + (idx&63)] = g_M[idx];
    for (int idx = lane; idx < N*N; idx += 32)
        t1[(idx>>6)*LD + (idx&63)] = g_VM[idx];
    __syncwarp();
    wgemm_cols(A, B, t0, t1, lane);
    __syncwarp();
#pragma unroll
    for (int j = 0; j < 64; ++j) { t1[j*LD + lane] = A[j]; t1[j*LD + lane + 32] = B[j]; }
    __syncwarp();
    pack_cols(A2, B2, t1, lane);
    hestenes_p(A2, B2, lane, 24);
    float n1, n2;
    norms_p(A2, B2, n1, n2);
    __syncwarp();
    unpack_rows(A2, B2, t1, lane);
    sG[2*lane]   = expf(-1.25f * logf(n1));
    sG[2*lane+1] = expf(-1.25f * logf(n2));
    __syncwarp();
    wouter_cols(A, B, t1, sG, lane);                          // Mis
    __syncwarp();
#pragma unroll
    for (int j = 0; j < 64; ++j) { t0[j*LD + lane] = A[j]; t0[j*LD + lane + 32] = B[j]; }  // t0 = Mis
    __syncwarp();

    // ---- eig(0.25(b+b^T) + sigma I) -> Bs ----
    float fro2 = 0.0f;
    for (int idx = lane; idx < N*N; idx += 32) {
        int i = idx >> 6, j = idx & 63;
        float v = 0.25f * (bias[i*64 + j] + bias[j*64 + i]);
        t1[i*LD + j] = v;
        fro2 = fmaf(v, v, fro2);
    }
#pragma unroll
    for (int o = 16; o > 0; o >>= 1) fro2 += __shfl_down_sync(FULL, fro2, o);
    if (lane == 0) s_sigma = 1.05f * sqrtf(fro2) + 1e-12f;
    __syncwarp();
    const float sb = s_sigma;
#pragma unroll
    for (int i = 0; i < 32; ++i) {
        float a0 = t1[(2*i)*LD + 2*lane]     + ((i == lane) ? sb : 0.0f);
        float a1 = t1[(2*i+1)*LD + 2*lane];
        float b0 = t1[(2*i)*LD + 2*lane + 1];
        float b1 = t1[(2*i+1)*LD + 2*lane+1] + ((i == lane) ? sb : 0.0f);
        A2[i] = pk2(a0, a1);
        B2[i] = pk2(b0, b1);
    }
    hestenes_p(A2, B2, lane, 24);
    norms_p(A2, B2, n1, n2);
    __syncwarp();
    unpack_rows(A2, B2, t1, lane);
    sG[2*lane]   = expf(sqrtf(n1) - sb) / n1;
    sG[2*lane+1] = expf(sqrtf(n2) - sb) / n2;
    __syncwarp();
    wouter_cols(A, B, t1, sG, lane);                          // Bs
    __syncwarp();
#pragma unroll
    for (int j = 0; j < 64; ++j) { t1[j*LD + lane] = A[j]; t1[j*LD + lane + 32] = B[j]; }  // t1 = Bs
    __syncwarp();
    wgemm_cols(A, B, t1, t0, lane);                           // C = Bs * Mis
    for (int i = 0; i < 64; ++i) {
        g_C[i*64 + lane]      = A[i];
        g_C[i*64 + lane + 32] = B[i];
    }
}

// ----------------------------------------------------------------------------
// Batch logm: one warp per matrix, 8 per block, packed odd-even Hestenes.
// ----------------------------------------------------------------------------
__global__ void __launch_bounds__(256) batch_log8_kernel(const float* __restrict__ data,
                                                         int warm, int store_v, int Bsz) {
    extern __shared__ float sm[];
    float* mis = sm;                          // 64 x LD, shared by all warps
    const int tid  = threadIdx.x;
    const int wid  = tid >> 5;
    const int lane = tid & 31;
    float* tile = sm + TILE * (1 + wid);
    float* sG = sm + 9*TILE + wid*64;
    float* sI = sm + 9*TILE + 512 + wid*64;

    for (int idx = tid; idx < N*N; idx += 256)
        mis[(idx >> 6)*LD + (idx & 63)] = g_Mis[idx];
    __syncthreads();

    const int b = blockIdx.x * 8 + wid;
    if (b >= Bsz) return;

    const float* X = data + (size_t)b * (N*N);
    for (int idx = lane; idx < 1024; idx += 32) {
        float4 v = ((const float4*)X)[idx];
        int r = idx >> 4, c = (idx & 15) << 2;
        tile[r*LD + c + 0] = v.x;
        tile[r*LD + c + 1] = v.y;
        tile[r*LD + c + 2] = v.z;
        tile[r*LD + c + 3] = v.w;
    }
    __syncwarp();

    const int c1 = lane, c2 = lane + 32;
    float A[64], B[64];

    // GEMM1: Z = X * Mis
#pragma unroll
    for (int j = 0; j < 64; ++j) { A[j] = 0.0f; B[j] = 0.0f; }
    for (int k = 0; k < 64; ++k) {
        float m1 = mis[k*LD + c1];
        float m2 = mis[k*LD + c2];
#pragma unroll
        for (int i = 0; i < 64; ++i) {
            float x = tile[i*LD + k];
            A[i] = fmaf(x, m1, A[i]);
            B[i] = fmaf(x, m2, B[i]);
        }
    }
    __syncwarp();
#pragma unroll
    for (int k = 0; k < 64; ++k) { tile[k*LD + c1] = A[k]; tile[k*LD + c2] = B[k]; }
    __syncwarp();

    // GEMM2: Y = Mis * Z
#pragma unroll
    for (int j = 0; j < 64; ++j) { A[j] = 0.0f; B[j] = 0.0f; }
    for (int k = 0; k < 64; ++k) {
        float z1 = tile[k*LD + c1];
        float z2 = tile[k*LD + c2];
#pragma unroll
        for (int i = 0; i < 64; ++i) {
            float m = mis[i*LD + k];
            A[i] = fmaf(m, z1, A[i]);
            B[i] = fmaf(m, z2, B[i]);
        }
    }

    if (warm) {
        __syncwarp();
#pragma unroll
        for (int i = 0; i < 64; ++i) { tile[i*LD + c1] = A[i]; tile[i*LD + c2] = B[i]; }  // Y
        __syncwarp();
        const float* Vp = g_Vw + (size_t)b * (N*N);
#pragma unroll
        for (int j = 0; j < 64; ++j) { A[j] = 0.0f; B[j] = 0.0f; }
        for (int k = 0; k < 64; ++k) {
            float v1 = Vp[k*64 + c1];
            float v2 = Vp[k*64 + c2];
#pragma unroll
            for (int i = 0; i < 64; ++i) {
                float y = tile[i*LD + k];
                A[i] = fmaf(y, v1, A[i]);
                B[i] = fmaf(y, v2, B[i]);
            }
        }
    }

    // relabel columns (c1,c2) -> packed positions (2*lane, 2*lane+1)
    __syncwarp();
#pragma unroll
    for (int j = 0; j < 64; ++j) { tile[j*LD + c1] = A[j]; tile[j*LD + c2] = B[j]; }
    __syncwarp();
    u64 A2[32], B2[32];
    pack_cols(A2, B2, tile, lane);

    hestenes_p(A2, B2, lane, 16);

    float n1, n2;
    norms_p(A2, B2, n1, n2);
    __syncwarp();
    unpack_rows(A2, B2, tile, lane);                          // tile = W^T
    sG[2*lane]   = 0.5f * logf(n1) / n1;     // log(lambda)/lambda^2
    sG[2*lane+1] = 0.5f * logf(n2) / n2;
    sI[2*lane]   = rsqrtf(n1);
    sI[2*lane+1] = rsqrtf(n2);
    __syncwarp();

    // O = W diag(g) W^T
    wouter_cols(A, B, tile, sG, lane);
    float* Ob = g_scratch + (size_t)b * (N*N);
#pragma unroll
    for (int j = 0; j < 16; ++j) {
        ((float4*)Ob)[c1*16 + j] = make_float4(A[4*j], A[4*j+1], A[4*j+2], A[4*j+3]);
        ((float4*)Ob)[c2*16 + j] = make_float4(B[4*j], B[4*j+1], B[4*j+2], B[4*j+3]);
    }

    if (store_v) {
        float* Vd = g_Vw + (size_t)b * (N*N);
#pragma unroll
        for (int k = 0; k < 64; ++k) {
            Vd[k*64 + c1] = tile[c1*LD + k] * sI[c1];
            Vd[k*64 + c2] = tile[c2*LD + k] * sI[c2];
        }
    }
}

// out_b = C X_b C^T
__global__ void __launch_bounds__(NT) apply_kernel(const float* __restrict__ data,
                                                   float* __restrict__ out) {
    extern __shared__ float sm[];
    float *b0 = sm, *b1 = sm + TILE, *b2 = sm + 2*TILE, *b3 = sm + 3*TILE;
    const size_t b = blockIdx.x;
    g2s(b1, g_C);
    g2s(b0, data + b * (N*N));
    gemm_nn(b2, b1, b0);
    gemm_nt(b3, b2, b1);
    s2g(out + b * (N*N), b3);
}

// ----------------------------------------------------------------------------
// Host launcher (graph-capturable)
// ----------------------------------------------------------------------------
extern "C" void kernel_launch(void* const* d_in, const int* in_sizes, int n_in,
                              void* d_out, int out_size) {
    const float* data = (const float*)d_in[0];
    const float* bias = (const float*)d_in[1];
    int sz0 = in_sizes[0], sz1 = (n_in > 1) ? in_sizes[1] : 0;
    if (sz0 == N*N && sz1 > N*N) {
        data = (const float*)d_in[1];
        bias = (const float*)d_in[0];
        int t = sz0; sz0 = sz1; sz1 = t;
    }
    int Bsz = sz0 / (N*N);
    if (Bsz > MAXB) Bsz = MAXB;
    float* out = (float*)d_out;

    const size_t shmem4 = 4 * TILE * sizeof(float);             // apply
    const size_t shmem8 = (9 * TILE + 1024) * sizeof(float);    // batch
    cudaFuncSetAttribute(batch_log8_kernel, cudaFuncAttributeMaxDynamicSharedMemorySize, (int)shmem8);
    cudaFuncSetAttribute(apply_kernel,      cudaFuncAttributeMaxDynamicSharedMemorySize, (int)shmem4);

    float *pM, *pL, *pScr, *pPart;
    cudaGetSymbolAddress((void**)&pM,    g_M);
    cudaGetSymbolAddress((void**)&pL,    g_L);
    cudaGetSymbolAddress((void**)&pScr,  g_scratch);
    cudaGetSymbolAddress((void**)&pPart, g_partial);

    const int nb1 = (Bsz + 31) / 32;
    const int nb8 = (Bsz + 7) / 8;
    const float inv = 1.0f / (float)Bsz;

    reduce32_kernel    <<<nb1, NT>>>(data, pPart, Bsz);
    reduceFinal_kernel <<<16,  NT>>>(pPart, pM, nb1, inv);

    for (int it = 0; it < 5; ++it) {
        prep_M_kernel     <<<1,   32>>>(it > 0 ? 1 : 0);
        batch_log8_kernel <<<nb8, 256, shmem8>>>(data, it > 0 ? 1 : 0, it < 4 ? 1 : 0, Bsz);
        reduce32_kernel    <<<nb1, NT>>>(pScr, pPart, Bsz);
        reduceFinal_kernel <<<16,  NT>>>(pPart, pL, nb1, inv);
        update_M_kernel   <<<1,   32>>>(it > 0 ? 1 : 0);
    }

    final_prep_kernel <<<1,   32>>>(bias);
    apply_kernel      <<<Bsz, NT, shmem4>>>(data, out);
}

// round 10
// speedup vs baseline: 2.9466x; 1.0246x over previous
#include <cuda_runtime.h>
#include <math.h>

#define N    64
#define LD   65            // padded leading dim in shared
#define NT   256
#define TILE (N*LD)
#define MAXB 8192

typedef unsigned long long u64;

// ----------------------------------------------------------------------------
// f32x2 packed helpers (sm_103a packed FP32 pipe; only reachable via PTX)
// ----------------------------------------------------------------------------
__device__ __forceinline__ u64 pk2(float lo, float hi) {
    u64 r; asm("mov.b64 %0,{%1,%2};" : "=l"(r) : "f"(lo), "f"(hi)); return r;
}
__device__ __forceinline__ void up2(u64 v, float& lo, float& hi) {
    asm("mov.b64 {%0,%1},%2;" : "=f"(lo), "=f"(hi) : "l"(v));
}
__device__ __forceinline__ u64 fma2(u64 a, u64 b, u64 c) {
    u64 r; asm("fma.rn.f32x2 %0,%1,%2,%3;" : "=l"(r) : "l"(a), "l"(b), "l"(c)); return r;
}
__device__ __forceinline__ u64 mul2(u64 a, u64 b) {
    u64 r; asm("mul.rn.f32x2 %0,%1,%2;" : "=l"(r) : "l"(a), "l"(b)); return r;
}
__device__ __forceinline__ u64 add2(u64 a, u64 b) {
    u64 r; asm("add.rn.f32x2 %0,%1,%2;" : "=l"(r) : "l"(a), "l"(b)); return r;
}

// ----------------------------------------------------------------------------
// Global scratch
// ----------------------------------------------------------------------------
__device__ float g_M  [N*N];
__device__ float g_Ms [N*N];
__device__ float g_Mis[N*N];
__device__ float g_L  [N*N];
__device__ float g_C  [N*N];
__device__ float g_VM [N*N];                   // warm-start eigvecs of M (row-major [k][c])
__device__ float g_VL [N*N];                   // warm-start eigvecs of L+sI
__device__ float g_scratch[(size_t)MAXB*N*N];  // per-matrix logm
__device__ float g_Vw     [(size_t)MAXB*N*N];  // per-matrix eigvecs, row-major [k][c]
__device__ float g_partial[(MAXB/32)*N*N];

// ----------------------------------------------------------------------------
// Packed one-sided (Hestenes) Jacobi, odd-even ordering. Lane l holds columns
// at positions 2l (A) and 2l+1 (B); each column = 32 packed f32x2 values.
// Even rounds pair (A,B) in-lane and swap; odd rounds pair (B_l, A_{l+1}) via
// shfl and swap across the boundary. 64 rounds/sweep covers all C(64,2) pairs.
// Dot products use 4 independent fma2 chains (latency-bound at 8 warps/SM).
// ----------------------------------------------------------------------------
__device__ __forceinline__ void hestenes_p(u64 (&A)[32], u64 (&B)[32],
                                           int lane, int max_sweeps, float thr) {
    const unsigned FULL = 0xffffffffu;
    for (int sweep = 0; sweep < max_sweeps; ++sweep) {
        float nA, nB;
        {
            u64 a0=0ull,a1=0ull,a2=0ull,a3=0ull, b0=0ull,b1=0ull,b2=0ull,b3=0ull;
#pragma unroll
            for (int i = 0; i < 32; i += 4) {
                a0 = fma2(A[i],   A[i],   a0);
                a1 = fma2(A[i+1], A[i+1], a1);
                a2 = fma2(A[i+2], A[i+2], a2);
                a3 = fma2(A[i+3], A[i+3], a3);
                b0 = fma2(B[i],   B[i],   b0);
                b1 = fma2(B[i+1], B[i+1], b1);
                b2 = fma2(B[i+2], B[i+2], b2);
                b3 = fma2(B[i+3], B[i+3], b3);
            }
            u64 sa = add2(add2(a0,a1), add2(a2,a3));
            u64 sb = add2(add2(b0,b1), add2(b2,b3));
            float x0,x1,y0,y1; up2(sa,x0,x1); up2(sb,y0,y1);
            nA = x0+x1; nB = y0+y1;
        }
        int rotated = 0;
        for (int rr = 0; rr < 32; ++rr) {
            // ---- even round: pair (A,B) within lane ----
            {
                u64 c0=0ull,c1_=0ull,c2_=0ull,c3=0ull;
#pragma unroll
                for (int i = 0; i < 32; i += 4) {
                    c0  = fma2(A[i],   B[i],   c0);
                    c1_ = fma2(A[i+1], B[i+1], c1_);
                    c2_ = fma2(A[i+2], B[i+2], c2_);
                    c3  = fma2(A[i+3], B[i+3], c3);
                }
                u64 sc = add2(add2(c0,c1_), add2(c2_,c3));
                float d0,d1; up2(sc,d0,d1);
                float d = d0+d1;
                bool rot = d*d > thr*nA*nB;
                if (__any_sync(FULL, rot)) {
                    rotated = 1;
                    float c = 1.0f, s = 0.0f;
                    if (rot) {
                        float ta = (nB-nA)/(2.0f*d);
                        float t  = copysignf(1.0f,ta)/(fabsf(ta)+sqrtf(fmaf(ta,ta,1.0f)));
                        c = rsqrtf(fmaf(t,t,1.0f)); s = t*c;
                    }
                    u64 cp = pk2(c,c), sp = pk2(s,s), np = pk2(-s,-s);
#pragma unroll
                    for (int i = 0; i < 32; ++i) {
                        u64 x = A[i], y = B[i];
                        A[i] = fma2(sp, x, mul2(cp, y));   // v -> pos 2l (swap)
                        B[i] = fma2(cp, x, mul2(np, y));   // u -> pos 2l+1
                    }
                    float cc=c*c, ss=s*s, cs2=2.0f*c*s;
                    float nu = cc*nA - cs2*d + ss*nB;
                    float nv = ss*nA + cs2*d + cc*nB;
                    nA = nv; nB = nu;
                } else {
#pragma unroll
                    for (int i = 0; i < 32; ++i) { u64 t=A[i]; A[i]=B[i]; B[i]=t; }
                    float t = nA; nA = nB; nB = t;
                }
            }
            // ---- odd round: pair (B_l, A_{l+1}); positions 0 and 63 idle ----
            {
                float ny = __shfl_down_sync(FULL, nA, 1);
                u64 c0=0ull,c1_=0ull,c2_=0ull,c3=0ull;
#pragma unroll
                for (int i = 0; i < 32; i += 4) {
                    u64 y0 = __shfl_down_sync(FULL, A[i],   1);
                    u64 y1 = __shfl_down_sync(FULL, A[i+1], 1);
                    u64 y2 = __shfl_down_sync(FULL, A[i+2], 1);
                    u64 y3 = __shfl_down_sync(FULL, A[i+3], 1);
                    c0  = fma2(B[i],   y0, c0);
                    c1_ = fma2(B[i+1], y1, c1_);
                    c2_ = fma2(B[i+2], y2, c2_);
                    c3  = fma2(B[i+3], y3, c3);
                }
                u64 sc = add2(add2(c0,c1_), add2(c2_,c3));
                float d0,d1; up2(sc,d0,d1);
                float d = d0+d1;
                bool rot = (lane < 31) && (d*d > thr*nB*ny);
                if (__any_sync(FULL, rot)) {
                    rotated = 1;
                    float c = 1.0f, s = 0.0f;
                    if (rot) {
                        float ta = (ny-nB)/(2.0f*d);
                        float t  = copysignf(1.0f,ta)/(fabsf(ta)+sqrtf(fmaf(ta,ta,1.0f)));
                        c = rsqrtf(fmaf(t,t,1.0f)); s = t*c;
                    }
                    u64 cp = pk2(c,c), sp = pk2(s,s), np = pk2(-s,-s);
#pragma unroll
                    for (int i = 0; i < 32; ++i) {
                        u64 x = B[i];
                        u64 y = __shfl_down_sync(FULL, A[i], 1);
                        u64 u = fma2(cp, x, mul2(np, y));
                        u64 v = fma2(sp, x, mul2(cp, y));
                        u64 us = __shfl_up_sync(FULL, u, 1);
                        B[i] = (lane==31) ? B[i] : v;
                        A[i] = (lane==0)  ? A[i] : us;
                    }
                    float cc=c*c, ss=s*s, cs2=2.0f*c*s;
                    float nu = cc*nB - cs2*d + ss*ny;
                    float nv = ss*nB + cs2*d + cc*ny;
                    float nus = __shfl_up_sync(FULL, nu, 1);
                    nB = (lane==31) ? nB : nv;
                    nA = (lane==0)  ? nA : nus;
                } else {
                    // quiet fast-path: pure positional swap across lane boundary
#pragma unroll
                    for (int i = 0; i < 32; ++i) {
                        u64 y  = __shfl_down_sync(FULL, A[i], 1);
                        u64 xs = __shfl_up_sync(FULL, B[i], 1);
                        B[i] = (lane==31) ? B[i] : y;
                        A[i] = (lane==0)  ? A[i] : xs;
                    }
                    float nus = __shfl_up_sync(FULL, nB, 1);
                    nB = (lane==31) ? nB : ny;
                    nA = (lane==0)  ? nA : nus;
                }
            }
        }
        if (!rotated) break;
    }
}

// pack columns (2*lane, 2*lane+1) of an LD-padded shared matrix into registers
__device__ __forceinline__ void pack_cols(u64 (&A)[32], u64 (&B)[32],
                                          const float* S, int lane) {
#pragma unroll
    for (int i = 0; i < 32; ++i) {
        A[i] = pk2(S[(2*i)*LD + 2*lane],     S[(2*i+1)*LD + 2*lane]);
        B[i] = pk2(S[(2*i)*LD + 2*lane + 1], S[(2*i+1)*LD + 2*lane + 1]);
    }
}
// packed squared norms of the two held columns (4-way chains)
__device__ __forceinline__ void norms_p(const u64 (&A)[32], const u64 (&B)[32],
                                        float& n1, float& n2) {
    u64 a0=0ull,a1=0ull,a2=0ull,a3=0ull, b0=0ull,b1=0ull,b2=0ull,b3=0ull;
#pragma unroll
    for (int i = 0; i < 32; i += 4) {
        a0 = fma2(A[i],   A[i],   a0);
        a1 = fma2(A[i+1], A[i+1], a1);
        a2 = fma2(A[i+2], A[i+2], a2);
        a3 = fma2(A[i+3], A[i+3], a3);
        b0 = fma2(B[i],   B[i],   b0);
        b1 = fma2(B[i+1], B[i+1], b1);
        b2 = fma2(B[i+2], B[i+2], b2);
        b3 = fma2(B[i+3], B[i+3], b3);
    }
    u64 sa = add2(add2(a0,a1), add2(a2,a3));
    u64 sb = add2(add2(b0,b1), add2(b2,b3));
    float x0,x1,y0,y1; up2(sa,x0,x1); up2(sb,y0,y1);
    n1 = fmaxf(x0+x1, 1e-30f);
    n2 = fmaxf(y0+y1, 1e-30f);
}
// write held columns as ROWS 2*lane, 2*lane+1 of an LD-padded shared matrix (W^T)
__device__ __forceinline__ void unpack_rows(const u64 (&A)[32], const u64 (&B)[32],
                                            float* S, int lane) {
#pragma unroll
    for (int i = 0; i < 32; ++i) {
        float x0,x1,y0,y1;
        up2(A[i],x0,x1); up2(B[i],y0,y1);
        S[(2*lane)*LD   + 2*i]     = x0;
        S[(2*lane)*LD   + 2*i + 1] = x1;
        S[(2*lane+1)*LD + 2*i]     = y0;
        S[(2*lane+1)*LD + 2*i + 1] = y1;
    }
}

// ----------------------------------------------------------------------------
// Warp GEMM helpers (1 warp computes two output columns: c=lane, c=lane+32)
// ----------------------------------------------------------------------------
__device__ __forceinline__ void wgemm_cols(float (&o1)[64], float (&o2)[64],
                                           const float* Ash, const float* Bsh, int lane) {
#pragma unroll
    for (int j = 0; j < 64; ++j) { o1[j] = 0.0f; o2[j] = 0.0f; }
    for (int k = 0; k < 64; ++k) {
        float b1 = Bsh[k*LD + lane];
        float b2 = Bsh[k*LD + lane + 32];
#pragma unroll
        for (int i = 0; i < 64; ++i) {
            float a = Ash[i*LD + k];
            o1[i] = fmaf(a, b1, o1[i]);
            o2[i] = fmaf(a, b2, o2[i]);
        }
    }
}
// o[:,c] = sum_k g[k] * W[:,k] * W[c,k], with Wt[k][j] = W[j][k] in shared
__device__ __forceinline__ void wouter_cols(float (&o1)[64], float (&o2)[64],
                                            const float* Wt, const float* g, int lane) {
#pragma unroll
    for (int j = 0; j < 64; ++j) { o1[j] = 0.0f; o2[j] = 0.0f; }
    for (int k = 0; k < 64; ++k) {
        float gk = g[k];
        float a1 = gk * Wt[k*LD + lane];
        float a2 = gk * Wt[k*LD + lane + 32];
#pragma unroll
        for (int i = 0; i < 64; ++i) {
            float s = Wt[k*LD + i];
            o1[i] = fmaf(s, a1, o1[i]);
            o2[i] = fmaf(s, a2, o2[i]);
        }
    }
}

// ----------------------------------------------------------------------------
// Block helpers for apply_kernel
// ----------------------------------------------------------------------------
__device__ __forceinline__ void g2s(float* S, const float* __restrict__ G) {
    for (int idx = threadIdx.x; idx < N*N; idx += NT)
        S[(idx >> 6) * LD + (idx & 63)] = G[idx];
    __syncthreads();
}
__device__ __forceinline__ void s2g(float* __restrict__ G, const float* S) {
    for (int idx = threadIdx.x; idx < N*N; idx += NT)
        G[idx] = S[(idx >> 6) * LD + (idx & 63)];
    __syncthreads();
}
__device__ __forceinline__ void gemm_nn(float* D, const float* A, const float* B) {
    const int tx = (threadIdx.x & 15) << 2;
    const int ty = (threadIdx.x >> 4) << 2;
    float acc[4][4] = {};
#pragma unroll 8
    for (int k = 0; k < N; ++k) {
        float a0 = A[(ty+0)*LD + k], a1 = A[(ty+1)*LD + k];
        float a2 = A[(ty+2)*LD + k], a3 = A[(ty+3)*LD + k];
        float b0 = B[k*LD + tx+0], b1 = B[k*LD + tx+1];
        float b2 = B[k*LD + tx+2], b3 = B[k*LD + tx+3];
        acc[0][0]+=a0*b0; acc[0][1]+=a0*b1; acc[0][2]+=a0*b2; acc[0][3]+=a0*b3;
        acc[1][0]+=a1*b0; acc[1][1]+=a1*b1; acc[1][2]+=a1*b2; acc[1][3]+=a1*b3;
        acc[2][0]+=a2*b0; acc[2][1]+=a2*b1; acc[2][2]+=a2*b2; acc[2][3]+=a2*b3;
        acc[3][0]+=a3*b0; acc[3][1]+=a3*b1; acc[3][2]+=a3*b2; acc[3][3]+=a3*b3;
    }
#pragma unroll
    for (int r = 0; r < 4; ++r)
#pragma unroll
        for (int c = 0; c < 4; ++c)
            D[(ty+r)*LD + tx + c] = acc[r][c];
    __syncthreads();
}
__device__ __forceinline__ void gemm_nt(float* D, const float* A, const float* B) {
    const int tx = (threadIdx.x & 15) << 2;
    const int ty = (threadIdx.x >> 4) << 2;
    float acc[4][4] = {};
#pragma unroll 8
    for (int k = 0; k < N; ++k) {
        float a0 = A[(ty+0)*LD + k], a1 = A[(ty+1)*LD + k];
        float a2 = A[(ty+2)*LD + k], a3 = A[(ty+3)*LD + k];
        float b0 = B[(tx+0)*LD + k], b1 = B[(tx+1)*LD + k];
        float b2 = B[(tx+2)*LD + k], b3 = B[(tx+3)*LD + k];
        acc[0][0]+=a0*b0; acc[0][1]+=a0*b1; acc[0][2]+=a0*b2; acc[0][3]+=a0*b3;
        acc[1][0]+=a1*b0; acc[1][1]+=a1*b1; acc[1][2]+=a1*b2; acc[1][3]+=a1*b3;
        acc[2][0]+=a2*b0; acc[2][1]+=a2*b1; acc[2][2]+=a2*b2; acc[2][3]+=a2*b3;
        acc[3][0]+=a3*b0; acc[3][1]+=a3*b1; acc[3][2]+=a3*b2; acc[3][3]+=a3*b3;
    }
#pragma unroll
    for (int r = 0; r < 4; ++r)
#pragma unroll
        for (int c = 0; c < 4; ++c)
            D[(ty+r)*LD + tx + c] = acc[r][c];
    __syncthreads();
}

// ----------------------------------------------------------------------------
// Reductions
// ----------------------------------------------------------------------------
__global__ void __launch_bounds__(NT) reduce32_kernel(const float* __restrict__ src,
                                                      float* __restrict__ dst, int Bsz) {
    int j = blockIdx.x;
    int b0 = j * 32;
    int cnt = min(32, Bsz - b0);
    for (int i = threadIdx.x; i < N*N; i += NT) {
        float a = 0.0f;
        for (int k = 0; k < cnt; ++k)
            a += src[(size_t)(b0 + k) * (N*N) + i];
        dst[(size_t)j * (N*N) + i] = a;
    }
}
__global__ void __launch_bounds__(NT) reduceFinal_kernel(const float* __restrict__ part,
                                                         float* __restrict__ dst,
                                                         int nb, float scale) {
    int i = blockIdx.x * NT + threadIdx.x;
    float a = 0.0f;
    for (int j = 0; j < nb; ++j)
        a += part[(size_t)j * (N*N) + i];
    dst[i] = a * scale;
}

// ----------------------------------------------------------------------------
// Single-matrix warp kernels (1 warp = 32 threads)
// ----------------------------------------------------------------------------

// eig(M) -> g_Ms = M^{1/2}, g_Mis = M^{-1/2}, V -> g_VM.  Warm from g_VM.
__global__ void __launch_bounds__(32) prep_M_kernel(int warm) {
    __shared__ float t0[TILE], t1[TILE];
    __shared__ float sG[64], sI[64];
    const int lane = threadIdx.x;
    float A[64], B[64];
    u64 A2[32], B2[32];

    for (int idx = lane; idx < N*N; idx += 32)
        t0[(idx>>6)*LD + (idx&63)] = g_M[idx];
    __syncwarp();

    if (warm) {
        for (int idx = lane; idx < N*N; idx += 32)
            t1[(idx>>6)*LD + (idx&63)] = g_VM[idx];          // [k][c]
        __syncwarp();
        wgemm_cols(A, B, t0, t1, lane);                      // W0 = M * Vp
        __syncwarp();
#pragma unroll
        for (int j = 0; j < 64; ++j) { t1[j*LD + lane] = A[j]; t1[j*LD + lane + 32] = B[j]; }
        __syncwarp();
        pack_cols(A2, B2, t1, lane);
    } else {
        pack_cols(A2, B2, t0, lane);
    }

    hestenes_p(A2, B2, lane, 24, 1e-10f);

    float n1, n2;
    norms_p(A2, B2, n1, n2);
    __syncwarp();
    unpack_rows(A2, B2, t1, lane);                            // t1 = W^T
    sI[2*lane]   = rsqrtf(n1);
    sI[2*lane+1] = rsqrtf(n2);
    // Ms: g = lambda^{-3/2} = n^{-3/4}
    sG[2*lane]   = expf(-0.75f * logf(n1));
    sG[2*lane+1] = expf(-0.75f * logf(n2));
    __syncwarp();

    // V -> g_VM (row-major [k][c]): V[:,c] = W[:,c]/lambda_c
    for (int k = 0; k < 64; ++k) {
        g_VM[k*64 + lane]      = t1[lane*LD + k]      * sI[lane];
        g_VM[k*64 + lane + 32] = t1[(lane+32)*LD + k] * sI[lane+32];
    }
    wouter_cols(A, B, t1, sG, lane);                          // Ms (symmetric)
#pragma unroll
    for (int j = 0; j < 16; ++j) {
        ((float4*)g_Ms)[lane*16 + j]      = make_float4(A[4*j],A[4*j+1],A[4*j+2],A[4*j+3]);
        ((float4*)g_Ms)[(lane+32)*16 + j] = make_float4(B[4*j],B[4*j+1],B[4*j+2],B[4*j+3]);
    }
    // Mis: g = n^{-5/4}
    sG[2*lane]   = expf(-1.25f * logf(n1));
    sG[2*lane+1] = expf(-1.25f * logf(n2));
    __syncwarp();
    wouter_cols(A, B, t1, sG, lane);
#pragma unroll
    for (int j = 0; j < 16; ++j) {
        ((float4*)g_Mis)[lane*16 + j]      = make_float4(A[4*j],A[4*j+1],A[4*j+2],A[4*j+3]);
        ((float4*)g_Mis)[(lane+32)*16 + j] = make_float4(B[4*j],B[4*j+1],B[4*j+2],B[4*j+3]);
    }
}

// M <- sym(Ms expm(L) Ms).  eig(L + sigma I) warm from g_VL.
__global__ void __launch_bounds__(32) update_M_kernel(int warm) {
    __shared__ float t0[TILE], t1[TILE];
    __shared__ float sG[64], sI[64];
    __shared__ float s_sigma;
    const int lane = threadIdx.x;
    const unsigned FULL = 0xffffffffu;
    float A[64], B[64];
    u64 A2[32], B2[32];

    float fro2 = 0.0f;
    for (int idx = lane; idx < N*N; idx += 32) {
        float v = g_L[idx];
        t0[(idx>>6)*LD + (idx&63)] = v;
        fro2 = fmaf(v, v, fro2);
    }
#pragma unroll
    for (int o = 16; o > 0; o >>= 1) fro2 += __shfl_down_sync(FULL, fro2, o);
    if (lane == 0) s_sigma = 1.05f * sqrtf(fro2) + 1e-12f;
    __syncwarp();
    const float sigma = s_sigma;

    if (warm) {
        for (int idx = lane; idx < N*N; idx += 32)
            t1[(idx>>6)*LD + (idx&63)] = g_VL[idx];
        __syncwarp();
        wgemm_cols(A, B, t0, t1, lane);                      // L*Vp
#pragma unroll
        for (int j = 0; j < 64; ++j) {                       // + sigma*Vp
            A[j] = fmaf(sigma, t1[j*LD + lane],      A[j]);
            B[j] = fmaf(sigma, t1[j*LD + lane + 32], B[j]);
        }
        __syncwarp();
#pragma unroll
        for (int j = 0; j < 64; ++j) { t1[j*LD + lane] = A[j]; t1[j*LD + lane + 32] = B[j]; }
        __syncwarp();
        pack_cols(A2, B2, t1, lane);
    } else {
#pragma unroll
        for (int i = 0; i < 32; ++i) {
            float a0 = t0[(2*i)*LD + 2*lane]     + ((i == lane) ? sigma : 0.0f);
            float a1 = t0[(2*i+1)*LD + 2*lane];
            float b0 = t0[(2*i)*LD + 2*lane + 1];
            float b1 = t0[(2*i+1)*LD + 2*lane+1] + ((i == lane) ? sigma : 0.0f);
            A2[i] = pk2(a0, a1);
            B2[i] = pk2(b0, b1);
        }
    }

    hestenes_p(A2, B2, lane, 24, 1e-10f);

    float n1, n2;
    norms_p(A2, B2, n1, n2);
    __syncwarp();
    unpack_rows(A2, B2, t0, lane);                            // t0 = W^T
    sI[2*lane]   = rsqrtf(n1);
    sI[2*lane+1] = rsqrtf(n2);
    sG[2*lane]   = expf(sqrtf(n1) - sigma) / n1;              // e^{lambda}/lambda'^2
    sG[2*lane+1] = expf(sqrtf(n2) - sigma) / n2;
    __syncwarp();
    for (int k = 0; k < 64; ++k) {                            // V -> g_VL
        g_VL[k*64 + lane]      = t0[lane*LD + k]      * sI[lane];
        g_VL[k*64 + lane + 32] = t0[(lane+32)*LD + k] * sI[lane+32];
    }
    wouter_cols(A, B, t0, sG, lane);                          // E = expm(L)
    __syncwarp();
#pragma unroll
    for (int j = 0; j < 64; ++j) { t0[j*LD + lane] = A[j]; t0[j*LD + lane + 32] = B[j]; }  // t0 = E
    for (int idx = lane; idx < N*N; idx += 32)
        t1[(idx>>6)*LD + (idx&63)] = g_Ms[idx];               // t1 = Ms
    __syncwarp();
    wgemm_cols(A, B, t1, t0, lane);                           // T = Ms*E
    __syncwarp();
#pragma unroll
    for (int j = 0; j < 64; ++j) { t0[j*LD + lane] = A[j]; t0[j*LD + lane + 32] = B[j]; }  // t0 = T
    __syncwarp();
    wgemm_cols(A, B, t0, t1, lane);                           // Mn = T*Ms
    __syncwarp();
#pragma unroll
    for (int j = 0; j < 64; ++j) { t0[j*LD + lane] = A[j]; t0[j*LD + lane + 32] = B[j]; }  // t0 = Mn
    __syncwarp();
    for (int idx = lane; idx < N*N; idx += 32) {
        int i = idx >> 6, j = idx & 63;
        g_M[idx] = 0.5f * (t0[i*LD + j] + t0[j*LD + i]);
    }
}

// C = expm(0.25 (bias + bias^T)) * invsqrtm(M)
__global__ void __launch_bounds__(32) final_prep_kernel(const float* __restrict__ bias) {
    __shared__ float t0[TILE], t1[TILE];
    __shared__ float sG[64];
    __shared__ float s_sigma;
    const int lane = threadIdx.x;
    const unsigned FULL = 0xffffffffu;
    float A[64], B[64];
    u64 A2[32], B2[32];

    // ---- eig(M), warm from g_VM -> Mis into t0 ----
    for (int idx = lane; idx < N*N; idx += 32)
        t0[(idx>>6)*LD + (idx&63)] = g_M[idx];
    for (int idx = lane; idx < N*N; idx += 32)
        t1[(idx>>6)*LD + (idx&63)] = g_VM[idx];
    __syncwarp();
    wgemm_cols(A, B, t0, t1, lane);
    __syncwarp();
#pragma unroll
    for (int j = 0; j < 64; ++j) { t1[j*LD + lane] = A[j]; t1[j*LD + lane + 32] = B[j]; }
    __syncwarp();
    pack_cols(A2, B2, t1, lane);
    hestenes_p(A2, B2, lane, 24, 1e-10f);
    float n1, n2;
    norms_p(A2, B2, n1, n2);
    __syncwarp();
    unpack_rows(A2, B2, t1, lane);
    sG[2*lane]   = expf(-1.25f * logf(n1));
    sG[2*lane+1] = expf(-1.25f * logf(n2));
    __syncwarp();
    wouter_cols(A, B, t1, sG, lane);                          // Mis
    __syncwarp();
#pragma unroll
    for (int j = 0; j < 64; ++j) { t0[j*LD + lane] = A[j]; t0[j*LD + lane + 32] = B[j]; }  // t0 = Mis
    __syncwarp();

    // ---- eig(0.25(b+b^T) + sigma I) -> Bs ----
    float fro2 = 0.0f;
    for (int idx = lane; idx < N*N; idx += 32) {
        int i = idx >> 6, j = idx & 63;
        float v = 0.25f * (bias[i*64 + j] + bias[j*64 + i]);
        t1[i*LD + j] = v;
        fro2 = fmaf(v, v, fro2);
    }
#pragma unroll
    for (int o = 16; o > 0; o >>= 1) fro2 += __shfl_down_sync(FULL, fro2, o);
    if (lane == 0) s_sigma = 1.05f * sqrtf(fro2) + 1e-12f;
    __syncwarp();
    const float sb = s_sigma;
#pragma unroll
    for (int i = 0; i < 32; ++i) {
        float a0 = t1[(2*i)*LD + 2*lane]     + ((i == lane) ? sb : 0.0f);
        float a1 = t1[(2*i+1)*LD + 2*lane];
        float b0 = t1[(2*i)*LD + 2*lane + 1];
        float b1 = t1[(2*i+1)*LD + 2*lane+1] + ((i == lane) ? sb : 0.0f);
        A2[i] = pk2(a0, a1);
        B2[i] = pk2(b0, b1);
    }
    hestenes_p(A2, B2, lane, 24, 1e-10f);
    norms_p(A2, B2, n1, n2);
    __syncwarp();
    unpack_rows(A2, B2, t1, lane);
    sG[2*lane]   = expf(sqrtf(n1) - sb) / n1;
    sG[2*lane+1] = expf(sqrtf(n2) - sb) / n2;
    __syncwarp();
    wouter_cols(A, B, t1, sG, lane);                          // Bs
    __syncwarp();
#pragma unroll
    for (int j = 0; j < 64; ++j) { t1[j*LD + lane] = A[j]; t1[j*LD + lane + 32] = B[j]; }  // t1 = Bs
    __syncwarp();
    wgemm_cols(A, B, t1, t0, lane);                           // C = Bs * Mis
    for (int i = 0; i < 64; ++i) {
        g_C[i*64 + lane]      = A[i];
        g_C[i*64 + lane + 32] = B[i];
    }
}

// ----------------------------------------------------------------------------
// Batch logm: one warp per matrix, 8 per block, packed odd-even Hestenes.
// ----------------------------------------------------------------------------
__global__ void __launch_bounds__(256) batch_log8_kernel(const float* __restrict__ data,
                                                         int warm, int store_v, int Bsz) {
    extern __shared__ float sm[];
    float* mis = sm;                          // 64 x LD, shared by all warps
    const int tid  = threadIdx.x;
    const int wid  = tid >> 5;
    const int lane = tid & 31;
    float* tile = sm + TILE * (1 + wid);
    float* sG = sm + 9*TILE + wid*64;
    float* sI = sm + 9*TILE + 512 + wid*64;

    for (int idx = tid; idx < N*N; idx += 256)
        mis[(idx >> 6)*LD + (idx & 63)] = g_Mis[idx];
    __syncthreads();

    const int b = blockIdx.x * 8 + wid;
    if (b >= Bsz) return;

    const float* X = data + (size_t)b * (N*N);
    for (int idx = lane; idx < 1024; idx += 32) {
        float4 v = ((const float4*)X)[idx];
        int r = idx >> 4, c = (idx & 15) << 2;
        tile[r*LD + c + 0] = v.x;
        tile[r*LD + c + 1] = v.y;
        tile[r*LD + c + 2] = v.z;
        tile[r*LD + c + 3] = v.w;
    }
    __syncwarp();

    const int c1 = lane, c2 = lane + 32;
    float A[64], B[64];

    // GEMM1: Z = X * Mis
#pragma unroll
    for (int j = 0; j < 64; ++j) { A[j] = 0.0f; B[j] = 0.0f; }
    for (int k = 0; k < 64; ++k) {
        float m1 = mis[k*LD + c1];
        float m2 = mis[k*LD + c2];
#pragma unroll
        for (int i = 0; i < 64; ++i) {
            float x = tile[i*LD + k];
            A[i] = fmaf(x, m1, A[i]);
            B[i] = fmaf(x, m2, B[i]);
        }
    }
    __syncwarp();
#pragma unroll
    for (int k = 0; k < 64; ++k) { tile[k*LD + c1] = A[k]; tile[k*LD + c2] = B[k]; }
    __syncwarp();

    // GEMM2: Y = Mis * Z
#pragma unroll
    for (int j = 0; j < 64; ++j) { A[j] = 0.0f; B[j] = 0.0f; }
    for (int k = 0; k < 64; ++k) {
        float z1 = tile[k*LD + c1];
        float z2 = tile[k*LD + c2];
#pragma unroll
        for (int i = 0; i < 64; ++i) {
            float m = mis[i*LD + k];
            A[i] = fmaf(m, z1, A[i]);
            B[i] = fmaf(m, z2, B[i]);
        }
    }

    if (warm) {
        __syncwarp();
#pragma unroll
        for (int i = 0; i < 64; ++i) { tile[i*LD + c1] = A[i]; tile[i*LD + c2] = B[i]; }  // Y
        __syncwarp();
        const float* Vp = g_Vw + (size_t)b * (N*N);
#pragma unroll
        for (int j = 0; j < 64; ++j) { A[j] = 0.0f; B[j] = 0.0f; }
        for (int k = 0; k < 64; ++k) {
            float v1 = Vp[k*64 + c1];
            float v2 = Vp[k*64 + c2];
#pragma unroll
            for (int i = 0; i < 64; ++i) {
                float y = tile[i*LD + k];
                A[i] = fmaf(y, v1, A[i]);
                B[i] = fmaf(y, v2, B[i]);
            }
        }
    }

    // relabel columns (c1,c2) -> packed positions (2*lane, 2*lane+1)
    __syncwarp();
#pragma unroll
    for (int j = 0; j < 64; ++j) { tile[j*LD + c1] = A[j]; tile[j*LD + c2] = B[j]; }
    __syncwarp();
    u64 A2[32], B2[32];
    pack_cols(A2, B2, tile, lane);

    hestenes_p(A2, B2, lane, 16, 1e-8f);

    float n1, n2;
    norms_p(A2, B2, n1, n2);
    __syncwarp();
    unpack_rows(A2, B2, tile, lane);                          // tile = W^T
    sG[2*lane]   = 0.5f * logf(n1) / n1;     // log(lambda)/lambda^2
    sG[2*lane+1] = 0.5f * logf(n2) / n2;
    sI[2*lane]   = rsqrtf(n1);
    sI[2*lane+1] = rsqrtf(n2);
    __syncwarp();

    // O = W diag(g) W^T
    wouter_cols(A, B, tile, sG, lane);
    float* Ob = g_scratch + (size_t)b * (N*N);
#pragma unroll
    for (int j = 0; j < 16; ++j) {
        ((float4*)Ob)[c1*16 + j] = make_float4(A[4*j], A[4*j+1], A[4*j+2], A[4*j+3]);
        ((float4*)Ob)[c2*16 + j] = make_float4(B[4*j], B[4*j+1], B[4*j+2], B[4*j+3]);
    }

    if (store_v) {
        float* Vd = g_Vw + (size_t)b * (N*N);
#pragma unroll
        for (int k = 0; k < 64; ++k) {
            Vd[k*64 + c1] = tile[c1*LD + k] * sI[c1];
            Vd[k*64 + c2] = tile[c2*LD + k] * sI[c2];
        }
    }
}

// out_b = C X_b C^T
__global__ void __launch_bounds__(NT) apply_kernel(const float* __restrict__ data,
                                                   float* __restrict__ out) {
    extern __shared__ float sm[];
    float *b0 = sm, *b1 = sm + TILE, *b2 = sm + 2*TILE, *b3 = sm + 3*TILE;
    const size_t b = blockIdx.x;
    g2s(b1, g_C);
    g2s(b0, data + b * (N*N));
    gemm_nn(b2, b1, b0);
    gemm_nt(b3, b2, b1);
    s2g(out + b * (N*N), b3);
}

// ----------------------------------------------------------------------------
// Host launcher (graph-capturable)
// ----------------------------------------------------------------------------
extern "C" void kernel_launch(void* const* d_in, const int* in_sizes, int n_in,
                              void* d_out, int out_size) {
    const float* data = (const float*)d_in[0];
    const float* bias = (const float*)d_in[1];
    int sz0 = in_sizes[0], sz1 = (n_in > 1) ? in_sizes[1] : 0;
    if (sz0 == N*N && sz1 > N*N) {
        data = (const float*)d_in[1];
        bias = (const float*)d_in[0];
        int t = sz0; sz0 = sz1; sz1 = t;
    }
    int Bsz = sz0 / (N*N);
    if (Bsz > MAXB) Bsz = MAXB;
    float* out = (float*)d_out;

    const size_t shmem4 = 4 * TILE * sizeof(float);             // apply
    const size_t shmem8 = (9 * TILE + 1024) * sizeof(float);    // batch
    cudaFuncSetAttribute(batch_log8_kernel, cudaFuncAttributeMaxDynamicSharedMemorySize, (int)shmem8);
    cudaFuncSetAttribute(apply_kernel,      cudaFuncAttributeMaxDynamicSharedMemorySize, (int)shmem4);

    float *pM, *pL, *pScr, *pPart;
    cudaGetSymbolAddress((void**)&pM,    g_M);
    cudaGetSymbolAddress((void**)&pL,    g_L);
    cudaGetSymbolAddress((void**)&pScr,  g_scratch);
    cudaGetSymbolAddress((void**)&pPart, g_partial);

    const int nb1 = (Bsz + 31) / 32;
    const int nb8 = (Bsz + 7) / 8;
    const float inv = 1.0f / (float)Bsz;

    reduce32_kernel    <<<nb1, NT>>>(data, pPart, Bsz);
    reduceFinal_kernel <<<16,  NT>>>(pPart, pM, nb1, inv);

    for (int it = 0; it < 5; ++it) {
        prep_M_kernel     <<<1,   32>>>(it > 0 ? 1 : 0);
        batch_log8_kernel <<<nb8, 256, shmem8>>>(data, it > 0 ? 1 : 0, it < 4 ? 1 : 0, Bsz);
        reduce32_kernel    <<<nb1, NT>>>(pScr, pPart, Bsz);
        reduceFinal_kernel <<<16,  NT>>>(pPart, pL, nb1, inv);
        update_M_kernel   <<<1,   32>>>(it > 0 ? 1 : 0);
    }

    final_prep_kernel <<<1,   32>>>(bias);
    apply_kernel      <<<Bsz, NT, shmem4>>>(data, out);
}

// round 11
// speedup vs baseline: 2.9807x; 1.0116x over previous
#include <cuda_runtime.h>
#include <math.h>

#define N    64
#define LD   65            // padded leading dim in shared
#define NT   256
#define TILE (N*LD)
#define MAXB 8192

typedef unsigned long long u64;

// ----------------------------------------------------------------------------
// f32x2 packed helpers (sm_103a packed FP32 pipe; only reachable via PTX)
// ----------------------------------------------------------------------------
__device__ __forceinline__ u64 pk2(float lo, float hi) {
    u64 r; asm("mov.b64 %0,{%1,%2};" : "=l"(r) : "f"(lo), "f"(hi)); return r;
}
__device__ __forceinline__ void up2(u64 v, float& lo, float& hi) {
    asm("mov.b64 {%0,%1},%2;" : "=f"(lo), "=f"(hi) : "l"(v));
}
__device__ __forceinline__ u64 fma2(u64 a, u64 b, u64 c) {
    u64 r; asm("fma.rn.f32x2 %0,%1,%2,%3;" : "=l"(r) : "l"(a), "l"(b), "l"(c)); return r;
}
__device__ __forceinline__ u64 mul2(u64 a, u64 b) {
    u64 r; asm("mul.rn.f32x2 %0,%1,%2;" : "=l"(r) : "l"(a), "l"(b)); return r;
}
__device__ __forceinline__ u64 add2(u64 a, u64 b) {
    u64 r; asm("add.rn.f32x2 %0,%1,%2;" : "=l"(r) : "l"(a), "l"(b)); return r;
}

// Fast rotation scalars: all-approx MUFU chain (div.approx / rsqrt.approx).
// Jacobi self-corrects <=4-ulp rotation errors; norms are refreshed per sweep.
__device__ __forceinline__ void rot_cs(float na, float nb, float d,
                                       float& c, float& s) {
    float ta = __fdividef(nb - na, 2.0f * d);
    float h  = fmaf(ta, ta, 1.0f);
    float t  = copysignf(1.0f, ta) * __fdividef(1.0f, fabsf(ta) + h * rsqrtf(h));
    c = rsqrtf(fmaf(t, t, 1.0f));
    s = t * c;
}

// ----------------------------------------------------------------------------
// Global scratch
// ----------------------------------------------------------------------------
__device__ float g_M  [N*N];
__device__ float g_Ms [N*N];
__device__ float g_Mis[N*N];
__device__ float g_L  [N*N];
__device__ float g_C  [N*N];
__device__ float g_VM [N*N];                   // warm-start eigvecs of M (row-major [k][c])
__device__ float g_VL [N*N];                   // warm-start eigvecs of L+sI
__device__ float g_scratch[(size_t)MAXB*N*N];  // per-matrix logm
__device__ float g_Vw     [(size_t)MAXB*N*N];  // per-matrix eigvecs, row-major [k][c]
__device__ float g_partial[(MAXB/32)*N*N];

// ----------------------------------------------------------------------------
// Packed one-sided (Hestenes) Jacobi, odd-even ordering. Lane l holds columns
// at positions 2l (A) and 2l+1 (B); each column = 32 packed f32x2 values.
// Even rounds pair (A,B) in-lane and swap; odd rounds pair (B_l, A_{l+1}) via
// shfl and swap across the boundary. 64 rounds/sweep covers all C(64,2) pairs.
// ----------------------------------------------------------------------------
__device__ __forceinline__ void hestenes_p(u64 (&A)[32], u64 (&B)[32],
                                           int lane, int max_sweeps, float thr) {
    const unsigned FULL = 0xffffffffu;
    for (int sweep = 0; sweep < max_sweeps; ++sweep) {
        float nA, nB;
        {
            u64 a0=0ull,a1=0ull,a2=0ull,a3=0ull, b0=0ull,b1=0ull,b2=0ull,b3=0ull;
#pragma unroll
            for (int i = 0; i < 32; i += 4) {
                a0 = fma2(A[i],   A[i],   a0);
                a1 = fma2(A[i+1], A[i+1], a1);
                a2 = fma2(A[i+2], A[i+2], a2);
                a3 = fma2(A[i+3], A[i+3], a3);
                b0 = fma2(B[i],   B[i],   b0);
                b1 = fma2(B[i+1], B[i+1], b1);
                b2 = fma2(B[i+2], B[i+2], b2);
                b3 = fma2(B[i+3], B[i+3], b3);
            }
            u64 sa = add2(add2(a0,a1), add2(a2,a3));
            u64 sb = add2(add2(b0,b1), add2(b2,b3));
            float x0,x1,y0,y1; up2(sa,x0,x1); up2(sb,y0,y1);
            nA = x0+x1; nB = y0+y1;
        }
        int rotated = 0;
        for (int rr = 0; rr < 32; ++rr) {
            // ---- even round: pair (A,B) within lane ----
            {
                u64 c0=0ull,c1_=0ull,c2_=0ull,c3=0ull;
#pragma unroll
                for (int i = 0; i < 32; i += 4) {
                    c0  = fma2(A[i],   B[i],   c0);
                    c1_ = fma2(A[i+1], B[i+1], c1_);
                    c2_ = fma2(A[i+2], B[i+2], c2_);
                    c3  = fma2(A[i+3], B[i+3], c3);
                }
                u64 sc = add2(add2(c0,c1_), add2(c2_,c3));
                float d0,d1; up2(sc,d0,d1);
                float d = d0+d1;
                bool rot = d*d > thr*nA*nB;
                if (__any_sync(FULL, rot)) {
                    rotated = 1;
                    float c = 1.0f, s = 0.0f;
                    if (rot) rot_cs(nA, nB, d, c, s);
                    u64 cp = pk2(c,c), sp = pk2(s,s), np = pk2(-s,-s);
#pragma unroll
                    for (int i = 0; i < 32; ++i) {
                        u64 x = A[i], y = B[i];
                        A[i] = fma2(sp, x, mul2(cp, y));   // v -> pos 2l (swap)
                        B[i] = fma2(cp, x, mul2(np, y));   // u -> pos 2l+1
                    }
                    float cc=c*c, ss=s*s, cs2=2.0f*c*s;
                    float nu = cc*nA - cs2*d + ss*nB;
                    float nv = ss*nA + cs2*d + cc*nB;
                    nA = nv; nB = nu;
                } else {
#pragma unroll
                    for (int i = 0; i < 32; ++i) { u64 t=A[i]; A[i]=B[i]; B[i]=t; }
                    float t = nA; nA = nB; nB = t;
                }
            }
            // ---- odd round: pair (B_l, A_{l+1}); positions 0 and 63 idle ----
            {
                float ny = __shfl_down_sync(FULL, nA, 1);
                u64 c0=0ull,c1_=0ull,c2_=0ull,c3=0ull;
#pragma unroll
                for (int i = 0; i < 32; i += 4) {
                    u64 y0 = __shfl_down_sync(FULL, A[i],   1);
                    u64 y1 = __shfl_down_sync(FULL, A[i+1], 1);
                    u64 y2 = __shfl_down_sync(FULL, A[i+2], 1);
                    u64 y3 = __shfl_down_sync(FULL, A[i+3], 1);
                    c0  = fma2(B[i],   y0, c0);
                    c1_ = fma2(B[i+1], y1, c1_);
                    c2_ = fma2(B[i+2], y2, c2_);
                    c3  = fma2(B[i+3], y3, c3);
                }
                u64 sc = add2(add2(c0,c1_), add2(c2_,c3));
                float d0,d1; up2(sc,d0,d1);
                float d = d0+d1;
                bool rot = (lane < 31) && (d*d > thr*nB*ny);
                if (__any_sync(FULL, rot)) {
                    rotated = 1;
                    float c = 1.0f, s = 0.0f;
                    if (rot) rot_cs(nB, ny, d, c, s);
                    u64 cp = pk2(c,c), sp = pk2(s,s), np = pk2(-s,-s);
#pragma unroll
                    for (int i = 0; i < 32; ++i) {
                        u64 x = B[i];
                        u64 y = __shfl_down_sync(FULL, A[i], 1);
                        u64 u = fma2(cp, x, mul2(np, y));
                        u64 v = fma2(sp, x, mul2(cp, y));
                        u64 us = __shfl_up_sync(FULL, u, 1);
                        B[i] = (lane==31) ? B[i] : v;
                        A[i] = (lane==0)  ? A[i] : us;
                    }
                    float cc=c*c, ss=s*s, cs2=2.0f*c*s;
                    float nu = cc*nB - cs2*d + ss*ny;
                    float nv = ss*nB + cs2*d + cc*ny;
                    float nus = __shfl_up_sync(FULL, nu, 1);
                    nB = (lane==31) ? nB : nv;
                    nA = (lane==0)  ? nA : nus;
                } else {
                    // quiet fast-path: pure positional swap across lane boundary
#pragma unroll
                    for (int i = 0; i < 32; ++i) {
                        u64 y  = __shfl_down_sync(FULL, A[i], 1);
                        u64 xs = __shfl_up_sync(FULL, B[i], 1);
                        B[i] = (lane==31) ? B[i] : y;
                        A[i] = (lane==0)  ? A[i] : xs;
                    }
                    float nus = __shfl_up_sync(FULL, nB, 1);
                    nB = (lane==31) ? nB : ny;
                    nA = (lane==0)  ? nA : nus;
                }
            }
        }
        if (!rotated) break;
    }
}

// pack columns (2*lane, 2*lane+1) of an LD-padded shared matrix into registers
__device__ __forceinline__ void pack_cols(u64 (&A)[32], u64 (&B)[32],
                                          const float* S, int lane) {
#pragma unroll
    for (int i = 0; i < 32; ++i) {
        A[i] = pk2(S[(2*i)*LD + 2*lane],     S[(2*i+1)*LD + 2*lane]);
        B[i] = pk2(S[(2*i)*LD + 2*lane + 1], S[(2*i+1)*LD + 2*lane + 1]);
    }
}
// packed squared norms of the two held columns (4-way chains)
__device__ __forceinline__ void norms_p(const u64 (&A)[32], const u64 (&B)[32],
                                        float& n1, float& n2) {
    u64 a0=0ull,a1=0ull,a2=0ull,a3=0ull, b0=0ull,b1=0ull,b2=0ull,b3=0ull;
#pragma unroll
    for (int i = 0; i < 32; i += 4) {
        a0 = fma2(A[i],   A[i],   a0);
        a1 = fma2(A[i+1], A[i+1], a1);
        a2 = fma2(A[i+2], A[i+2], a2);
        a3 = fma2(A[i+3], A[i+3], a3);
        b0 = fma2(B[i],   B[i],   b0);
        b1 = fma2(B[i+1], B[i+1], b1);
        b2 = fma2(B[i+2], B[i+2], b2);
        b3 = fma2(B[i+3], B[i+3], b3);
    }
    u64 sa = add2(add2(a0,a1), add2(a2,a3));
    u64 sb = add2(add2(b0,b1), add2(b2,b3));
    float x0,x1,y0,y1; up2(sa,x0,x1); up2(sb,y0,y1);
    n1 = fmaxf(x0+x1, 1e-30f);
    n2 = fmaxf(y0+y1, 1e-30f);
}
// write held columns as ROWS 2*lane, 2*lane+1 of an LD-padded shared matrix (W^T)
__device__ __forceinline__ void unpack_rows(const u64 (&A)[32], const u64 (&B)[32],
                                            float* S, int lane) {
#pragma unroll
    for (int i = 0; i < 32; ++i) {
        float x0,x1,y0,y1;
        up2(A[i],x0,x1); up2(B[i],y0,y1);
        S[(2*lane)*LD   + 2*i]     = x0;
        S[(2*lane)*LD   + 2*i + 1] = x1;
        S[(2*lane+1)*LD + 2*i]     = y0;
        S[(2*lane+1)*LD + 2*i + 1] = y1;
    }
}

// ----------------------------------------------------------------------------
// Warp GEMM helpers (1 warp computes two output columns: c=lane, c=lane+32)
// ----------------------------------------------------------------------------
__device__ __forceinline__ void wgemm_cols(float (&o1)[64], float (&o2)[64],
                                           const float* Ash, const float* Bsh, int lane) {
#pragma unroll
    for (int j = 0; j < 64; ++j) { o1[j] = 0.0f; o2[j] = 0.0f; }
    for (int k = 0; k < 64; ++k) {
        float b1 = Bsh[k*LD + lane];
        float b2 = Bsh[k*LD + lane + 32];
#pragma unroll
        for (int i = 0; i < 64; ++i) {
            float a = Ash[i*LD + k];
            o1[i] = fmaf(a, b1, o1[i]);
            o2[i] = fmaf(a, b2, o2[i]);
        }
    }
}
// o[:,c] = sum_k g[k] * W[:,k] * W[c,k], with Wt[k][j] = W[j][k] in shared
__device__ __forceinline__ void wouter_cols(float (&o1)[64], float (&o2)[64],
                                            const float* Wt, const float* g, int lane) {
#pragma unroll
    for (int j = 0; j < 64; ++j) { o1[j] = 0.0f; o2[j] = 0.0f; }
    for (int k = 0; k < 64; ++k) {
        float gk = g[k];
        float a1 = gk * Wt[k*LD + lane];
        float a2 = gk * Wt[k*LD + lane + 32];
#pragma unroll
        for (int i = 0; i < 64; ++i) {
            float s = Wt[k*LD + i];
            o1[i] = fmaf(s, a1, o1[i]);
            o2[i] = fmaf(s, a2, o2[i]);
        }
    }
}

// ----------------------------------------------------------------------------
// Block helpers for apply_kernel
// ----------------------------------------------------------------------------
__device__ __forceinline__ void g2s(float* S, const float* __restrict__ G) {
    for (int idx = threadIdx.x; idx < N*N; idx += NT)
        S[(idx >> 6) * LD + (idx & 63)] = G[idx];
    __syncthreads();
}
__device__ __forceinline__ void s2g(float* __restrict__ G, const float* S) {
    for (int idx = threadIdx.x; idx < N*N; idx += NT)
        G[idx] = S[(idx >> 6) * LD + (idx & 63)];
    __syncthreads();
}
__device__ __forceinline__ void gemm_nn(float* D, const float* A, const float* B) {
    const int tx = (threadIdx.x & 15) << 2;
    const int ty = (threadIdx.x >> 4) << 2;
    float acc[4][4] = {};
#pragma unroll 8
    for (int k = 0; k < N; ++k) {
        float a0 = A[(ty+0)*LD + k], a1 = A[(ty+1)*LD + k];
        float a2 = A[(ty+2)*LD + k], a3 = A[(ty+3)*LD + k];
        float b0 = B[k*LD + tx+0], b1 = B[k*LD + tx+1];
        float b2 = B[k*LD + tx+2], b3 = B[k*LD + tx+3];
        acc[0][0]+=a0*b0; acc[0][1]+=a0*b1; acc[0][2]+=a0*b2; acc[0][3]+=a0*b3;
        acc[1][0]+=a1*b0; acc[1][1]+=a1*b1; acc[1][2]+=a1*b2; acc[1][3]+=a1*b3;
        acc[2][0]+=a2*b0; acc[2][1]+=a2*b1; acc[2][2]+=a2*b2; acc[2][3]+=a2*b3;
        acc[3][0]+=a3*b0; acc[3][1]+=a3*b1; acc[3][2]+=a3*b2; acc[3][3]+=a3*b3;
    }
#pragma unroll
    for (int r = 0; r < 4; ++r)
#pragma unroll
        for (int c = 0; c < 4; ++c)
            D[(ty+r)*LD + tx + c] = acc[r][c];
    __syncthreads();
}
__device__ __forceinline__ void gemm_nt(float* D, const float* A, const float* B) {
    const int tx = (threadIdx.x & 15) << 2;
    const int ty = (threadIdx.x >> 4) << 2;
    float acc[4][4] = {};
#pragma unroll 8
    for (int k = 0; k < N; ++k) {
        float a0 = A[(ty+0)*LD + k], a1 = A[(ty+1)*LD + k];
        float a2 = A[(ty+2)*LD + k], a3 = A[(ty+3)*LD + k];
        float b0 = B[(tx+0)*LD + k], b1 = B[(tx+1)*LD + k];
        float b2 = B[(tx+2)*LD + k], b3 = B[(tx+3)*LD + k];
        acc[0][0]+=a0*b0; acc[0][1]+=a0*b1; acc[0][2]+=a0*b2; acc[0][3]+=a0*b3;
        acc[1][0]+=a1*b0; acc[1][1]+=a1*b1; acc[1][2]+=a1*b2; acc[1][3]+=a1*b3;
        acc[2][0]+=a2*b0; acc[2][1]+=a2*b1; acc[2][2]+=a2*b2; acc[2][3]+=a2*b3;
        acc[3][0]+=a3*b0; acc[3][1]+=a3*b1; acc[3][2]+=a3*b2; acc[3][3]+=a3*b3;
    }
#pragma unroll
    for (int r = 0; r < 4; ++r)
#pragma unroll
        for (int c = 0; c < 4; ++c)
            D[(ty+r)*LD + tx + c] = acc[r][c];
    __syncthreads();
}

// ----------------------------------------------------------------------------
// Reductions
// ----------------------------------------------------------------------------
__global__ void __launch_bounds__(NT) reduce32_kernel(const float* __restrict__ src,
                                                      float* __restrict__ dst, int Bsz) {
    int j = blockIdx.x;
    int b0 = j * 32;
    int cnt = min(32, Bsz - b0);
    for (int i = threadIdx.x; i < N*N; i += NT) {
        float a = 0.0f;
        for (int k = 0; k < cnt; ++k)
            a += src[(size_t)(b0 + k) * (N*N) + i];
        dst[(size_t)j * (N*N) + i] = a;
    }
}
__global__ void __launch_bounds__(NT) reduceFinal_kernel(const float* __restrict__ part,
                                                         float* __restrict__ dst,
                                                         int nb, float scale) {
    int i = blockIdx.x * NT + threadIdx.x;
    float a = 0.0f;
    for (int j = 0; j < nb; ++j)
        a += part[(size_t)j * (N*N) + i];
    dst[i] = a * scale;
}

// ----------------------------------------------------------------------------
// Single-matrix warp kernels (1 warp = 32 threads)
// ----------------------------------------------------------------------------

// eig(M) -> g_Ms = M^{1/2}, g_Mis = M^{-1/2}, V -> g_VM.  Warm from g_VM.
__global__ void __launch_bounds__(32) prep_M_kernel(int warm) {
    __shared__ float t0[TILE], t1[TILE];
    __shared__ float sG[64], sI[64];
    const int lane = threadIdx.x;
    float A[64], B[64];
    u64 A2[32], B2[32];

    for (int idx = lane; idx < N*N; idx += 32)
        t0[(idx>>6)*LD + (idx&63)] = g_M[idx];
    __syncwarp();

    if (warm) {
        for (int idx = lane; idx < N*N; idx += 32)
            t1[(idx>>6)*LD + (idx&63)] = g_VM[idx];          // [k][c]
        __syncwarp();
        wgemm_cols(A, B, t0, t1, lane);                      // W0 = M * Vp
        __syncwarp();
#pragma unroll
        for (int j = 0; j < 64; ++j) { t1[j*LD + lane] = A[j]; t1[j*LD + lane + 32] = B[j]; }
        __syncwarp();
        pack_cols(A2, B2, t1, lane);
    } else {
        pack_cols(A2, B2, t0, lane);
    }

    hestenes_p(A2, B2, lane, 24, 1e-10f);

    float n1, n2;
    norms_p(A2, B2, n1, n2);
    __syncwarp();
    unpack_rows(A2, B2, t1, lane);                            // t1 = W^T
    sI[2*lane]   = rsqrtf(n1);
    sI[2*lane+1] = rsqrtf(n2);
    // Ms: g = lambda^{-3/2} = n^{-3/4}
    sG[2*lane]   = __expf(-0.75f * __logf(n1));
    sG[2*lane+1] = __expf(-0.75f * __logf(n2));
    __syncwarp();

    // V -> g_VM (row-major [k][c]): V[:,c] = W[:,c]/lambda_c
    for (int k = 0; k < 64; ++k) {
        g_VM[k*64 + lane]      = t1[lane*LD + k]      * sI[lane];
        g_VM[k*64 + lane + 32] = t1[(lane+32)*LD + k] * sI[lane+32];
    }
    wouter_cols(A, B, t1, sG, lane);                          // Ms (symmetric)
#pragma unroll
    for (int j = 0; j < 16; ++j) {
        ((float4*)g_Ms)[lane*16 + j]      = make_float4(A[4*j],A[4*j+1],A[4*j+2],A[4*j+3]);
        ((float4*)g_Ms)[(lane+32)*16 + j] = make_float4(B[4*j],B[4*j+1],B[4*j+2],B[4*j+3]);
    }
    // Mis: g = n^{-5/4}
    sG[2*lane]   = __expf(-1.25f * __logf(n1));
    sG[2*lane+1] = __expf(-1.25f * __logf(n2));
    __syncwarp();
    wouter_cols(A, B, t1, sG, lane);
#pragma unroll
    for (int j = 0; j < 16; ++j) {
        ((float4*)g_Mis)[lane*16 + j]      = make_float4(A[4*j],A[4*j+1],A[4*j+2],A[4*j+3]);
        ((float4*)g_Mis)[(lane+32)*16 + j] = make_float4(B[4*j],B[4*j+1],B[4*j+2],B[4*j+3]);
    }
}

// M <- sym(Ms expm(L) Ms).  eig(L + sigma I) warm from g_VL.
__global__ void __launch_bounds__(32) update_M_kernel(int warm) {
    __shared__ float t0[TILE], t1[TILE];
    __shared__ float sG[64], sI[64];
    __shared__ float s_sigma;
    const int lane = threadIdx.x;
    const unsigned FULL = 0xffffffffu;
    float A[64], B[64];
    u64 A2[32], B2[32];

    float fro2 = 0.0f;
    for (int idx = lane; idx < N*N; idx += 32) {
        float v = g_L[idx];
        t0[(idx>>6)*LD + (idx&63)] = v;
        fro2 = fmaf(v, v, fro2);
    }
#pragma unroll
    for (int o = 16; o > 0; o >>= 1) fro2 += __shfl_down_sync(FULL, fro2, o);
    if (lane == 0) s_sigma = 1.05f * sqrtf(fro2) + 1e-12f;
    __syncwarp();
    const float sigma = s_sigma;

    if (warm) {
        for (int idx = lane; idx < N*N; idx += 32)
            t1[(idx>>6)*LD + (idx&63)] = g_VL[idx];
        __syncwarp();
        wgemm_cols(A, B, t0, t1, lane);                      // L*Vp
#pragma unroll
        for (int j = 0; j < 64; ++j) {                       // + sigma*Vp
            A[j] = fmaf(sigma, t1[j*LD + lane],      A[j]);
            B[j] = fmaf(sigma, t1[j*LD + lane + 32], B[j]);
        }
        __syncwarp();
#pragma unroll
        for (int j = 0; j < 64; ++j) { t1[j*LD + lane] = A[j]; t1[j*LD + lane + 32] = B[j]; }
        __syncwarp();
        pack_cols(A2, B2, t1, lane);
    } else {
#pragma unroll
        for (int i = 0; i < 32; ++i) {
            float a0 = t0[(2*i)*LD + 2*lane]     + ((i == lane) ? sigma : 0.0f);
            float a1 = t0[(2*i+1)*LD + 2*lane];
            float b0 = t0[(2*i)*LD + 2*lane + 1];
            float b1 = t0[(2*i+1)*LD + 2*lane+1] + ((i == lane) ? sigma : 0.0f);
            A2[i] = pk2(a0, a1);
            B2[i] = pk2(b0, b1);
        }
    }

    hestenes_p(A2, B2, lane, 24, 1e-10f);

    float n1, n2;
    norms_p(A2, B2, n1, n2);
    __syncwarp();
    unpack_rows(A2, B2, t0, lane);                            // t0 = W^T
    sI[2*lane]   = rsqrtf(n1);
    sI[2*lane+1] = rsqrtf(n2);
    sG[2*lane]   = __expf(__fsqrt_rn(n1) - sigma) * __fdividef(1.0f, n1);  // e^{lambda}/lambda'^2
    sG[2*lane+1] = __expf(__fsqrt_rn(n2) - sigma) * __fdividef(1.0f, n2);
    __syncwarp();
    for (int k = 0; k < 64; ++k) {                            // V -> g_VL
        g_VL[k*64 + lane]      = t0[lane*LD + k]      * sI[lane];
        g_VL[k*64 + lane + 32] = t0[(lane+32)*LD + k] * sI[lane+32];
    }
    wouter_cols(A, B, t0, sG, lane);                          // E = expm(L)
    __syncwarp();
#pragma unroll
    for (int j = 0; j < 64; ++j) { t0[j*LD + lane] = A[j]; t0[j*LD + lane + 32] = B[j]; }  // t0 = E
    for (int idx = lane; idx < N*N; idx += 32)
        t1[(idx>>6)*LD + (idx&63)] = g_Ms[idx];               // t1 = Ms
    __syncwarp();
    wgemm_cols(A, B, t1, t0, lane);                           // T = Ms*E
    __syncwarp();
#pragma unroll
    for (int j = 0; j < 64; ++j) { t0[j*LD + lane] = A[j]; t0[j*LD + lane + 32] = B[j]; }  // t0 = T
    __syncwarp();
    wgemm_cols(A, B, t0, t1, lane);                           // Mn = T*Ms
    __syncwarp();
#pragma unroll
    for (int j = 0; j < 64; ++j) { t0[j*LD + lane] = A[j]; t0[j*LD + lane + 32] = B[j]; }  // t0 = Mn
    __syncwarp();
    for (int idx = lane; idx < N*N; idx += 32) {
        int i = idx >> 6, j = idx & 63;
        g_M[idx] = 0.5f * (t0[i*LD + j] + t0[j*LD + i]);
    }
}

// C = expm(0.25 (bias + bias^T)) * invsqrtm(M)
__global__ void __launch_bounds__(32) final_prep_kernel(const float* __restrict__ bias) {
    __shared__ float t0[TILE], t1[TILE];
    __shared__ float sG[64];
    __shared__ float s_sigma;
    const int lane = threadIdx.x;
    const unsigned FULL = 0xffffffffu;
    float A[64], B[64];
    u64 A2[32], B2[32];

    // ---- eig(M), warm from g_VM -> Mis into t0 ----
    for (int idx = lane; idx < N*N; idx += 32)
        t0[(idx>>6)*LD + (idx&63)] = g_M[idx];
    for (int idx = lane; idx < N*N; idx += 32)
        t1[(idx>>6)*LD + (idx&63)] = g_VM[idx];
    __syncwarp();
    wgemm_cols(A, B, t0, t1, lane);
    __syncwarp();
#pragma unroll
    for (int j = 0; j < 64; ++j) { t1[j*LD + lane] = A[j]; t1[j*LD + lane + 32] = B[j]; }
    __syncwarp();
    pack_cols(A2, B2, t1, lane);
    hestenes_p(A2, B2, lane, 24, 1e-10f);
    float n1, n2;
    norms_p(A2, B2, n1, n2);
    __syncwarp();
    unpack_rows(A2, B2, t1, lane);
    sG[2*lane]   = __expf(-1.25f * __logf(n1));
    sG[2*lane+1] = __expf(-1.25f * __logf(n2));
    __syncwarp();
    wouter_cols(A, B, t1, sG, lane);                          // Mis
    __syncwarp();
#pragma unroll
    for (int j = 0; j < 64; ++j) { t0[j*LD + lane] = A[j]; t0[j*LD + lane + 32] = B[j]; }  // t0 = Mis
    __syncwarp();

    // ---- eig(0.25(b+b^T) + sigma I) -> Bs ----
    float fro2 = 0.0f;
    for (int idx = lane; idx < N*N; idx += 32) {
        int i = idx >> 6, j = idx & 63;
        float v = 0.25f * (bias[i*64 + j] + bias[j*64 + i]);
        t1[i*LD + j] = v;
        fro2 = fmaf(v, v, fro2);
    }
#pragma unroll
    for (int o = 16; o > 0; o >>= 1) fro2 += __shfl_down_sync(FULL, fro2, o);
    if (lane == 0) s_sigma = 1.05f * sqrtf(fro2) + 1e-12f;
    __syncwarp();
    const float sb = s_sigma;
#pragma unroll
    for (int i = 0; i < 32; ++i) {
        float a0 = t1[(2*i)*LD + 2*lane]     + ((i == lane) ? sb : 0.0f);
        float a1 = t1[(2*i+1)*LD + 2*lane];
        float b0 = t1[(2*i)*LD + 2*lane + 1];
        float b1 = t1[(2*i+1)*LD + 2*lane+1] + ((i == lane) ? sb : 0.0f);
        A2[i] = pk2(a0, a1);
        B2[i] = pk2(b0, b1);
    }
    hestenes_p(A2, B2, lane, 24, 1e-10f);
    norms_p(A2, B2, n1, n2);
    __syncwarp();
    unpack_rows(A2, B2, t1, lane);
    sG[2*lane]   = __expf(__fsqrt_rn(n1) - sb) * __fdividef(1.0f, n1);
    sG[2*lane+1] = __expf(__fsqrt_rn(n2) - sb) * __fdividef(1.0f, n2);
    __syncwarp();
    wouter_cols(A, B, t1, sG, lane);                          // Bs
    __syncwarp();
#pragma unroll
    for (int j = 0; j < 64; ++j) { t1[j*LD + lane] = A[j]; t1[j*LD + lane + 32] = B[j]; }  // t1 = Bs
    __syncwarp();
    wgemm_cols(A, B, t1, t0, lane);                           // C = Bs * Mis
    for (int i = 0; i < 64; ++i) {
        g_C[i*64 + lane]      = A[i];
        g_C[i*64 + lane + 32] = B[i];
    }
}

// ----------------------------------------------------------------------------
// Batch logm: one warp per matrix, 8 per block, packed odd-even Hestenes.
// ----------------------------------------------------------------------------
__global__ void __launch_bounds__(256) batch_log8_kernel(const float* __restrict__ data,
                                                         int warm, int store_v, int Bsz) {
    extern __shared__ float sm[];
    float* mis = sm;                          // 64 x LD, shared by all warps
    const int tid  = threadIdx.x;
    const int wid  = tid >> 5;
    const int lane = tid & 31;
    float* tile = sm + TILE * (1 + wid);
    float* sG = sm + 9*TILE + wid*64;
    float* sI = sm + 9*TILE + 512 + wid*64;

    for (int idx = tid; idx < N*N; idx += 256)
        mis[(idx >> 6)*LD + (idx & 63)] = g_Mis[idx];
    __syncthreads();

    const int b = blockIdx.x * 8 + wid;
    if (b >= Bsz) return;

    const float* X = data + (size_t)b * (N*N);
    for (int idx = lane; idx < 1024; idx += 32) {
        float4 v = ((const float4*)X)[idx];
        int r = idx >> 4, c = (idx & 15) << 2;
        tile[r*LD + c + 0] = v.x;
        tile[r*LD + c + 1] = v.y;
        tile[r*LD + c + 2] = v.z;
        tile[r*LD + c + 3] = v.w;
    }
    __syncwarp();

    const int c1 = lane, c2 = lane + 32;
    float A[64], B[64];

    // GEMM1: Z = X * Mis
#pragma unroll
    for (int j = 0; j < 64; ++j) { A[j] = 0.0f; B[j] = 0.0f; }
    for (int k = 0; k < 64; ++k) {
        float m1 = mis[k*LD + c1];
        float m2 = mis[k*LD + c2];
#pragma unroll
        for (int i = 0; i < 64; ++i) {
            float x = tile[i*LD + k];
            A[i] = fmaf(x, m1, A[i]);
            B[i] = fmaf(x, m2, B[i]);
        }
    }
    __syncwarp();
#pragma unroll
    for (int k = 0; k < 64; ++k) { tile[k*LD + c1] = A[k]; tile[k*LD + c2] = B[k]; }
    __syncwarp();

    // GEMM2: Y = Mis * Z
#pragma unroll
    for (int j = 0; j < 64; ++j) { A[j] = 0.0f; B[j] = 0.0f; }
    for (int k = 0; k < 64; ++k) {
        float z1 = tile[k*LD + c1];
        float z2 = tile[k*LD + c2];
#pragma unroll
        for (int i = 0; i < 64; ++i) {
            float m = mis[i*LD + k];
            A[i] = fmaf(m, z1, A[i]);
            B[i] = fmaf(m, z2, B[i]);
        }
    }

    if (warm) {
        __syncwarp();
#pragma unroll
        for (int i = 0; i < 64; ++i) { tile[i*LD + c1] = A[i]; tile[i*LD + c2] = B[i]; }  // Y
        __syncwarp();
        const float* Vp = g_Vw + (size_t)b * (N*N);
#pragma unroll
        for (int j = 0; j < 64; ++j) { A[j] = 0.0f; B[j] = 0.0f; }
        for (int k = 0; k < 64; ++k) {
            float v1 = Vp[k*64 + c1];
            float v2 = Vp[k*64 + c2];
#pragma unroll
            for (int i = 0; i < 64; ++i) {
                float y = tile[i*LD + k];
                A[i] = fmaf(y, v1, A[i]);
                B[i] = fmaf(y, v2, B[i]);
            }
        }
    }

    // relabel columns (c1,c2) -> packed positions (2*lane, 2*lane+1)
    __syncwarp();
#pragma unroll
    for (int j = 0; j < 64; ++j) { tile[j*LD + c1] = A[j]; tile[j*LD + c2] = B[j]; }
    __syncwarp();
    u64 A2[32], B2[32];
    pack_cols(A2, B2, tile, lane);

    hestenes_p(A2, B2, lane, 16, 1e-8f);

    float n1, n2;
    norms_p(A2, B2, n1, n2);
    __syncwarp();
    unpack_rows(A2, B2, tile, lane);                          // tile = W^T
    sG[2*lane]   = __fdividef(0.5f * __logf(n1), n1);     // log(lambda)/lambda^2
    sG[2*lane+1] = __fdividef(0.5f * __logf(n2), n2);
    sI[2*lane]   = rsqrtf(n1);
    sI[2*lane+1] = rsqrtf(n2);
    __syncwarp();

    // O = W diag(g) W^T
    wouter_cols(A, B, tile, sG, lane);
    float* Ob = g_scratch + (size_t)b * (N*N);
#pragma unroll
    for (int j = 0; j < 16; ++j) {
        ((float4*)Ob)[c1*16 + j] = make_float4(A[4*j], A[4*j+1], A[4*j+2], A[4*j+3]);
        ((float4*)Ob)[c2*16 + j] = make_float4(B[4*j], B[4*j+1], B[4*j+2], B[4*j+3]);
    }

    if (store_v) {
        float* Vd = g_Vw + (size_t)b * (N*N);
#pragma unroll
        for (int k = 0; k < 64; ++k) {
            Vd[k*64 + c1] = tile[c1*LD + k] * sI[c1];
            Vd[k*64 + c2] = tile[c2*LD + k] * sI[c2];
        }
    }
}

// out_b = C X_b C^T
__global__ void __launch_bounds__(NT) apply_kernel(const float* __restrict__ data,
                                                   float* __restrict__ out) {
    extern __shared__ float sm[];
    float *b0 = sm, *b1 = sm + TILE, *b2 = sm + 2*TILE, *b3 = sm + 3*TILE;
    const size_t b = blockIdx.x;
    g2s(b1, g_C);
    g2s(b0, data + b * (N*N));
    gemm_nn(b2, b1, b0);
    gemm_nt(b3, b2, b1);
    s2g(out + b * (N*N), b3);
}

// ----------------------------------------------------------------------------
// Host launcher (graph-capturable)
// ----------------------------------------------------------------------------
extern "C" void kernel_launch(void* const* d_in, const int* in_sizes, int n_in,
                              void* d_out, int out_size) {
    const float* data = (const float*)d_in[0];
    const float* bias = (const float*)d_in[1];
    int sz0 = in_sizes[0], sz1 = (n_in > 1) ? in_sizes[1] : 0;
    if (sz0 == N*N && sz1 > N*N) {
        data = (const float*)d_in[1];
        bias = (const float*)d_in[0];
        int t = sz0; sz0 = sz1; sz1 = t;
    }
    int Bsz = sz0 / (N*N);
    if (Bsz > MAXB) Bsz = MAXB;
    float* out = (float*)d_out;

    const size_t shmem4 = 4 * TILE * sizeof(float);             // apply
    const size_t shmem8 = (9 * TILE + 1024) * sizeof(float);    // batch
    cudaFuncSetAttribute(batch_log8_kernel, cudaFuncAttributeMaxDynamicSharedMemorySize, (int)shmem8);
    cudaFuncSetAttribute(apply_kernel,      cudaFuncAttributeMaxDynamicSharedMemorySize, (int)shmem4);

    float *pM, *pL, *pScr, *pPart;
    cudaGetSymbolAddress((void**)&pM,    g_M);
    cudaGetSymbolAddress((void**)&pL,    g_L);
    cudaGetSymbolAddress((void**)&pScr,  g_scratch);
    cudaGetSymbolAddress((void**)&pPart, g_partial);

    const int nb1 = (Bsz + 31) / 32;
    const int nb8 = (Bsz + 7) / 8;
    const float inv = 1.0f / (float)Bsz;

    reduce32_kernel    <<<nb1, NT>>>(data, pPart, Bsz);
    reduceFinal_kernel <<<16,  NT>>>(pPart, pM, nb1, inv);

    for (int it = 0; it < 5; ++it) {
        prep_M_kernel     <<<1,   32>>>(it > 0 ? 1 : 0);
        batch_log8_kernel <<<nb8, 256, shmem8>>>(data, it > 0 ? 1 : 0, it < 4 ? 1 : 0, Bsz);
        reduce32_kernel    <<<nb1, NT>>>(pScr, pPart, Bsz);
        reduceFinal_kernel <<<16,  NT>>>(pPart, pL, nb1, inv);
        update_M_kernel   <<<1,   32>>>(it > 0 ? 1 : 0);
    }

    final_prep_kernel <<<1,   32>>>(bias);
    apply_kernel      <<<Bsz, NT, shmem4>>>(data, out);
}

// round 12
// speedup vs baseline: 3.2868x; 1.1027x over previous
#include <cuda_runtime.h>
#include <math.h>

#define N    64
#define LD   68            // padded leading dim (floats) for packed kernels; 16B-aligned rows
#define LDA  65            // leading dim for the block-GEMM apply kernel
#define NT   256
#define TILE  (N*LD)       // 4352 floats
#define TILEA (N*LDA)      // 4160 floats
#define MAXB 8192

typedef unsigned long long u64;

// ----------------------------------------------------------------------------
// f32x2 packed helpers (sm_103a packed FP32 pipe; only reachable via PTX)
// ----------------------------------------------------------------------------
__device__ __forceinline__ u64 pk2(float lo, float hi) {
    u64 r; asm("mov.b64 %0,{%1,%2};" : "=l"(r) : "f"(lo), "f"(hi)); return r;
}
__device__ __forceinline__ void up2(u64 v, float& lo, float& hi) {
    asm("mov.b64 {%0,%1},%2;" : "=f"(lo), "=f"(hi) : "l"(v));
}
__device__ __forceinline__ u64 fma2(u64 a, u64 b, u64 c) {
    u64 r; asm("fma.rn.f32x2 %0,%1,%2,%3;" : "=l"(r) : "l"(a), "l"(b), "l"(c)); return r;
}
__device__ __forceinline__ u64 mul2(u64 a, u64 b) {
    u64 r; asm("mul.rn.f32x2 %0,%1,%2;" : "=l"(r) : "l"(a), "l"(b)); return r;
}
__device__ __forceinline__ u64 add2(u64 a, u64 b) {
    u64 r; asm("add.rn.f32x2 %0,%1,%2;" : "=l"(r) : "l"(a), "l"(b)); return r;
}

// Fast rotation scalars (MUFU approx; Jacobi self-corrects ulp-level errors)
__device__ __forceinline__ void rot_cs(float na, float nb, float d,
                                       float& c, float& s) {
    float ta = __fdividef(nb - na, 2.0f * d);
    float h  = fmaf(ta, ta, 1.0f);
    float t  = copysignf(1.0f, ta) * __fdividef(1.0f, fabsf(ta) + h * rsqrtf(h));
    c = rsqrtf(fmaf(t, t, 1.0f));
    s = t * c;
}

// ----------------------------------------------------------------------------
// Global scratch
// ----------------------------------------------------------------------------
__device__ float g_M  [N*N];
__device__ float g_Ms [N*N];
__device__ float g_Mis[N*N];
__device__ float g_L  [N*N];
__device__ float g_C  [N*N];
__device__ float g_VM [N*N];                   // warm-start eigvecs of M (row-major [k][c])
__device__ float g_VL [N*N];                   // warm-start eigvecs of L+sI
__device__ float g_scratch[(size_t)MAXB*N*N];  // per-matrix logm
__device__ float g_Vw     [(size_t)MAXB*N*N];  // per-matrix eigvecs, row-major [k][c]
__device__ float g_partial[(MAXB/32)*N*N];

// ----------------------------------------------------------------------------
// Packed one-sided (Hestenes) Jacobi, odd-even ordering. Lane l holds columns
// at positions 2l (A) and 2l+1 (B); each column = 32 packed f32x2 values
// (element j lives in A[j>>1] half j&1). Unchanged from R10.
// ----------------------------------------------------------------------------
__device__ __forceinline__ void hestenes_p(u64 (&A)[32], u64 (&B)[32],
                                           int lane, int max_sweeps, float thr) {
    const unsigned FULL = 0xffffffffu;
    for (int sweep = 0; sweep < max_sweeps; ++sweep) {
        float nA, nB;
        {
            u64 a0=0ull,a1=0ull,a2=0ull,a3=0ull, b0=0ull,b1=0ull,b2=0ull,b3=0ull;
#pragma unroll
            for (int i = 0; i < 32; i += 4) {
                a0 = fma2(A[i],   A[i],   a0);
                a1 = fma2(A[i+1], A[i+1], a1);
                a2 = fma2(A[i+2], A[i+2], a2);
                a3 = fma2(A[i+3], A[i+3], a3);
                b0 = fma2(B[i],   B[i],   b0);
                b1 = fma2(B[i+1], B[i+1], b1);
                b2 = fma2(B[i+2], B[i+2], b2);
                b3 = fma2(B[i+3], B[i+3], b3);
            }
            u64 sa = add2(add2(a0,a1), add2(a2,a3));
            u64 sb = add2(add2(b0,b1), add2(b2,b3));
            float x0,x1,y0,y1; up2(sa,x0,x1); up2(sb,y0,y1);
            nA = x0+x1; nB = y0+y1;
        }
        int rotated = 0;
        for (int rr = 0; rr < 32; ++rr) {
            // ---- even round: pair (A,B) within lane ----
            {
                u64 c0=0ull,c1_=0ull,c2_=0ull,c3=0ull;
#pragma unroll
                for (int i = 0; i < 32; i += 4) {
                    c0  = fma2(A[i],   B[i],   c0);
                    c1_ = fma2(A[i+1], B[i+1], c1_);
                    c2_ = fma2(A[i+2], B[i+2], c2_);
                    c3  = fma2(A[i+3], B[i+3], c3);
                }
                u64 sc = add2(add2(c0,c1_), add2(c2_,c3));
                float d0,d1; up2(sc,d0,d1);
                float d = d0+d1;
                bool rot = d*d > thr*nA*nB;
                if (__any_sync(FULL, rot)) {
                    rotated = 1;
                    float c = 1.0f, s = 0.0f;
                    if (rot) rot_cs(nA, nB, d, c, s);
                    u64 cp = pk2(c,c), sp = pk2(s,s), np = pk2(-s,-s);
#pragma unroll
                    for (int i = 0; i < 32; ++i) {
                        u64 x = A[i], y = B[i];
                        A[i] = fma2(sp, x, mul2(cp, y));   // v -> pos 2l (swap)
                        B[i] = fma2(cp, x, mul2(np, y));   // u -> pos 2l+1
                    }
                    float cc=c*c, ss=s*s, cs2=2.0f*c*s;
                    float nu = cc*nA - cs2*d + ss*nB;
                    float nv = ss*nA + cs2*d + cc*nB;
                    nA = nv; nB = nu;
                } else {
#pragma unroll
                    for (int i = 0; i < 32; ++i) { u64 t=A[i]; A[i]=B[i]; B[i]=t; }
                    float t = nA; nA = nB; nB = t;
                }
            }
            // ---- odd round: pair (B_l, A_{l+1}); positions 0 and 63 idle ----
            {
                float ny = __shfl_down_sync(FULL, nA, 1);
                u64 c0=0ull,c1_=0ull,c2_=0ull,c3=0ull;
#pragma unroll
                for (int i = 0; i < 32; i += 4) {
                    u64 y0 = __shfl_down_sync(FULL, A[i],   1);
                    u64 y1 = __shfl_down_sync(FULL, A[i+1], 1);
                    u64 y2 = __shfl_down_sync(FULL, A[i+2], 1);
                    u64 y3 = __shfl_down_sync(FULL, A[i+3], 1);
                    c0  = fma2(B[i],   y0, c0);
                    c1_ = fma2(B[i+1], y1, c1_);
                    c2_ = fma2(B[i+2], y2, c2_);
                    c3  = fma2(B[i+3], y3, c3);
                }
                u64 sc = add2(add2(c0,c1_), add2(c2_,c3));
                float d0,d1; up2(sc,d0,d1);
                float d = d0+d1;
                bool rot = (lane < 31) && (d*d > thr*nB*ny);
                if (__any_sync(FULL, rot)) {
                    rotated = 1;
                    float c = 1.0f, s = 0.0f;
                    if (rot) rot_cs(nB, ny, d, c, s);
                    u64 cp = pk2(c,c), sp = pk2(s,s), np = pk2(-s,-s);
#pragma unroll
                    for (int i = 0; i < 32; ++i) {
                        u64 x = B[i];
                        u64 y = __shfl_down_sync(FULL, A[i], 1);
                        u64 u = fma2(cp, x, mul2(np, y));
                        u64 v = fma2(sp, x, mul2(cp, y));
                        u64 us = __shfl_up_sync(FULL, u, 1);
                        B[i] = (lane==31) ? B[i] : v;
                        A[i] = (lane==0)  ? A[i] : us;
                    }
                    float cc=c*c, ss=s*s, cs2=2.0f*c*s;
                    float nu = cc*nB - cs2*d + ss*ny;
                    float nv = ss*nB + cs2*d + cc*ny;
                    float nus = __shfl_up_sync(FULL, nu, 1);
                    nB = (lane==31) ? nB : nv;
                    nA = (lane==0)  ? nA : nus;
                } else {
#pragma unroll
                    for (int i = 0; i < 32; ++i) {
                        u64 y  = __shfl_down_sync(FULL, A[i], 1);
                        u64 xs = __shfl_up_sync(FULL, B[i], 1);
                        B[i] = (lane==31) ? B[i] : y;
                        A[i] = (lane==0)  ? A[i] : xs;
                    }
                    float nus = __shfl_up_sync(FULL, nB, 1);
                    nB = (lane==31) ? nB : ny;
                    nA = (lane==0)  ? nA : nus;
                }
            }
        }
        if (!rotated) break;
    }
}

// ----------------------------------------------------------------------------
// Packed warp-GEMM: A2/B2 = columns (2*lane, 2*lane+1) of P = Bcast * Col.
// Bcast layout: Bc[k*LD + i] == Bcast[i][k] (for symmetric operands this is the
// plain row-major matrix; for warp-GEMM outputs, columns-stored-as-rows).
// Broadcast loads are 16B ulonglong2 (1 wavefront); Col is one float2 per k.
// ----------------------------------------------------------------------------
__device__ __forceinline__ void wgemm_p(u64 (&A2)[32], u64 (&B2)[32],
                                        const float* Bc, const float* Csrc, int lane) {
#pragma unroll
    for (int i = 0; i < 32; ++i) { A2[i] = 0ull; B2[i] = 0ull; }
    for (int k = 0; k < 64; ++k) {
        float2 mv = *(const float2*)&Csrc[k*LD + 2*lane];
        u64 m1 = pk2(mv.x, mv.x), m2 = pk2(mv.y, mv.y);
        const ulonglong2* row = (const ulonglong2*)&Bc[k*LD];
#pragma unroll
        for (int j = 0; j < 16; ++j) {
            ulonglong2 xv = row[j];
            A2[2*j]   = fma2(xv.x, m1, A2[2*j]);
            A2[2*j+1] = fma2(xv.y, m1, A2[2*j+1]);
            B2[2*j]   = fma2(xv.x, m2, B2[2*j]);
            B2[2*j+1] = fma2(xv.y, m2, B2[2*j+1]);
        }
    }
}
// Col operand from GLOBAL row-major [k][c] (stride 64)
__device__ __forceinline__ void wgemm_pg(u64 (&A2)[32], u64 (&B2)[32],
                                         const float* Bc, const float* __restrict__ Cg,
                                         int lane) {
#pragma unroll
    for (int i = 0; i < 32; ++i) { A2[i] = 0ull; B2[i] = 0ull; }
    for (int k = 0; k < 64; ++k) {
        float2 mv = *(const float2*)&Cg[k*64 + 2*lane];
        u64 m1 = pk2(mv.x, mv.x), m2 = pk2(mv.y, mv.y);
        const ulonglong2* row = (const ulonglong2*)&Bc[k*LD];
#pragma unroll
        for (int j = 0; j < 16; ++j) {
            ulonglong2 xv = row[j];
            A2[2*j]   = fma2(xv.x, m1, A2[2*j]);
            A2[2*j+1] = fma2(xv.y, m1, A2[2*j+1]);
            B2[2*j]   = fma2(xv.x, m2, B2[2*j]);
            B2[2*j+1] = fma2(xv.y, m2, B2[2*j+1]);
        }
    }
}
// Packed W diag(g) W^T: Wt[k*LD+i] = W[i][k]; g in shared [64]
__device__ __forceinline__ void wouter_p(u64 (&A2)[32], u64 (&B2)[32],
                                         const float* Wt, const float* g, int lane) {
#pragma unroll
    for (int i = 0; i < 32; ++i) { A2[i] = 0ull; B2[i] = 0ull; }
    for (int k = 0; k < 64; ++k) {
        float2 wv = *(const float2*)&Wt[k*LD + 2*lane];
        float gk = g[k];
        float s1 = gk * wv.x, s2 = gk * wv.y;
        u64 m1 = pk2(s1, s1), m2 = pk2(s2, s2);
        const ulonglong2* row = (const ulonglong2*)&Wt[k*LD];
#pragma unroll
        for (int j = 0; j < 16; ++j) {
            ulonglong2 xv = row[j];
            A2[2*j]   = fma2(xv.x, m1, A2[2*j]);
            A2[2*j+1] = fma2(xv.y, m1, A2[2*j+1]);
            B2[2*j]   = fma2(xv.x, m2, B2[2*j]);
            B2[2*j+1] = fma2(xv.y, m2, B2[2*j+1]);
        }
    }
}

// pack columns (2*lane, 2*lane+1) from row-major LD-padded shared
__device__ __forceinline__ void pack_cols(u64 (&A)[32], u64 (&B)[32],
                                          const float* S, int lane) {
#pragma unroll
    for (int i = 0; i < 32; ++i) {
        A[i] = pk2(S[(2*i)*LD + 2*lane],     S[(2*i+1)*LD + 2*lane]);
        B[i] = pk2(S[(2*i)*LD + 2*lane + 1], S[(2*i+1)*LD + 2*lane + 1]);
    }
}
__device__ __forceinline__ void norms_p(const u64 (&A)[32], const u64 (&B)[32],
                                        float& n1, float& n2) {
    u64 a0=0ull,a1=0ull,a2=0ull,a3=0ull, b0=0ull,b1=0ull,b2=0ull,b3=0ull;
#pragma unroll
    for (int i = 0; i < 32; i += 4) {
        a0 = fma2(A[i],   A[i],   a0);
        a1 = fma2(A[i+1], A[i+1], a1);
        a2 = fma2(A[i+2], A[i+2], a2);
        a3 = fma2(A[i+3], A[i+3], a3);
        b0 = fma2(B[i],   B[i],   b0);
        b1 = fma2(B[i+1], B[i+1], b1);
        b2 = fma2(B[i+2], B[i+2], b2);
        b3 = fma2(B[i+3], B[i+3], b3);
    }
    u64 sa = add2(add2(a0,a1), add2(a2,a3));
    u64 sb = add2(add2(b0,b1), add2(b2,b3));
    float x0,x1,y0,y1; up2(sa,x0,x1); up2(sb,y0,y1);
    n1 = fmaxf(x0+x1, 1e-30f);
    n2 = fmaxf(y0+y1, 1e-30f);
}
// write held columns as ROWS 2*lane, 2*lane+1 (u64 stores, rows 8B-aligned)
__device__ __forceinline__ void unpack_rows(const u64 (&A)[32], const u64 (&B)[32],
                                            float* S, int lane) {
    u64* r0 = (u64*)&S[(2*lane)*LD];
    u64* r1 = (u64*)&S[(2*lane+1)*LD];
#pragma unroll
    for (int i = 0; i < 32; ++i) {
        r0[i] = A[i];
        r1[i] = B[i];
    }
}
// straight copy global NxN row-major -> LD-padded shared (float4)
__device__ __forceinline__ void ld_tile_warp(float* S, const float* __restrict__ G, int lane) {
    const float4* G4 = (const float4*)G;
    for (int idx = lane; idx < 1024; idx += 32) {
        int r = idx >> 4, c = (idx & 15) << 2;
        *(float4*)&S[r*LD + c] = G4[idx];
    }
}

// ----------------------------------------------------------------------------
// Block helpers for apply_kernel (unchanged, LDA layout)
// ----------------------------------------------------------------------------
__device__ __forceinline__ void g2s(float* S, const float* __restrict__ G) {
    for (int idx = threadIdx.x; idx < N*N; idx += NT)
        S[(idx >> 6) * LDA + (idx & 63)] = G[idx];
    __syncthreads();
}
__device__ __forceinline__ void s2g(float* __restrict__ G, const float* S) {
    for (int idx = threadIdx.x; idx < N*N; idx += NT)
        G[idx] = S[(idx >> 6) * LDA + (idx & 63)];
    __syncthreads();
}
__device__ __forceinline__ void gemm_nn(float* D, const float* A, const float* B) {
    const int tx = (threadIdx.x & 15) << 2;
    const int ty = (threadIdx.x >> 4) << 2;
    float acc[4][4] = {};
#pragma unroll 8
    for (int k = 0; k < N; ++k) {
        float a0 = A[(ty+0)*LDA + k], a1 = A[(ty+1)*LDA + k];
        float a2 = A[(ty+2)*LDA + k], a3 = A[(ty+3)*LDA + k];
        float b0 = B[k*LDA + tx+0], b1 = B[k*LDA + tx+1];
        float b2 = B[k*LDA + tx+2], b3 = B[k*LDA + tx+3];
        acc[0][0]+=a0*b0; acc[0][1]+=a0*b1; acc[0][2]+=a0*b2; acc[0][3]+=a0*b3;
        acc[1][0]+=a1*b0; acc[1][1]+=a1*b1; acc[1][2]+=a1*b2; acc[1][3]+=a1*b3;
        acc[2][0]+=a2*b0; acc[2][1]+=a2*b1; acc[2][2]+=a2*b2; acc[2][3]+=a2*b3;
        acc[3][0]+=a3*b0; acc[3][1]+=a3*b1; acc[3][2]+=a3*b2; acc[3][3]+=a3*b3;
    }
#pragma unroll
    for (int r = 0; r < 4; ++r)
#pragma unroll
        for (int c = 0; c < 4; ++c)
            D[(ty+r)*LDA + tx + c] = acc[r][c];
    __syncthreads();
}
__device__ __forceinline__ void gemm_nt(float* D, const float* A, const float* B) {
    const int tx = (threadIdx.x & 15) << 2;
    const int ty = (threadIdx.x >> 4) << 2;
    float acc[4][4] = {};
#pragma unroll 8
    for (int k = 0; k < N; ++k) {
        float a0 = A[(ty+0)*LDA + k], a1 = A[(ty+1)*LDA + k];
        float a2 = A[(ty+2)*LDA + k], a3 = A[(ty+3)*LDA + k];
        float b0 = B[(tx+0)*LDA + k], b1 = B[(tx+1)*LDA + k];
        float b2 = B[(tx+2)*LDA + k], b3 = B[(tx+3)*LDA + k];
        acc[0][0]+=a0*b0; acc[0][1]+=a0*b1; acc[0][2]+=a0*b2; acc[0][3]+=a0*b3;
        acc[1][0]+=a1*b0; acc[1][1]+=a1*b1; acc[1][2]+=a1*b2; acc[1][3]+=a1*b3;
        acc[2][0]+=a2*b0; acc[2][1]+=a2*b1; acc[2][2]+=a2*b2; acc[2][3]+=a2*b3;
        acc[3][0]+=a3*b0; acc[3][1]+=a3*b1; acc[3][2]+=a3*b2; acc[3][3]+=a3*b3;
    }
#pragma unroll
    for (int r = 0; r < 4; ++r)
#pragma unroll
        for (int c = 0; c < 4; ++c)
            D[(ty+r)*LDA + tx + c] = acc[r][c];
    __syncthreads();
}

// ----------------------------------------------------------------------------
// Reductions
// ----------------------------------------------------------------------------
__global__ void __launch_bounds__(NT) reduce32_kernel(const float* __restrict__ src,
                                                      float* __restrict__ dst, int Bsz) {
    int j = blockIdx.x;
    int b0 = j * 32;
    int cnt = min(32, Bsz - b0);
    for (int i = threadIdx.x; i < N*N; i += NT) {
        float a = 0.0f;
        for (int k = 0; k < cnt; ++k)
            a += src[(size_t)(b0 + k) * (N*N) + i];
        dst[(size_t)j * (N*N) + i] = a;
    }
}
__global__ void __launch_bounds__(NT) reduceFinal_kernel(const float* __restrict__ part,
                                                         float* __restrict__ dst,
                                                         int nb, float scale) {
    int i = blockIdx.x * NT + threadIdx.x;
    float a = 0.0f;
    for (int j = 0; j < nb; ++j)
        a += part[(size_t)j * (N*N) + i];
    dst[i] = a * scale;
}

// ----------------------------------------------------------------------------
// Single-matrix warp kernels (1 warp)
// ----------------------------------------------------------------------------

// eig(M) -> g_Ms, g_Mis, V -> g_VM.  Warm from g_VM.
__global__ void __launch_bounds__(32) prep_M_kernel(int warm) {
    __shared__ __align__(16) float t0[TILE], t1[TILE];
    __shared__ float sG[64];
    const int lane = threadIdx.x;
    u64 A2[32], B2[32];

    ld_tile_warp(t0, g_M, lane);
    __syncwarp();
    if (warm) {
        ld_tile_warp(t1, g_VM, lane);       // Vp row-major [k][c]
        __syncwarp();
        wgemm_p(A2, B2, t0, t1, lane);      // W0 = M * Vp  (M symmetric: t0 is bcast-ready)
    } else {
        pack_cols(A2, B2, t0, lane);
    }

    hestenes_p(A2, B2, lane, 24, 1e-10f);

    float n1, n2;
    norms_p(A2, B2, n1, n2);
    float inv1 = rsqrtf(n1), inv2 = rsqrtf(n2);
    __syncwarp();
    unpack_rows(A2, B2, t1, lane);          // t1[k][i] = W[i][k]
    sG[2*lane]   = __expf(-0.75f * __logf(n1));   // lambda^{-3/2}
    sG[2*lane+1] = __expf(-0.75f * __logf(n2));
    __syncwarp();

    // V -> g_VM row-major [k][c]
    for (int k = 0; k < 64; ++k) {
        g_VM[k*64 + 2*lane]     = t1[(2*lane)*LD + k]   * inv1;
        g_VM[k*64 + 2*lane + 1] = t1[(2*lane+1)*LD + k] * inv2;
    }
    wouter_p(A2, B2, t1, sG, lane);         // Ms columns (symmetric -> store rows)
#pragma unroll
    for (int j = 0; j < 16; ++j) {
        float x0,x1,y0,y1,z0,z1,w0,w1;
        up2(A2[2*j],x0,x1); up2(A2[2*j+1],y0,y1);
        up2(B2[2*j],z0,z1); up2(B2[2*j+1],w0,w1);
        ((float4*)g_Ms)[(2*lane)*16 + j]   = make_float4(x0,x1,y0,y1);
        ((float4*)g_Ms)[(2*lane+1)*16 + j] = make_float4(z0,z1,w0,w1);
    }
    sG[2*lane]   = __expf(-1.25f * __logf(n1));   // lambda^{-5/2} -> Mis
    sG[2*lane+1] = __expf(-1.25f * __logf(n2));
    __syncwarp();
    wouter_p(A2, B2, t1, sG, lane);
#pragma unroll
    for (int j = 0; j < 16; ++j) {
        float x0,x1,y0,y1,z0,z1,w0,w1;
        up2(A2[2*j],x0,x1); up2(A2[2*j+1],y0,y1);
        up2(B2[2*j],z0,z1); up2(B2[2*j+1],w0,w1);
        ((float4*)g_Mis)[(2*lane)*16 + j]   = make_float4(x0,x1,y0,y1);
        ((float4*)g_Mis)[(2*lane+1)*16 + j] = make_float4(z0,z1,w0,w1);
    }
}

// M <- sym(Ms expm(L) Ms).  eig(L + sigma I) warm from g_VL.
__global__ void __launch_bounds__(32) update_M_kernel(int warm) {
    __shared__ __align__(16) float t0[TILE], t1[TILE];
    __shared__ float sG[64];
    __shared__ float s_sigma;
    const int lane = threadIdx.x;
    const unsigned FULL = 0xffffffffu;
    u64 A2[32], B2[32];

    float fro2 = 0.0f;
    for (int idx = lane; idx < N*N; idx += 32) {
        float v = g_L[idx];
        t0[(idx>>6)*LD + (idx&63)] = v;
        fro2 = fmaf(v, v, fro2);
    }
#pragma unroll
    for (int o = 16; o > 0; o >>= 1) fro2 += __shfl_down_sync(FULL, fro2, o);
    if (lane == 0) s_sigma = 1.05f * sqrtf(fro2) + 1e-12f;
    __syncwarp();
    const float sigma = s_sigma;

    if (warm) {
        ld_tile_warp(t1, g_VL, lane);
        __syncwarp();
        wgemm_p(A2, B2, t0, t1, lane);      // L*Vp (L symmetric)
        u64 sg = pk2(sigma, sigma);
#pragma unroll
        for (int i = 0; i < 32; ++i) {      // + sigma*Vp
            A2[i] = fma2(sg, pk2(t1[(2*i)*LD + 2*lane],   t1[(2*i+1)*LD + 2*lane]),   A2[i]);
            B2[i] = fma2(sg, pk2(t1[(2*i)*LD + 2*lane+1], t1[(2*i+1)*LD + 2*lane+1]), B2[i]);
        }
    } else {
#pragma unroll
        for (int i = 0; i < 32; ++i) {
            float a0 = t0[(2*i)*LD + 2*lane]     + ((i == lane) ? sigma : 0.0f);
            float a1 = t0[(2*i+1)*LD + 2*lane];
            float b0 = t0[(2*i)*LD + 2*lane + 1];
            float b1 = t0[(2*i+1)*LD + 2*lane+1] + ((i == lane) ? sigma : 0.0f);
            A2[i] = pk2(a0, a1);
            B2[i] = pk2(b0, b1);
        }
    }

    hestenes_p(A2, B2, lane, 24, 1e-10f);

    float n1, n2;
    norms_p(A2, B2, n1, n2);
    float inv1 = rsqrtf(n1), inv2 = rsqrtf(n2);
    __syncwarp();
    unpack_rows(A2, B2, t0, lane);          // t0 = W^T
    sG[2*lane]   = __expf(__fsqrt_rn(n1) - sigma) * __fdividef(1.0f, n1);
    sG[2*lane+1] = __expf(__fsqrt_rn(n2) - sigma) * __fdividef(1.0f, n2);
    __syncwarp();
    for (int k = 0; k < 64; ++k) {          // V -> g_VL
        g_VL[k*64 + 2*lane]     = t0[(2*lane)*LD + k]   * inv1;
        g_VL[k*64 + 2*lane + 1] = t0[(2*lane+1)*LD + k] * inv2;
    }
    wouter_p(A2, B2, t0, sG, lane);         // E = expm(L) columns
    __syncwarp();
    unpack_rows(A2, B2, t1, lane);          // t1[k][i] = E[i][k] (E symmetric)
    __syncwarp();
    ld_tile_warp(t0, g_Ms, lane);           // t0 = Ms (symmetric, bcast-ready)
    __syncwarp();
    wgemm_p(A2, B2, t0, t1, lane);          // T = Ms * E  (cols)
    __syncwarp();
    unpack_rows(A2, B2, t1, lane);          // t1[k][i] = T[i][k]
    __syncwarp();
    wgemm_p(A2, B2, t1, t0, lane);          // Mn = T * Ms (cols)
    __syncwarp();
    unpack_rows(A2, B2, t0, lane);          // t0[c][i] = Mn[i][c]
    __syncwarp();
    for (int idx = lane; idx < N*N; idx += 32) {
        int i = idx >> 6, j = idx & 63;
        g_M[idx] = 0.5f * (t0[j*LD + i] + t0[i*LD + j]);
    }
}

// C = expm(0.25 (bias + bias^T)) * invsqrtm(M)
__global__ void __launch_bounds__(32) final_prep_kernel(const float* __restrict__ bias) {
    __shared__ __align__(16) float t0[TILE], t1[TILE];
    __shared__ float sG[64];
    __shared__ float s_sigma;
    const int lane = threadIdx.x;
    const unsigned FULL = 0xffffffffu;
    u64 A2[32], B2[32];

    // ---- eig(M) warm from g_VM -> Mis rows into t1 ----
    ld_tile_warp(t0, g_M, lane);
    ld_tile_warp(t1, g_VM, lane);
    __syncwarp();
    wgemm_p(A2, B2, t0, t1, lane);          // W0 = M * Vp
    hestenes_p(A2, B2, lane, 24, 1e-10f);
    float n1, n2;
    norms_p(A2, B2, n1, n2);
    __syncwarp();
    unpack_rows(A2, B2, t0, lane);          // t0 = W^T
    sG[2*lane]   = __expf(-1.25f * __logf(n1));
    sG[2*lane+1] = __expf(-1.25f * __logf(n2));
    __syncwarp();
    wouter_p(A2, B2, t0, sG, lane);         // Mis columns
    __syncwarp();
    unpack_rows(A2, B2, t1, lane);          // t1[k][i] = Mis[i][k] (symmetric)
    __syncwarp();

    // ---- eig(0.25(b+b^T) + sigma I) -> Bs rows in t0 ----
    float fro2 = 0.0f;
    for (int idx = lane; idx < N*N; idx += 32) {
        int i = idx >> 6, j = idx & 63;
        float v = 0.25f * (bias[i*64 + j] + bias[j*64 + i]);
        t0[i*LD + j] = v;
        fro2 = fmaf(v, v, fro2);
    }
#pragma unroll
    for (int o = 16; o > 0; o >>= 1) fro2 += __shfl_down_sync(FULL, fro2, o);
    if (lane == 0) s_sigma = 1.05f * sqrtf(fro2) + 1e-12f;
    __syncwarp();
    const float sb = s_sigma;
#pragma unroll
    for (int i = 0; i < 32; ++i) {
        float a0 = t0[(2*i)*LD + 2*lane]     + ((i == lane) ? sb : 0.0f);
        float a1 = t0[(2*i+1)*LD + 2*lane];
        float b0 = t0[(2*i)*LD + 2*lane + 1];
        float b1 = t0[(2*i+1)*LD + 2*lane+1] + ((i == lane) ? sb : 0.0f);
        A2[i] = pk2(a0, a1);
        B2[i] = pk2(b0, b1);
    }
    hestenes_p(A2, B2, lane, 24, 1e-10f);
    norms_p(A2, B2, n1, n2);
    __syncwarp();
    unpack_rows(A2, B2, t0, lane);          // t0 = Wb^T
    sG[2*lane]   = __expf(__fsqrt_rn(n1) - sb) * __fdividef(1.0f, n1);
    sG[2*lane+1] = __expf(__fsqrt_rn(n2) - sb) * __fdividef(1.0f, n2);
    __syncwarp();
    wouter_p(A2, B2, t0, sG, lane);         // Bs columns
    __syncwarp();
    unpack_rows(A2, B2, t0, lane);          // t0[k][i] = Bs[i][k] (symmetric)
    __syncwarp();
    wgemm_p(A2, B2, t0, t1, lane);          // C = Bs * Mis (cols 2lane, 2lane+1)
    // store C row-major (NOT symmetric)
#pragma unroll
    for (int i = 0; i < 32; ++i) {
        float x0,x1,y0,y1;
        up2(A2[i],x0,x1); up2(B2[i],y0,y1);
        g_C[(2*i)*64   + 2*lane]     = x0;
        g_C[(2*i+1)*64 + 2*lane]     = x1;
        g_C[(2*i)*64   + 2*lane + 1] = y0;
        g_C[(2*i+1)*64 + 2*lane + 1] = y1;
    }
}

// ----------------------------------------------------------------------------
// Batch logm: one warp per matrix, 8 per block. Packed GEMMs feed the packed
// Hestenes directly (columns 2lane/2lane+1 everywhere; no relabel round-trips).
// ----------------------------------------------------------------------------
__global__ void __launch_bounds__(256) batch_log8_kernel(const float* __restrict__ data,
                                                         int warm, int store_v, int Bsz) {
    extern __shared__ __align__(16) float sm[];
    float* mis = sm;                          // 64 x LD, shared by all warps
    const int tid  = threadIdx.x;
    const int wid  = tid >> 5;
    const int lane = tid & 31;
    float* tile = sm + TILE * (1 + wid);
    float* sGw  = sm + 9*TILE + wid*64;

    {
        const float4* G4 = (const float4*)g_Mis;
        for (int idx = tid; idx < 1024; idx += 256) {
            int r = idx >> 4, c = (idx & 15) << 2;
            *(float4*)&mis[r*LD + c] = G4[idx];
        }
    }
    __syncthreads();

    const int b = blockIdx.x * 8 + wid;
    if (b >= Bsz) return;

    ld_tile_warp(tile, data + (size_t)b * (N*N), lane);   // X (symmetric)
    __syncwarp();

    u64 A2[32], B2[32];

    wgemm_p(A2, B2, tile, mis, lane);        // Z = X * Mis  (cols 2lane,2lane+1)
    __syncwarp();
    // store Z as [k][c] scalars for GEMM2's column reads
#pragma unroll
    for (int i = 0; i < 32; ++i) {
        float x0,x1,y0,y1;
        up2(A2[i],x0,x1); up2(B2[i],y0,y1);
        tile[(2*i)*LD   + 2*lane]     = x0;
        tile[(2*i+1)*LD + 2*lane]     = x1;
        tile[(2*i)*LD   + 2*lane + 1] = y0;
        tile[(2*i+1)*LD + 2*lane + 1] = y1;
    }
    __syncwarp();
    wgemm_p(A2, B2, mis, tile, lane);        // Y = Mis * Z

    if (warm) {
        __syncwarp();
        unpack_rows(A2, B2, tile, lane);     // tile[k][i] = Y[i][k] (Y symmetric)
        __syncwarp();
        wgemm_pg(A2, B2, tile, g_Vw + (size_t)b * (N*N), lane);   // W0 = Y * Vp
    }

    hestenes_p(A2, B2, lane, 16, 1e-8f);

    float n1, n2;
    norms_p(A2, B2, n1, n2);
    float inv1 = rsqrtf(n1), inv2 = rsqrtf(n2);
    __syncwarp();
    unpack_rows(A2, B2, tile, lane);         // tile = W^T
    sGw[2*lane]   = __fdividef(0.5f * __logf(n1), n1);   // log(l)/l^2
    sGw[2*lane+1] = __fdividef(0.5f * __logf(n2), n2);
    __syncwarp();

    wouter_p(A2, B2, tile, sGw, lane);       // O = W diag(g) W^T (cols; symmetric)
    float* Ob = g_scratch + (size_t)b * (N*N);
#pragma unroll
    for (int j = 0; j < 16; ++j) {
        float x0,x1,y0,y1,z0,z1,w0,w1;
        up2(A2[2*j],x0,x1); up2(A2[2*j+1],y0,y1);
        up2(B2[2*j],z0,z1); up2(B2[2*j+1],w0,w1);
        ((float4*)Ob)[(2*lane)*16 + j]   = make_float4(x0,x1,y0,y1);
        ((float4*)Ob)[(2*lane+1)*16 + j] = make_float4(z0,z1,w0,w1);
    }

    if (store_v) {
        float* Vd = g_Vw + (size_t)b * (N*N);
#pragma unroll
        for (int k = 0; k < 64; ++k) {
            Vd[k*64 + 2*lane]     = tile[(2*lane)*LD + k]   * inv1;
            Vd[k*64 + 2*lane + 1] = tile[(2*lane+1)*LD + k] * inv2;
        }
    }
}

// out_b = C X_b C^T  (block version, unchanged)
__global__ void __launch_bounds__(NT) apply_kernel(const float* __restrict__ data,
                                                   float* __restrict__ out) {
    extern __shared__ __align__(16) float sm[];
    float *b0 = sm, *b1 = sm + TILEA, *b2 = sm + 2*TILEA, *b3 = sm + 3*TILEA;
    const size_t b = blockIdx.x;
    g2s(b1, g_C);
    g2s(b0, data + b * (N*N));
    gemm_nn(b2, b1, b0);
    gemm_nt(b3, b2, b1);
    s2g(out + b * (N*N), b3);
}

// ----------------------------------------------------------------------------
// Host launcher (graph-capturable)
// ----------------------------------------------------------------------------
extern "C" void kernel_launch(void* const* d_in, const int* in_sizes, int n_in,
                              void* d_out, int out_size) {
    const float* data = (const float*)d_in[0];
    const float* bias = (const float*)d_in[1];
    int sz0 = in_sizes[0], sz1 = (n_in > 1) ? in_sizes[1] : 0;
    if (sz0 == N*N && sz1 > N*N) {
        data = (const float*)d_in[1];
        bias = (const float*)d_in[0];
        int t = sz0; sz0 = sz1; sz1 = t;
    }
    int Bsz = sz0 / (N*N);
    if (Bsz > MAXB) Bsz = MAXB;
    float* out = (float*)d_out;

    const size_t shmem4 = 4 * TILEA * sizeof(float);            // apply: 66,560 B
    const size_t shmem8 = (9 * TILE + 512) * sizeof(float);     // batch: 158,720 B
    cudaFuncSetAttribute(batch_log8_kernel, cudaFuncAttributeMaxDynamicSharedMemorySize, (int)shmem8);
    cudaFuncSetAttribute(apply_kernel,      cudaFuncAttributeMaxDynamicSharedMemorySize, (int)shmem4);

    float *pM, *pL, *pScr, *pPart;
    cudaGetSymbolAddress((void**)&pM,    g_M);
    cudaGetSymbolAddress((void**)&pL,    g_L);
    cudaGetSymbolAddress((void**)&pScr,  g_scratch);
    cudaGetSymbolAddress((void**)&pPart, g_partial);

    const int nb1 = (Bsz + 31) / 32;
    const int nb8 = (Bsz + 7) / 8;
    const float inv = 1.0f / (float)Bsz;

    reduce32_kernel    <<<nb1, NT>>>(data, pPart, Bsz);
    reduceFinal_kernel <<<16,  NT>>>(pPart, pM, nb1, inv);

    for (int it = 0; it < 5; ++it) {
        prep_M_kernel     <<<1,   32>>>(it > 0 ? 1 : 0);
        batch_log8_kernel <<<nb8, 256, shmem8>>>(data, it > 0 ? 1 : 0, it < 4 ? 1 : 0, Bsz);
        reduce32_kernel    <<<nb1, NT>>>(pScr, pPart, Bsz);
        reduceFinal_kernel <<<16,  NT>>>(pPart, pL, nb1, inv);
        update_M_kernel   <<<1,   32>>>(it > 0 ? 1 : 0);
    }

    final_prep_kernel <<<1,   32>>>(bias);
    apply_kernel      <<<Bsz, NT, shmem4>>>(data, out);
}

// round 13
// speedup vs baseline: 3.5870x; 1.0914x over previous
#include <cuda_runtime.h>
#include <math.h>

#define N    64
#define LD   68            // padded leading dim (floats); 16B-aligned rows
#define NT   256
#define TILE (N*LD)        // 4352 floats
#define MAXB 8192

typedef unsigned long long u64;

// ----------------------------------------------------------------------------
// f32x2 packed helpers (sm_103a packed FP32 pipe; only reachable via PTX)
// ----------------------------------------------------------------------------
__device__ __forceinline__ u64 pk2(float lo, float hi) {
    u64 r; asm("mov.b64 %0,{%1,%2};" : "=l"(r) : "f"(lo), "f"(hi)); return r;
}
__device__ __forceinline__ void up2(u64 v, float& lo, float& hi) {
    asm("mov.b64 {%0,%1},%2;" : "=f"(lo), "=f"(hi) : "l"(v));
}
__device__ __forceinline__ u64 fma2(u64 a, u64 b, u64 c) {
    u64 r; asm("fma.rn.f32x2 %0,%1,%2,%3;" : "=l"(r) : "l"(a), "l"(b), "l"(c)); return r;
}
__device__ __forceinline__ u64 mul2(u64 a, u64 b) {
    u64 r; asm("mul.rn.f32x2 %0,%1,%2;" : "=l"(r) : "l"(a), "l"(b)); return r;
}
__device__ __forceinline__ u64 add2(u64 a, u64 b) {
    u64 r; asm("add.rn.f32x2 %0,%1,%2;" : "=l"(r) : "l"(a), "l"(b)); return r;
}

// Fast rotation scalars (MUFU approx; Jacobi self-corrects ulp-level errors)
__device__ __forceinline__ void rot_cs(float na, float nb, float d,
                                       float& c, float& s) {
    float ta = __fdividef(nb - na, 2.0f * d);
    float h  = fmaf(ta, ta, 1.0f);
    float t  = copysignf(1.0f, ta) * __fdividef(1.0f, fabsf(ta) + h * rsqrtf(h));
    c = rsqrtf(fmaf(t, t, 1.0f));
    s = t * c;
}

// ----------------------------------------------------------------------------
// Global scratch
// ----------------------------------------------------------------------------
__device__ float g_M  [N*N];
__device__ float g_Ms [N*N];
__device__ float g_Mis[N*N];
__device__ float g_L  [N*N];
__device__ float g_Ct [N*N];                   // C^T row-major (= C columns as rows)
__device__ float g_VM [N*N];                   // warm-start eigvecs of M (row-major [k][c])
__device__ float g_VL [N*N];                   // warm-start eigvecs of L+sI
__device__ float g_scratch[(size_t)MAXB*N*N];  // per-matrix logm
__device__ float g_Vw     [(size_t)MAXB*N*N];  // per-matrix eigvecs, row-major [k][c]
__device__ float g_partial[(MAXB/32)*N*N];

// ----------------------------------------------------------------------------
// Packed one-sided (Hestenes) Jacobi, odd-even ordering. Lane l holds columns
// at positions 2l (A) and 2l+1 (B); each column = 32 packed f32x2 values.
// Sweep exit: when a full sweep saw NO pair with d^2 > tiny*nA*nB (rotations
// between thr and tiny are still applied in that final sweep) — this removes
// the terminal all-quiet confirmation sweep.
// ----------------------------------------------------------------------------
__device__ __forceinline__ void hestenes_p(u64 (&A)[32], u64 (&B)[32],
                                           int lane, int max_sweeps,
                                           float thr, float tiny) {
    const unsigned FULL = 0xffffffffu;
    for (int sweep = 0; sweep < max_sweeps; ++sweep) {
        float nA, nB;
        {
            u64 a0=0ull,a1=0ull,a2=0ull,a3=0ull, b0=0ull,b1=0ull,b2=0ull,b3=0ull;
#pragma unroll
            for (int i = 0; i < 32; i += 4) {
                a0 = fma2(A[i],   A[i],   a0);
                a1 = fma2(A[i+1], A[i+1], a1);
                a2 = fma2(A[i+2], A[i+2], a2);
                a3 = fma2(A[i+3], A[i+3], a3);
                b0 = fma2(B[i],   B[i],   b0);
                b1 = fma2(B[i+1], B[i+1], b1);
                b2 = fma2(B[i+2], B[i+2], b2);
                b3 = fma2(B[i+3], B[i+3], b3);
            }
            u64 sa = add2(add2(a0,a1), add2(a2,a3));
            u64 sb = add2(add2(b0,b1), add2(b2,b3));
            float x0,x1,y0,y1; up2(sa,x0,x1); up2(sb,y0,y1);
            nA = x0+x1; nB = y0+y1;
        }
        int big = 0;   // per-lane: saw any pair above the tiny threshold
        for (int rr = 0; rr < 32; ++rr) {
            // ---- even round: pair (A,B) within lane ----
            {
                u64 c0=0ull,c1_=0ull,c2_=0ull,c3=0ull;
#pragma unroll
                for (int i = 0; i < 32; i += 4) {
                    c0  = fma2(A[i],   B[i],   c0);
                    c1_ = fma2(A[i+1], B[i+1], c1_);
                    c2_ = fma2(A[i+2], B[i+2], c2_);
                    c3  = fma2(A[i+3], B[i+3], c3);
                }
                u64 sc = add2(add2(c0,c1_), add2(c2_,c3));
                float d0,d1; up2(sc,d0,d1);
                float d = d0+d1;
                float np = nA*nB;
                bool rot = d*d > thr*np;
                big |= (d*d > tiny*np);
                if (__any_sync(FULL, rot)) {
                    float c = 1.0f, s = 0.0f;
                    if (rot) rot_cs(nA, nB, d, c, s);
                    u64 cp = pk2(c,c), sp = pk2(s,s), np2 = pk2(-s,-s);
#pragma unroll
                    for (int i = 0; i < 32; ++i) {
                        u64 x = A[i], y = B[i];
                        A[i] = fma2(sp, x, mul2(cp, y));   // v -> pos 2l (swap)
                        B[i] = fma2(cp, x, mul2(np2, y));  // u -> pos 2l+1
                    }
                    float cc=c*c, ss=s*s, cs2=2.0f*c*s;
                    float nu = cc*nA - cs2*d + ss*nB;
                    float nv = ss*nA + cs2*d + cc*nB;
                    nA = nv; nB = nu;
                } else {
#pragma unroll
                    for (int i = 0; i < 32; ++i) { u64 t=A[i]; A[i]=B[i]; B[i]=t; }
                    float t = nA; nA = nB; nB = t;
                }
            }
            // ---- odd round: pair (B_l, A_{l+1}); positions 0 and 63 idle ----
            {
                float ny = __shfl_down_sync(FULL, nA, 1);
                u64 c0=0ull,c1_=0ull,c2_=0ull,c3=0ull;
#pragma unroll
                for (int i = 0; i < 32; i += 4) {
                    u64 y0 = __shfl_down_sync(FULL, A[i],   1);
                    u64 y1 = __shfl_down_sync(FULL, A[i+1], 1);
                    u64 y2 = __shfl_down_sync(FULL, A[i+2], 1);
                    u64 y3 = __shfl_down_sync(FULL, A[i+3], 1);
                    c0  = fma2(B[i],   y0, c0);
                    c1_ = fma2(B[i+1], y1, c1_);
                    c2_ = fma2(B[i+2], y2, c2_);
                    c3  = fma2(B[i+3], y3, c3);
                }
                u64 sc = add2(add2(c0,c1_), add2(c2_,c3));
                float d0,d1; up2(sc,d0,d1);
                float d = d0+d1;
                float np = nB*ny;
                bool rot = (lane < 31) && (d*d > thr*np);
                big |= (int)((lane < 31) && (d*d > tiny*np));
                if (__any_sync(FULL, rot)) {
                    float c = 1.0f, s = 0.0f;
                    if (rot) rot_cs(nB, ny, d, c, s);
                    u64 cp = pk2(c,c), sp = pk2(s,s), np2 = pk2(-s,-s);
#pragma unroll
                    for (int i = 0; i < 32; ++i) {
                        u64 x = B[i];
                        u64 y = __shfl_down_sync(FULL, A[i], 1);
                        u64 u = fma2(cp, x, mul2(np2, y));
                        u64 v = fma2(sp, x, mul2(cp, y));
                        u64 us = __shfl_up_sync(FULL, u, 1);
                        B[i] = (lane==31) ? B[i] : v;
                        A[i] = (lane==0)  ? A[i] : us;
                    }
                    float cc=c*c, ss=s*s, cs2=2.0f*c*s;
                    float nu = cc*nB - cs2*d + ss*ny;
                    float nv = ss*nB + cs2*d + cc*ny;
                    float nus = __shfl_up_sync(FULL, nu, 1);
                    nB = (lane==31) ? nB : nv;
                    nA = (lane==0)  ? nA : nus;
                } else {
                    // quiet fast-path: pure positional swap across lane boundary
#pragma unroll
                    for (int i = 0; i < 32; ++i) {
                        u64 y  = __shfl_down_sync(FULL, A[i], 1);
                        u64 xs = __shfl_up_sync(FULL, B[i], 1);
                        B[i] = (lane==31) ? B[i] : y;
                        A[i] = (lane==0)  ? A[i] : xs;
                    }
                    float nus = __shfl_up_sync(FULL, nB, 1);
                    nB = (lane==31) ? nB : ny;
                    nA = (lane==0)  ? nA : nus;
                }
            }
        }
        if (!__any_sync(FULL, big)) break;
    }
}

// ----------------------------------------------------------------------------
// Packed warp-GEMM: A2/B2 = columns (2*lane, 2*lane+1) of P = Bcast * Col.
// Bc[k*LD + i] == Bcast[i][k]; broadcast loads are 16B ulonglong2.
// ----------------------------------------------------------------------------
__device__ __forceinline__ void wgemm_p(u64 (&A2)[32], u64 (&B2)[32],
                                        const float* Bc, const float* Csrc, int lane) {
#pragma unroll
    for (int i = 0; i < 32; ++i) { A2[i] = 0ull; B2[i] = 0ull; }
    for (int k = 0; k < 64; ++k) {
        float2 mv = *(const float2*)&Csrc[k*LD + 2*lane];
        u64 m1 = pk2(mv.x, mv.x), m2 = pk2(mv.y, mv.y);
        const ulonglong2* row = (const ulonglong2*)&Bc[k*LD];
#pragma unroll
        for (int j = 0; j < 16; ++j) {
            ulonglong2 xv = row[j];
            A2[2*j]   = fma2(xv.x, m1, A2[2*j]);
            A2[2*j+1] = fma2(xv.y, m1, A2[2*j+1]);
            B2[2*j]   = fma2(xv.x, m2, B2[2*j]);
            B2[2*j+1] = fma2(xv.y, m2, B2[2*j+1]);
        }
    }
}
// Col operand from GLOBAL row-major [k][c] (stride 64)
__device__ __forceinline__ void wgemm_pg(u64 (&A2)[32], u64 (&B2)[32],
                                         const float* Bc, const float* __restrict__ Cg,
                                         int lane) {
#pragma unroll
    for (int i = 0; i < 32; ++i) { A2[i] = 0ull; B2[i] = 0ull; }
    for (int k = 0; k < 64; ++k) {
        float2 mv = *(const float2*)&Cg[k*64 + 2*lane];
        u64 m1 = pk2(mv.x, mv.x), m2 = pk2(mv.y, mv.y);
        const ulonglong2* row = (const ulonglong2*)&Bc[k*LD];
#pragma unroll
        for (int j = 0; j < 16; ++j) {
            ulonglong2 xv = row[j];
            A2[2*j]   = fma2(xv.x, m1, A2[2*j]);
            A2[2*j+1] = fma2(xv.y, m1, A2[2*j+1]);
            B2[2*j]   = fma2(xv.x, m2, B2[2*j]);
            B2[2*j+1] = fma2(xv.y, m2, B2[2*j+1]);
        }
    }
}
// Packed W diag(g) W^T: Wt[k*LD+i] = W[i][k]; g in shared [64]
__device__ __forceinline__ void wouter_p(u64 (&A2)[32], u64 (&B2)[32],
                                         const float* Wt, const float* g, int lane) {
#pragma unroll
    for (int i = 0; i < 32; ++i) { A2[i] = 0ull; B2[i] = 0ull; }
    for (int k = 0; k < 64; ++k) {
        float2 wv = *(const float2*)&Wt[k*LD + 2*lane];
        float gk = g[k];
        float s1 = gk * wv.x, s2 = gk * wv.y;
        u64 m1 = pk2(s1, s1), m2 = pk2(s2, s2);
        const ulonglong2* row = (const ulonglong2*)&Wt[k*LD];
#pragma unroll
        for (int j = 0; j < 16; ++j) {
            ulonglong2 xv = row[j];
            A2[2*j]   = fma2(xv.x, m1, A2[2*j]);
            A2[2*j+1] = fma2(xv.y, m1, A2[2*j+1]);
            B2[2*j]   = fma2(xv.x, m2, B2[2*j]);
            B2[2*j+1] = fma2(xv.y, m2, B2[2*j+1]);
        }
    }
}

// pack columns (2*lane, 2*lane+1) from row-major LD-padded shared
__device__ __forceinline__ void pack_cols(u64 (&A)[32], u64 (&B)[32],
                                          const float* S, int lane) {
#pragma unroll
    for (int i = 0; i < 32; ++i) {
        A[i] = pk2(S[(2*i)*LD + 2*lane],     S[(2*i+1)*LD + 2*lane]);
        B[i] = pk2(S[(2*i)*LD + 2*lane + 1], S[(2*i+1)*LD + 2*lane + 1]);
    }
}
__device__ __forceinline__ void norms_p(const u64 (&A)[32], const u64 (&B)[32],
                                        float& n1, float& n2) {
    u64 a0=0ull,a1=0ull,a2=0ull,a3=0ull, b0=0ull,b1=0ull,b2=0ull,b3=0ull;
#pragma unroll
    for (int i = 0; i < 32; i += 4) {
        a0 = fma2(A[i],   A[i],   a0);
        a1 = fma2(A[i+1], A[i+1], a1);
        a2 = fma2(A[i+2], A[i+2], a2);
        a3 = fma2(A[i+3], A[i+3], a3);
        b0 = fma2(B[i],   B[i],   b0);
        b1 = fma2(B[i+1], B[i+1], b1);
        b2 = fma2(B[i+2], B[i+2], b2);
        b3 = fma2(B[i+3], B[i+3], b3);
    }
    u64 sa = add2(add2(a0,a1), add2(a2,a3));
    u64 sb = add2(add2(b0,b1), add2(b2,b3));
    float x0,x1,y0,y1; up2(sa,x0,x1); up2(sb,y0,y1);
    n1 = fmaxf(x0+x1, 1e-30f);
    n2 = fmaxf(y0+y1, 1e-30f);
}
// write held columns as ROWS 2*lane, 2*lane+1 (u64 stores)
__device__ __forceinline__ void unpack_rows(const u64 (&A)[32], const u64 (&B)[32],
                                            float* S, int lane) {
    u64* r0 = (u64*)&S[(2*lane)*LD];
    u64* r1 = (u64*)&S[(2*lane+1)*LD];
#pragma unroll
    for (int i = 0; i < 32; ++i) {
        r0[i] = A[i];
        r1[i] = B[i];
    }
}
// write held columns as [k][c] scalars (for GEMM column-operand handoff)
__device__ __forceinline__ void unpack_cols(const u64 (&A)[32], const u64 (&B)[32],
                                            float* S, int lane) {
#pragma unroll
    for (int i = 0; i < 32; ++i) {
        float x0,x1,y0,y1;
        up2(A[i],x0,x1); up2(B[i],y0,y1);
        S[(2*i)*LD   + 2*lane]     = x0;
        S[(2*i+1)*LD + 2*lane]     = x1;
        S[(2*i)*LD   + 2*lane + 1] = y0;
        S[(2*i+1)*LD + 2*lane + 1] = y1;
    }
}
// straight copy global NxN row-major -> LD-padded shared (float4)
__device__ __forceinline__ void ld_tile_warp(float* S, const float* __restrict__ G, int lane) {
    const float4* G4 = (const float4*)G;
    for (int idx = lane; idx < 1024; idx += 32) {
        int r = idx >> 4, c = (idx & 15) << 2;
        *(float4*)&S[r*LD + c] = G4[idx];
    }
}
// store held symmetric result columns as rows to global (float4)
__device__ __forceinline__ void st_sym_global(const u64 (&A2)[32], const u64 (&B2)[32],
                                              float* __restrict__ G, int lane) {
#pragma unroll
    for (int j = 0; j < 16; ++j) {
        float x0,x1,y0,y1,z0,z1,w0,w1;
        up2(A2[2*j],x0,x1); up2(A2[2*j+1],y0,y1);
        up2(B2[2*j],z0,z1); up2(B2[2*j+1],w0,w1);
        ((float4*)G)[(2*lane)*16 + j]   = make_float4(x0,x1,y0,y1);
        ((float4*)G)[(2*lane+1)*16 + j] = make_float4(z0,z1,w0,w1);
    }
}

// ----------------------------------------------------------------------------
// Reductions
// ----------------------------------------------------------------------------
__global__ void __launch_bounds__(NT) reduce32_kernel(const float* __restrict__ src,
                                                      float* __restrict__ dst, int Bsz) {
    int j = blockIdx.x;
    int b0 = j * 32;
    int cnt = min(32, Bsz - b0);
    for (int i = threadIdx.x; i < N*N; i += NT) {
        float a = 0.0f;
        for (int k = 0; k < cnt; ++k)
            a += src[(size_t)(b0 + k) * (N*N) + i];
        dst[(size_t)j * (N*N) + i] = a;
    }
}
__global__ void __launch_bounds__(NT) reduceFinal_kernel(const float* __restrict__ part,
                                                         float* __restrict__ dst,
                                                         int nb, float scale) {
    int i = blockIdx.x * NT + threadIdx.x;
    float a = 0.0f;
    for (int j = 0; j < nb; ++j)
        a += part[(size_t)j * (N*N) + i];
    dst[i] = a * scale;
}

// ----------------------------------------------------------------------------
// Single-matrix warp kernels (1 warp)
// ----------------------------------------------------------------------------

// eig(M) -> g_Ms, g_Mis, V -> g_VM.  Warm from g_VM.
__global__ void __launch_bounds__(32) prep_M_kernel(int warm) {
    __shared__ __align__(16) float t0[TILE], t1[TILE];
    __shared__ float sG[64];
    const int lane = threadIdx.x;
    u64 A2[32], B2[32];

    ld_tile_warp(t0, g_M, lane);
    __syncwarp();
    if (warm) {
        ld_tile_warp(t1, g_VM, lane);       // Vp row-major [k][c]
        __syncwarp();
        wgemm_p(A2, B2, t0, t1, lane);      // W0 = M * Vp
    } else {
        pack_cols(A2, B2, t0, lane);
    }

    hestenes_p(A2, B2, lane, 24, 1e-10f, 1e-9f);

    float n1, n2;
    norms_p(A2, B2, n1, n2);
    float inv1 = rsqrtf(n1), inv2 = rsqrtf(n2);
    __syncwarp();
    unpack_rows(A2, B2, t1, lane);          // t1[k][i] = W[i][k]
    sG[2*lane]   = __expf(-0.75f * __logf(n1));   // lambda^{-3/2}
    sG[2*lane+1] = __expf(-0.75f * __logf(n2));
    __syncwarp();

    for (int k = 0; k < 64; ++k) {          // V -> g_VM row-major [k][c]
        g_VM[k*64 + 2*lane]     = t1[(2*lane)*LD + k]   * inv1;
        g_VM[k*64 + 2*lane + 1] = t1[(2*lane+1)*LD + k] * inv2;
    }
    wouter_p(A2, B2, t1, sG, lane);         // Ms
    st_sym_global(A2, B2, g_Ms, lane);
    sG[2*lane]   = __expf(-1.25f * __logf(n1));   // lambda^{-5/2} -> Mis
    sG[2*lane+1] = __expf(-1.25f * __logf(n2));
    __syncwarp();
    wouter_p(A2, B2, t1, sG, lane);
    st_sym_global(A2, B2, g_Mis, lane);
}

// M <- sym(Ms expm(L) Ms).  eig(L + sigma I) warm from g_VL.
__global__ void __launch_bounds__(32) update_M_kernel(int warm) {
    __shared__ __align__(16) float t0[TILE], t1[TILE];
    __shared__ float sG[64];
    __shared__ float s_sigma;
    const int lane = threadIdx.x;
    const unsigned FULL = 0xffffffffu;
    u64 A2[32], B2[32];

    float fro2 = 0.0f;
    for (int idx = lane; idx < N*N; idx += 32) {
        float v = g_L[idx];
        t0[(idx>>6)*LD + (idx&63)] = v;
        fro2 = fmaf(v, v, fro2);
    }
#pragma unroll
    for (int o = 16; o > 0; o >>= 1) fro2 += __shfl_down_sync(FULL, fro2, o);
    if (lane == 0) s_sigma = 1.05f * sqrtf(fro2) + 1e-12f;
    __syncwarp();
    const float sigma = s_sigma;

    if (warm) {
        ld_tile_warp(t1, g_VL, lane);
        __syncwarp();
        wgemm_p(A2, B2, t0, t1, lane);      // L*Vp
        u64 sg = pk2(sigma, sigma);
#pragma unroll
        for (int i = 0; i < 32; ++i) {      // + sigma*Vp
            A2[i] = fma2(sg, pk2(t1[(2*i)*LD + 2*lane],   t1[(2*i+1)*LD + 2*lane]),   A2[i]);
            B2[i] = fma2(sg, pk2(t1[(2*i)*LD + 2*lane+1], t1[(2*i+1)*LD + 2*lane+1]), B2[i]);
        }
    } else {
#pragma unroll
        for (int i = 0; i < 32; ++i) {
            float a0 = t0[(2*i)*LD + 2*lane]     + ((i == lane) ? sigma : 0.0f);
            float a1 = t0[(2*i+1)*LD + 2*lane];
            float b0 = t0[(2*i)*LD + 2*lane + 1];
            float b1 = t0[(2*i+1)*LD + 2*lane+1] + ((i == lane) ? sigma : 0.0f);
            A2[i] = pk2(a0, a1);
            B2[i] = pk2(b0, b1);
        }
    }

    hestenes_p(A2, B2, lane, 24, 1e-10f, 1e-9f);

    float n1, n2;
    norms_p(A2, B2, n1, n2);
    float inv1 = rsqrtf(n1), inv2 = rsqrtf(n2);
    __syncwarp();
    unpack_rows(A2, B2, t0, lane);          // t0 = W^T
    sG[2*lane]   = __expf(__fsqrt_rn(n1) - sigma) * __fdividef(1.0f, n1);
    sG[2*lane+1] = __expf(__fsqrt_rn(n2) - sigma) * __fdividef(1.0f, n2);
    __syncwarp();
    for (int k = 0; k < 64; ++k) {          // V -> g_VL
        g_VL[k*64 + 2*lane]     = t0[(2*lane)*LD + k]   * inv1;
        g_VL[k*64 + 2*lane + 1] = t0[(2*lane+1)*LD + k] * inv2;
    }
    wouter_p(A2, B2, t0, sG, lane);         // E = expm(L)
    __syncwarp();
    unpack_rows(A2, B2, t1, lane);          // t1[k][i] = E[i][k] (E symmetric)
    __syncwarp();
    ld_tile_warp(t0, g_Ms, lane);           // t0 = Ms (symmetric)
    __syncwarp();
    wgemm_p(A2, B2, t0, t1, lane);          // T = Ms * E
    __syncwarp();
    unpack_rows(A2, B2, t1, lane);          // t1[k][i] = T[i][k]
    __syncwarp();
    wgemm_p(A2, B2, t1, t0, lane);          // Mn = T * Ms
    __syncwarp();
    unpack_rows(A2, B2, t0, lane);          // t0[c][i] = Mn[i][c]
    __syncwarp();
    for (int idx = lane; idx < N*N; idx += 32) {
        int i = idx >> 6, j = idx & 63;
        g_M[idx] = 0.5f * (t0[j*LD + i] + t0[i*LD + j]);
    }
}

// C = expm(0.25 (bias + bias^T)) * invsqrtm(M);  stores C^T row-major in g_Ct
__global__ void __launch_bounds__(32) final_prep_kernel(const float* __restrict__ bias) {
    __shared__ __align__(16) float t0[TILE], t1[TILE];
    __shared__ float sG[64];
    __shared__ float s_sigma;
    const int lane = threadIdx.x;
    const unsigned FULL = 0xffffffffu;
    u64 A2[32], B2[32];

    // ---- eig(M) warm from g_VM -> Mis rows into t1 ----
    ld_tile_warp(t0, g_M, lane);
    ld_tile_warp(t1, g_VM, lane);
    __syncwarp();
    wgemm_p(A2, B2, t0, t1, lane);          // W0 = M * Vp
    hestenes_p(A2, B2, lane, 24, 1e-10f, 1e-9f);
    float n1, n2;
    norms_p(A2, B2, n1, n2);
    __syncwarp();
    unpack_rows(A2, B2, t0, lane);          // t0 = W^T
    sG[2*lane]   = __expf(-1.25f * __logf(n1));
    sG[2*lane+1] = __expf(-1.25f * __logf(n2));
    __syncwarp();
    wouter_p(A2, B2, t0, sG, lane);         // Mis columns
    __syncwarp();
    unpack_rows(A2, B2, t1, lane);          // t1[k][i] = Mis[i][k] (symmetric)
    __syncwarp();

    // ---- eig(0.25(b+b^T) + sigma I) -> Bs ----
    float fro2 = 0.0f;
    for (int idx = lane; idx < N*N; idx += 32) {
        int i = idx >> 6, j = idx & 63;
        float v = 0.25f * (bias[i*64 + j] + bias[j*64 + i]);
        t0[i*LD + j] = v;
        fro2 = fmaf(v, v, fro2);
    }
#pragma unroll
    for (int o = 16; o > 0; o >>= 1) fro2 += __shfl_down_sync(FULL, fro2, o);
    if (lane == 0) s_sigma = 1.05f * sqrtf(fro2) + 1e-12f;
    __syncwarp();
    const float sb = s_sigma;
#pragma unroll
    for (int i = 0; i < 32; ++i) {
        float a0 = t0[(2*i)*LD + 2*lane]     + ((i == lane) ? sb : 0.0f);
        float a1 = t0[(2*i+1)*LD + 2*lane];
        float b0 = t0[(2*i)*LD + 2*lane + 1];
        float b1 = t0[(2*i+1)*LD + 2*lane+1] + ((i == lane) ? sb : 0.0f);
        A2[i] = pk2(a0, a1);
        B2[i] = pk2(b0, b1);
    }
    hestenes_p(A2, B2, lane, 24, 1e-10f, 1e-9f);
    norms_p(A2, B2, n1, n2);
    __syncwarp();
    unpack_rows(A2, B2, t0, lane);          // t0 = Wb^T
    sG[2*lane]   = __expf(__fsqrt_rn(n1) - sb) * __fdividef(1.0f, n1);
    sG[2*lane+1] = __expf(__fsqrt_rn(n2) - sb) * __fdividef(1.0f, n2);
    __syncwarp();
    wouter_p(A2, B2, t0, sG, lane);         // Bs columns
    __syncwarp();
    unpack_rows(A2, B2, t0, lane);          // t0[k][i] = Bs[i][k] (symmetric)
    __syncwarp();
    wgemm_p(A2, B2, t0, t1, lane);          // C = Bs * Mis (cols 2lane, 2lane+1)
    // store C^T row-major: g_Ct[c*64 + j] = C[j][c]  (column c -> row c, contiguous)
    {
        u64* r0 = (u64*)&g_Ct[(2*lane)*64];
        u64* r1 = (u64*)&g_Ct[(2*lane+1)*64];
#pragma unroll
        for (int i = 0; i < 32; ++i) { r0[i] = A2[i]; r1[i] = B2[i]; }
    }
}

// ----------------------------------------------------------------------------
// Batch logm: one warp per matrix, 8 per block.
// ----------------------------------------------------------------------------
__global__ void __launch_bounds__(256) batch_log8_kernel(const float* __restrict__ data,
                                                         int warm, int store_v, int Bsz) {
    extern __shared__ __align__(16) float sm[];
    float* mis = sm;                          // 64 x LD, shared by all warps
    const int tid  = threadIdx.x;
    const int wid  = tid >> 5;
    const int lane = tid & 31;
    float* tile = sm + TILE * (1 + wid);
    float* sGw  = sm + 9*TILE + wid*64;

    {
        const float4* G4 = (const float4*)g_Mis;
        for (int idx = tid; idx < 1024; idx += 256) {
            int r = idx >> 4, c = (idx & 15) << 2;
            *(float4*)&mis[r*LD + c] = G4[idx];
        }
    }
    __syncthreads();

    const int b = blockIdx.x * 8 + wid;
    if (b >= Bsz) return;

    ld_tile_warp(tile, data + (size_t)b * (N*N), lane);   // X (symmetric)
    __syncwarp();

    u64 A2[32], B2[32];

    wgemm_p(A2, B2, tile, mis, lane);        // Z = X * Mis
    __syncwarp();
    unpack_cols(A2, B2, tile, lane);         // Z as [k][c]
    __syncwarp();
    wgemm_p(A2, B2, mis, tile, lane);        // Y = Mis * Z

    if (warm) {
        __syncwarp();
        unpack_rows(A2, B2, tile, lane);     // tile[k][i] = Y[i][k] (Y symmetric)
        __syncwarp();
        wgemm_pg(A2, B2, tile, g_Vw + (size_t)b * (N*N), lane);   // W0 = Y * Vp
    }

    hestenes_p(A2, B2, lane, 16, 1e-8f, 1e-6f);

    float n1, n2;
    norms_p(A2, B2, n1, n2);
    float inv1 = rsqrtf(n1), inv2 = rsqrtf(n2);
    __syncwarp();
    unpack_rows(A2, B2, tile, lane);         // tile = W^T
    sGw[2*lane]   = __fdividef(0.5f * __logf(n1), n1);   // log(l)/l^2
    sGw[2*lane+1] = __fdividef(0.5f * __logf(n2), n2);
    __syncwarp();

    wouter_p(A2, B2, tile, sGw, lane);       // O = W diag(g) W^T
    st_sym_global(A2, B2, g_scratch + (size_t)b * (N*N), lane);

    if (store_v) {
        float* Vd = g_Vw + (size_t)b * (N*N);
#pragma unroll
        for (int k = 0; k < 64; ++k) {
            Vd[k*64 + 2*lane]     = tile[(2*lane)*LD + k]   * inv1;
            Vd[k*64 + 2*lane + 1] = tile[(2*lane+1)*LD + k] * inv2;
        }
    }
}

// ----------------------------------------------------------------------------
// Apply: out_b = C X_b C^T (symmetric). One warp per matrix, 8 per block.
// GEMM1: Z = X * C^T  (X symmetric -> bcast-ready; col operand = ct[k][c]).
// GEMM2: out = C * Z  (broadcast operand ct[k][i] = C[i][k]).
// ----------------------------------------------------------------------------
__global__ void __launch_bounds__(256) apply8_kernel(const float* __restrict__ data,
                                                     float* __restrict__ out, int Bsz) {
    extern __shared__ __align__(16) float sm[];
    float* ct = sm;                           // 64 x LD, shared by all warps
    const int tid  = threadIdx.x;
    const int wid  = tid >> 5;
    const int lane = tid & 31;
    float* tile = sm + TILE * (1 + wid);

    {
        const float4* G4 = (const float4*)g_Ct;
        for (int idx = tid; idx < 1024; idx += 256) {
            int r = idx >> 4, c = (idx & 15) << 2;
            *(float4*)&ct[r*LD + c] = G4[idx];
        }
    }
    __syncthreads();

    const int b = blockIdx.x * 8 + wid;
    if (b >= Bsz) return;

    ld_tile_warp(tile, data + (size_t)b * (N*N), lane);
    __syncwarp();

    u64 A2[32], B2[32];
    wgemm_p(A2, B2, tile, ct, lane);         // Z = X * C^T (cols 2lane, 2lane+1)
    __syncwarp();
    unpack_cols(A2, B2, tile, lane);         // Z as [k][c]
    __syncwarp();
    wgemm_p(A2, B2, ct, tile, lane);         // out = C * Z (symmetric)
    st_sym_global(A2, B2, out + (size_t)b * (N*N), lane);
}

// ----------------------------------------------------------------------------
// Host launcher (graph-capturable)
// ----------------------------------------------------------------------------
extern "C" void kernel_launch(void* const* d_in, const int* in_sizes, int n_in,
                              void* d_out, int out_size) {
    const float* data = (const float*)d_in[0];
    const float* bias = (const float*)d_in[1];
    int sz0 = in_sizes[0], sz1 = (n_in > 1) ? in_sizes[1] : 0;
    if (sz0 == N*N && sz1 > N*N) {
        data = (const float*)d_in[1];
        bias = (const float*)d_in[0];
        int t = sz0; sz0 = sz1; sz1 = t;
    }
    int Bsz = sz0 / (N*N);
    if (Bsz > MAXB) Bsz = MAXB;
    float* out = (float*)d_out;

    const size_t shmem8 = (9 * TILE + 512) * sizeof(float);     // 158,720 B
    cudaFuncSetAttribute(batch_log8_kernel, cudaFuncAttributeMaxDynamicSharedMemorySize, (int)shmem8);
    cudaFuncSetAttribute(apply8_kernel,     cudaFuncAttributeMaxDynamicSharedMemorySize, (int)shmem8);

    float *pM, *pL, *pScr, *pPart;
    cudaGetSymbolAddress((void**)&pM,    g_M);
    cudaGetSymbolAddress((void**)&pL,    g_L);
    cudaGetSymbolAddress((void**)&pScr,  g_scratch);
    cudaGetSymbolAddress((void**)&pPart, g_partial);

    const int nb1 = (Bsz + 31) / 32;
    const int nb8 = (Bsz + 7) / 8;
    const float inv = 1.0f / (float)Bsz;

    reduce32_kernel    <<<nb1, NT>>>(data, pPart, Bsz);
    reduceFinal_kernel <<<16,  NT>>>(pPart, pM, nb1, inv);

    for (int it = 0; it < 5; ++it) {
        prep_M_kernel     <<<1,   32>>>(it > 0 ? 1 : 0);
        batch_log8_kernel <<<nb8, 256, shmem8>>>(data, it > 0 ? 1 : 0, it < 4 ? 1 : 0, Bsz);
        reduce32_kernel    <<<nb1, NT>>>(pScr, pPart, Bsz);
        reduceFinal_kernel <<<16,  NT>>>(pPart, pL, nb1, inv);
        update_M_kernel   <<<1,   32>>>(it > 0 ? 1 : 0);
    }

    final_prep_kernel <<<1,   32>>>(bias);
    apply8_kernel     <<<nb8, 256, shmem8>>>(data, out, Bsz);
}